// round 1
// baseline (speedup 1.0000x reference)
#include <cuda_runtime.h>
#include <math.h>

#define BSZ   8
#define DIM   512
#define NTOK  1024
#define EMBD  128
#define CDIM  512
#define MTOK  256
#define HEADS 8
#define DHEAD 64
#define INNER 512
#define DFF   2048
#define GROUPS 32

// ---------------- scratch (device globals; no allocations allowed) ----------
__device__ float g_xt [BSZ*NTOK*DIM];          // token-major running state
__device__ float g_buf[BSZ*NTOK*DIM];          // LN output / silu(h) buffer
__device__ float g_q  [BSZ*NTOK*INNER];
__device__ float g_k  [BSZ*NTOK*INNER];
__device__ float g_v  [BSZ*NTOK*INNER];
__device__ float g_o  [BSZ*NTOK*INNER];
__device__ float g_scores[BSZ*HEADS*NTOK*NTOK];   // 268 MB (reused for cross)
__device__ float g_u  [BSZ*NTOK*2*DFF];           // GEGLU pre-activation
__device__ float g_vf [BSZ*NTOK*DFF];             // GEGLU output
__device__ float g_scale[BSZ*DIM];                // 1 + scale
__device__ float g_shift[BSZ*DIM];
__device__ float g_gn_mu[BSZ*GROUPS];
__device__ float g_gn_rs[BSZ*GROUPS];

// ---------------- small reductions -----------------------------------------
__device__ __forceinline__ float block_reduce_sum(float v, float* sh) {
    __syncthreads();
    #pragma unroll
    for (int o = 16; o > 0; o >>= 1) v += __shfl_xor_sync(0xffffffffu, v, o);
    int warp = threadIdx.x >> 5;
    if ((threadIdx.x & 31) == 0) sh[warp] = v;
    __syncthreads();
    int nw = blockDim.x >> 5;
    v = (threadIdx.x < nw) ? sh[threadIdx.x] : 0.f;
    if (threadIdx.x < 32) {
        #pragma unroll
        for (int o = 16; o > 0; o >>= 1) v += __shfl_xor_sync(0xffffffffu, v, o);
    }
    if (threadIdx.x == 0) sh[0] = v;
    __syncthreads();
    return sh[0];
}

__device__ __forceinline__ float block_reduce_max(float v, float* sh) {
    __syncthreads();
    #pragma unroll
    for (int o = 16; o > 0; o >>= 1) v = fmaxf(v, __shfl_xor_sync(0xffffffffu, v, o));
    int warp = threadIdx.x >> 5;
    if ((threadIdx.x & 31) == 0) sh[warp] = v;
    __syncthreads();
    int nw = blockDim.x >> 5;
    v = (threadIdx.x < nw) ? sh[threadIdx.x] : -3.4e38f;
    if (threadIdx.x < 32) {
        #pragma unroll
        for (int o = 16; o > 0; o >>= 1) v = fmaxf(v, __shfl_xor_sync(0xffffffffu, v, o));
    }
    if (threadIdx.x == 0) sh[0] = v;
    __syncthreads();
    return sh[0];
}

// ---------------- generic strided batched SGEMM -----------------------------
// C[i,j] = alpha * sum_k A[i*sAi + k*sAk] * B[j*sBj + k*sBk]  (+bias)(+res)
// batch z: outer = z / batchInner, inner = z % batchInner, two strides each.
// M,N multiples of 64; K multiple of 16.
__global__ __launch_bounds__(256) void gemm_kernel(
    const float* __restrict__ A, long sAi, long sAk, long sAo, long sAin,
    const float* __restrict__ Bm, long sBj, long sBk, long sBo, long sBin,
    float* __restrict__ C, long sCi, long sCj, long sCo, long sCin,
    const float* __restrict__ bias, int bias_mode,           // 0 none,1 over i,2 over j
    const float* __restrict__ Res, long sRi, long sRj, long sRo, long sRin,
    int M, int N, int K, int batchInner, float alpha)
{
    int z = blockIdx.z;
    int zo = z / batchInner, zi = z - zo * batchInner;
    A  += zo * sAo + zi * sAin;
    Bm += zo * sBo + zi * sBin;
    C  += zo * sCo + zi * sCin;
    if (Res) Res += zo * sRo + zi * sRin;

    int i0 = blockIdx.y * 64;
    int j0 = blockIdx.x * 64;
    __shared__ float As[16][64];
    __shared__ float Bs[16][64];
    int tid = threadIdx.x;
    int tx = tid & 15, ty = tid >> 4;

    float acc[4][4] = {};

    for (int k0 = 0; k0 < K; k0 += 16) {
        // ---- stage A tile ----
        if (sAk == 1) {
            int i = tid >> 2, kq = (tid & 3) * 4;
            float4 vv = *reinterpret_cast<const float4*>(A + (long)(i0 + i) * sAi + (k0 + kq));
            As[kq+0][i] = vv.x; As[kq+1][i] = vv.y; As[kq+2][i] = vv.z; As[kq+3][i] = vv.w;
        } else {
            int i = tid & 63, kb = tid >> 6;
            #pragma unroll
            for (int r = 0; r < 4; r++) {
                int k = kb + r * 4;
                As[k][i] = A[(long)(i0 + i) * sAi + (long)(k0 + k) * sAk];
            }
        }
        // ---- stage B tile ----
        if (sBk == 1) {
            int j = tid >> 2, kq = (tid & 3) * 4;
            float4 vv = *reinterpret_cast<const float4*>(Bm + (long)(j0 + j) * sBj + (k0 + kq));
            Bs[kq+0][j] = vv.x; Bs[kq+1][j] = vv.y; Bs[kq+2][j] = vv.z; Bs[kq+3][j] = vv.w;
        } else {
            int j = tid & 63, kb = tid >> 6;
            #pragma unroll
            for (int r = 0; r < 4; r++) {
                int k = kb + r * 4;
                Bs[k][j] = Bm[(long)(j0 + j) * sBj + (long)(k0 + k) * sBk];
            }
        }
        __syncthreads();
        #pragma unroll
        for (int k = 0; k < 16; k++) {
            float4 a = *reinterpret_cast<const float4*>(&As[k][ty * 4]);
            float4 b = *reinterpret_cast<const float4*>(&Bs[k][tx * 4]);
            float av[4] = {a.x, a.y, a.z, a.w};
            float bv[4] = {b.x, b.y, b.z, b.w};
            #pragma unroll
            for (int u = 0; u < 4; u++)
                #pragma unroll
                for (int v = 0; v < 4; v++)
                    acc[u][v] += av[u] * bv[v];
        }
        __syncthreads();
    }

    #pragma unroll
    for (int u = 0; u < 4; u++) {
        int i = i0 + ty * 4 + u;
        #pragma unroll
        for (int v = 0; v < 4; v++) {
            int j = j0 + tx * 4 + v;
            float val = alpha * acc[u][v];
            if (bias_mode == 1) val += bias[i];
            else if (bias_mode == 2) val += bias[j];
            if (Res) val += Res[(long)i * sRi + (long)j * sRj];
            C[(long)i * sCi + (long)j * sCj] = val;
        }
    }
}

// ---------------- tiny / elementwise kernels --------------------------------

// emb_out = silu(emb) @ w_emb^T + b_emb ; split into (1+scale), shift
__global__ void emb_kernel(const float* __restrict__ emb,
                           const float* __restrict__ w,
                           const float* __restrict__ bias)
{
    int b = blockIdx.x;
    __shared__ float e[EMBD];
    if (threadIdx.x < EMBD) {
        float v = emb[b * EMBD + threadIdx.x];
        e[threadIdx.x] = v / (1.f + __expf(-v));
    }
    __syncthreads();
    int o = threadIdx.x;   // blockDim = 1024 = 2*DIM
    float acc = bias[o];
    const float* wr = w + (long)o * EMBD;
    #pragma unroll 8
    for (int kk = 0; kk < EMBD; kk++) acc += e[kk] * wr[kk];
    if (o < DIM) g_scale[b * DIM + o] = 1.f + acc;
    else         g_shift[b * DIM + (o - DIM)] = acc;
}

__global__ void gn_stats_kernel(const float* __restrict__ X)
{
    __shared__ float sh[32];
    int b = blockIdx.x / GROUPS, g = blockIdx.x % GROUPS;
    const int CH = DIM / GROUPS;              // 16
    const float* p = X + ((long)b * DIM + (long)g * CH) * NTOK;
    float s = 0.f, ss = 0.f;
    for (int i = threadIdx.x; i < CH * NTOK; i += blockDim.x) {
        float v = p[i]; s += v; ss += v * v;
    }
    s  = block_reduce_sum(s, sh);
    ss = block_reduce_sum(ss, sh);
    if (threadIdx.x == 0) {
        float inv = 1.f / (CH * NTOK);
        float mu = s * inv;
        float var = ss * inv - mu * mu;
        g_gn_mu[blockIdx.x] = mu;
        g_gn_rs[blockIdx.x] = rsqrtf(var + 1e-6f);
    }
}

// h = silu( (gn(x)*g+b) * (1+scale) + shift )
__global__ void gn_apply_kernel(const float* __restrict__ X,
                                const float* __restrict__ gn_g,
                                const float* __restrict__ gn_b,
                                float* __restrict__ H)
{
    long idx = (long)blockIdx.x * blockDim.x + threadIdx.x;
    long bc = idx >> 10;                  // / NTOK
    int c = (int)(bc % DIM);
    int b = (int)(bc / DIM);
    int grp = b * GROUPS + (c >> 4);
    float v = (X[idx] - g_gn_mu[grp]) * g_gn_rs[grp] * gn_g[c] + gn_b[c];
    v = v * g_scale[bc] + g_shift[bc];
    H[idx] = v / (1.f + __expf(-v));
}

__global__ void layernorm_kernel(const float* __restrict__ X, float* __restrict__ Y,
                                 const float* __restrict__ g, const float* __restrict__ b)
{
    __shared__ float sh[32];
    long t = blockIdx.x;
    const float* x = X + t * DIM;
    float* y = Y + t * DIM;
    float s = 0.f, ss = 0.f;
    for (int i = threadIdx.x; i < DIM; i += blockDim.x) {
        float v = x[i]; s += v; ss += v * v;
    }
    s  = block_reduce_sum(s, sh);
    ss = block_reduce_sum(ss, sh);
    float mu = s * (1.f / DIM);
    float var = ss * (1.f / DIM) - mu * mu;
    float rs = rsqrtf(var + 1e-5f);
    for (int i = threadIdx.x; i < DIM; i += blockDim.x)
        y[i] = (x[i] - mu) * rs * g[i] + b[i];
}

__global__ void softmax_kernel(float* __restrict__ S, int W)
{
    __shared__ float sh[32];
    float* p = S + (long)blockIdx.x * W;
    float m = -3.4e38f;
    for (int j = threadIdx.x; j < W; j += blockDim.x) m = fmaxf(m, p[j]);
    m = block_reduce_max(m, sh);
    float s = 0.f;
    for (int j = threadIdx.x; j < W; j += blockDim.x) {
        float e = __expf(p[j] - m);
        p[j] = e; s += e;
    }
    s = block_reduce_sum(s, sh);
    float inv = 1.f / s;
    for (int j = threadIdx.x; j < W; j += blockDim.x) p[j] *= inv;
}

__global__ void geglu_kernel(const float* __restrict__ U, float* __restrict__ V)
{
    long idx = (long)blockIdx.x * blockDim.x + threadIdx.x;   // B*NTOK*DFF
    long t = idx / DFF;
    int f = (int)(idx - t * DFF);
    float a = U[t * (2 * DFF) + f];
    float gg = U[t * (2 * DFF) + DFF + f];
    float ge = 0.5f * gg * (1.f + erff(gg * 0.70710678118654752f));
    V[idx] = a * ge;
}

__global__ void out_transpose_kernel(const float* __restrict__ XT, float* __restrict__ OUT)
{
    __shared__ float tile[32][33];
    int b = blockIdx.z;
    int n0 = blockIdx.x * 32, c0 = blockIdx.y * 32;
    for (int r = threadIdx.y; r < 32; r += 8)
        tile[r][threadIdx.x] = XT[((long)b * NTOK + n0 + r) * DIM + c0 + threadIdx.x];
    __syncthreads();
    for (int r = threadIdx.y; r < 32; r += 8)
        OUT[((long)b * DIM + c0 + r) * NTOK + n0 + threadIdx.x] = tile[threadIdx.x][r];
}

// ---------------- host orchestration ----------------------------------------
static void launch_gemm(const float* A, long sAi, long sAk, long sAo, long sAin,
                        const float* Bm, long sBj, long sBk, long sBo, long sBin,
                        float* C, long sCi, long sCj, long sCo, long sCin,
                        const float* bias, int bmode,
                        const float* R, long sRi, long sRj, long sRo, long sRin,
                        int M, int N, int K, int batch, int batchInner, float alpha)
{
    dim3 grid(N / 64, M / 64, batch);
    gemm_kernel<<<grid, 256>>>(A, sAi, sAk, sAo, sAin, Bm, sBj, sBk, sBo, sBin,
                               C, sCi, sCj, sCo, sCin, bias, bmode,
                               R, sRi, sRj, sRo, sRin, M, N, K, batchInner, alpha);
}

extern "C" void kernel_launch(void* const* d_in, const int* in_sizes, int n_in,
                              void* d_out, int out_size)
{
    const float* x      = (const float*)d_in[0];
    const float* emb    = (const float*)d_in[1];
    const float* ctx    = (const float*)d_in[2];
    const float* w_emb  = (const float*)d_in[3];
    const float* b_emb  = (const float*)d_in[4];
    const float* gn_g   = (const float*)d_in[5];
    const float* gn_b   = (const float*)d_in[6];
    const float* conv_w = (const float*)d_in[7];
    const float* conv_b = (const float*)d_in[8];
    const float* a1_wq  = (const float*)d_in[9];
    const float* a1_wk  = (const float*)d_in[10];
    const float* a1_wv  = (const float*)d_in[11];
    const float* a1_wo  = (const float*)d_in[12];
    const float* a1_bo  = (const float*)d_in[13];
    const float* a2_wq  = (const float*)d_in[14];
    const float* a2_wk  = (const float*)d_in[15];
    const float* a2_wv  = (const float*)d_in[16];
    const float* a2_wo  = (const float*)d_in[17];
    const float* a2_bo  = (const float*)d_in[18];
    const float* ln1_g  = (const float*)d_in[19];
    const float* ln1_b  = (const float*)d_in[20];
    const float* ln2_g  = (const float*)d_in[21];
    const float* ln2_b  = (const float*)d_in[22];
    const float* ln3_g  = (const float*)d_in[23];
    const float* ln3_b  = (const float*)d_in[24];
    const float* ff_w1  = (const float*)d_in[25];
    const float* ff_b1  = (const float*)d_in[26];
    const float* ff_w2  = (const float*)d_in[27];
    const float* ff_b2  = (const float*)d_in[28];
    float* out = (float*)d_out;

    float *xt, *buf, *q, *k, *v, *o, *sc, *u, *vf;
    cudaGetSymbolAddress((void**)&xt,  g_xt);
    cudaGetSymbolAddress((void**)&buf, g_buf);
    cudaGetSymbolAddress((void**)&q,   g_q);
    cudaGetSymbolAddress((void**)&k,   g_k);
    cudaGetSymbolAddress((void**)&v,   g_v);
    cudaGetSymbolAddress((void**)&o,   g_o);
    cudaGetSymbolAddress((void**)&sc,  g_scores);
    cudaGetSymbolAddress((void**)&u,   g_u);
    cudaGetSymbolAddress((void**)&vf,  g_vf);

    const long TD = (long)NTOK * DIM;        // token-major batch stride
    const long XD = (long)DIM * NTOK;        // channel-major batch stride
    const float iscale = 0.125f;             // 1/sqrt(64)

    // 1) embedding modulation
    emb_kernel<<<BSZ, 2 * DIM>>>(emb, w_emb, b_emb);
    // 2) GroupNorm stats + apply + silu
    gn_stats_kernel<<<BSZ * GROUPS, 256>>>(x);
    gn_apply_kernel<<<(int)((long)BSZ * DIM * NTOK / 256), 256>>>(x, gn_g, gn_b, buf);
    // 3) 1x1 conv + residual, write token-major into xt
    launch_gemm(conv_w, DIM, 1, 0, 0,
                buf, 1, NTOK, XD, 0,
                xt, 1, DIM, TD, 0,
                conv_b, 1,
                x, NTOK, 1, XD, 0,
                DIM, NTOK, DIM, BSZ, 1, 1.f);

    // ---- self attention ----
    layernorm_kernel<<<BSZ * NTOK, 256>>>(xt, buf, ln1_g, ln1_b);
    launch_gemm(buf, DIM, 1, 0, 0, a1_wq, DIM, 1, 0, 0, q, INNER, 1, 0, 0,
                nullptr, 0, nullptr, 0, 0, 0, 0, BSZ * NTOK, INNER, DIM, 1, 1, 1.f);
    launch_gemm(buf, DIM, 1, 0, 0, a1_wk, DIM, 1, 0, 0, k, INNER, 1, 0, 0,
                nullptr, 0, nullptr, 0, 0, 0, 0, BSZ * NTOK, INNER, DIM, 1, 1, 1.f);
    launch_gemm(buf, DIM, 1, 0, 0, a1_wv, DIM, 1, 0, 0, v, INNER, 1, 0, 0,
                nullptr, 0, nullptr, 0, 0, 0, 0, BSZ * NTOK, INNER, DIM, 1, 1, 1.f);
    // scores = q @ k^T * scale
    launch_gemm(q, INNER, 1, TD, DHEAD,
                k, INNER, 1, TD, DHEAD,
                sc, NTOK, 1, (long)HEADS * NTOK * NTOK, (long)NTOK * NTOK,
                nullptr, 0, nullptr, 0, 0, 0, 0,
                NTOK, NTOK, DHEAD, BSZ * HEADS, HEADS, iscale);
    softmax_kernel<<<BSZ * HEADS * NTOK, 256>>>(sc, NTOK);
    // o = P @ V
    launch_gemm(sc, NTOK, 1, (long)HEADS * NTOK * NTOK, (long)NTOK * NTOK,
                v, 1, INNER, TD, DHEAD,
                o, INNER, 1, TD, DHEAD,
                nullptr, 0, nullptr, 0, 0, 0, 0,
                NTOK, DHEAD, NTOK, BSZ * HEADS, HEADS, 1.f);
    // out proj + residual
    launch_gemm(o, INNER, 1, 0, 0, a1_wo, INNER, 1, 0, 0, xt, DIM, 1, 0, 0,
                a1_bo, 2, xt, DIM, 1, 0, 0,
                BSZ * NTOK, DIM, INNER, 1, 1, 1.f);

    // ---- cross attention ----
    layernorm_kernel<<<BSZ * NTOK, 256>>>(xt, buf, ln2_g, ln2_b);
    launch_gemm(buf, DIM, 1, 0, 0, a2_wq, DIM, 1, 0, 0, q, INNER, 1, 0, 0,
                nullptr, 0, nullptr, 0, 0, 0, 0, BSZ * NTOK, INNER, DIM, 1, 1, 1.f);
    // k,v from channel-major context (A strides: i over m -> 1, k over c -> MTOK)
    launch_gemm(ctx, 1, MTOK, (long)CDIM * MTOK, 0,
                a2_wk, CDIM, 1, 0, 0,
                k, INNER, 1, (long)MTOK * INNER, 0,
                nullptr, 0, nullptr, 0, 0, 0, 0,
                MTOK, INNER, CDIM, BSZ, 1, 1.f);
    launch_gemm(ctx, 1, MTOK, (long)CDIM * MTOK, 0,
                a2_wv, CDIM, 1, 0, 0,
                v, INNER, 1, (long)MTOK * INNER, 0,
                nullptr, 0, nullptr, 0, 0, 0, 0,
                MTOK, INNER, CDIM, BSZ, 1, 1.f);
    launch_gemm(q, INNER, 1, TD, DHEAD,
                k, INNER, 1, (long)MTOK * INNER, DHEAD,
                sc, MTOK, 1, (long)HEADS * NTOK * MTOK, (long)NTOK * MTOK,
                nullptr, 0, nullptr, 0, 0, 0, 0,
                NTOK, MTOK, DHEAD, BSZ * HEADS, HEADS, iscale);
    softmax_kernel<<<BSZ * HEADS * NTOK, 256>>>(sc, MTOK);
    launch_gemm(sc, MTOK, 1, (long)HEADS * NTOK * MTOK, (long)NTOK * MTOK,
                v, 1, INNER, (long)MTOK * INNER, DHEAD,
                o, INNER, 1, TD, DHEAD,
                nullptr, 0, nullptr, 0, 0, 0, 0,
                NTOK, DHEAD, MTOK, BSZ * HEADS, HEADS, 1.f);
    launch_gemm(o, INNER, 1, 0, 0, a2_wo, INNER, 1, 0, 0, xt, DIM, 1, 0, 0,
                a2_bo, 2, xt, DIM, 1, 0, 0,
                BSZ * NTOK, DIM, INNER, 1, 1, 1.f);

    // ---- GEGLU feed-forward ----
    layernorm_kernel<<<BSZ * NTOK, 256>>>(xt, buf, ln3_g, ln3_b);
    launch_gemm(buf, DIM, 1, 0, 0, ff_w1, DIM, 1, 0, 0, u, 2 * DFF, 1, 0, 0,
                ff_b1, 2, nullptr, 0, 0, 0, 0,
                BSZ * NTOK, 2 * DFF, DIM, 1, 1, 1.f);
    geglu_kernel<<<(int)((long)BSZ * NTOK * DFF / 256), 256>>>(u, vf);
    launch_gemm(vf, DFF, 1, 0, 0, ff_w2, DFF, 1, 0, 0, xt, DIM, 1, 0, 0,
                ff_b2, 2, xt, DIM, 1, 0, 0,
                BSZ * NTOK, DIM, DFF, 1, 1, 1.f);

    // ---- back to [B, DIM, N] ----
    out_transpose_kernel<<<dim3(NTOK / 32, DIM / 32, BSZ), dim3(32, 8)>>>(xt, out);
}

// round 2
// speedup vs baseline: 1.2630x; 1.2630x over previous
#include <cuda_runtime.h>
#include <math.h>

#define BSZ   8
#define DIM   512
#define NTOK  1024
#define EMBD  128
#define CDIM  512
#define MTOK  256
#define HEADS 8
#define DHEAD 64
#define INNER 512
#define DFF   2048
#define GROUPS 32

// ---------------- scratch (device globals; no allocations allowed) ----------
__device__ float g_xt [BSZ*NTOK*DIM];
__device__ float g_buf[BSZ*NTOK*DIM];
__device__ float g_q  [BSZ*NTOK*INNER];
__device__ float g_k  [BSZ*NTOK*INNER];
__device__ float g_v  [BSZ*NTOK*INNER];
__device__ float g_o  [BSZ*NTOK*INNER];
__device__ float g_scores[BSZ*HEADS*NTOK*NTOK];
__device__ float g_u  [BSZ*NTOK*2*DFF];
__device__ float g_vf [BSZ*NTOK*DFF];
__device__ float g_scale[BSZ*DIM];
__device__ float g_shift[BSZ*DIM];
__device__ float g_gn_mu[BSZ*GROUPS];
__device__ float g_gn_rs[BSZ*GROUPS];

// ---------------- small reductions -----------------------------------------
__device__ __forceinline__ float block_reduce_sum(float v, float* sh) {
    __syncthreads();
    #pragma unroll
    for (int o = 16; o > 0; o >>= 1) v += __shfl_xor_sync(0xffffffffu, v, o);
    int warp = threadIdx.x >> 5;
    if ((threadIdx.x & 31) == 0) sh[warp] = v;
    __syncthreads();
    int nw = blockDim.x >> 5;
    v = (threadIdx.x < nw) ? sh[threadIdx.x] : 0.f;
    if (threadIdx.x < 32) {
        #pragma unroll
        for (int o = 16; o > 0; o >>= 1) v += __shfl_xor_sync(0xffffffffu, v, o);
    }
    if (threadIdx.x == 0) sh[0] = v;
    __syncthreads();
    return sh[0];
}

__device__ __forceinline__ float block_reduce_max(float v, float* sh) {
    __syncthreads();
    #pragma unroll
    for (int o = 16; o > 0; o >>= 1) v = fmaxf(v, __shfl_xor_sync(0xffffffffu, v, o));
    int warp = threadIdx.x >> 5;
    if ((threadIdx.x & 31) == 0) sh[warp] = v;
    __syncthreads();
    int nw = blockDim.x >> 5;
    v = (threadIdx.x < nw) ? sh[threadIdx.x] : -3.4e38f;
    if (threadIdx.x < 32) {
        #pragma unroll
        for (int o = 16; o > 0; o >>= 1) v = fmaxf(v, __shfl_xor_sync(0xffffffffu, v, o));
    }
    if (threadIdx.x == 0) sh[0] = v;
    __syncthreads();
    return sh[0];
}

// ---------------- templated strided batched SGEMM ---------------------------
// C[i,j] = alpha * sum_k A[i*sAi+k*sAk] * B[j*sBj+k*sBk] (+bias)(+res)
// BK=16 fixed. blockDim=256 arranged 16x16. M%BM==0, N%BN==0, K%16==0.
template<int BM, int BN, int TM, int TN>
__global__ __launch_bounds__(256) void gemm_tpl(
    const float* __restrict__ A, long sAi, long sAk, long sAo, long sAin,
    const float* __restrict__ Bm, long sBj, long sBk, long sBo, long sBin,
    float* __restrict__ C, long sCi, long sCj, long sCo, long sCin,
    const float* __restrict__ bias, int bias_mode,
    const float* __restrict__ Res, long sRi, long sRj, long sRo, long sRin,
    int K, int batchInner, float alpha)
{
    constexpr int BK = 16;
    constexpr int ARV = BM * BK / 256;   // scalars per thread for A tile
    constexpr int BRV = BN * BK / 256;

    int z = blockIdx.z;
    int zo = z / batchInner, zi = z - zo * batchInner;
    A  += zo * sAo + zi * sAin;
    Bm += zo * sBo + zi * sBin;
    C  += zo * sCo + zi * sCin;
    if (Res) Res += zo * sRo + zi * sRin;

    int i0 = blockIdx.y * BM;
    int j0 = blockIdx.x * BN;

    __shared__ float As[2][BK][BM];
    __shared__ float Bs[2][BK][BN];

    int tid = threadIdx.x;
    int tx = tid & 15, ty = tid >> 4;

    float ra[ARV], rb[BRV];
    float acc[TM][TN] = {};

    const bool aCont = (sAk == 1);
    const bool bCont = (sBk == 1);

    // ---------- prologue: load k-block 0 ----------
    #define LOAD_A(K0)                                                          \
        if (aCont) {                                                            \
            _Pragma("unroll")                                                   \
            for (int s = 0; s < ARV/4; s++) {                                   \
                int q = tid + s * 256;                                          \
                int i = q >> 2, kq = (q & 3) * 4;                               \
                float4 vv = *reinterpret_cast<const float4*>(                   \
                    A + (long)(i0 + i) * sAi + ((K0) + kq));                    \
                ra[s*4+0]=vv.x; ra[s*4+1]=vv.y; ra[s*4+2]=vv.z; ra[s*4+3]=vv.w; \
            }                                                                   \
        } else {                                                                \
            _Pragma("unroll")                                                   \
            for (int r = 0; r < ARV; r++) {                                     \
                int e = tid + r * 256;                                          \
                int k = e / BM, i = e % BM;                                     \
                ra[r] = A[(long)(i0 + i) * sAi + (long)((K0) + k) * sAk];       \
            }                                                                   \
        }
    #define STORE_A(BUF)                                                        \
        if (aCont) {                                                            \
            _Pragma("unroll")                                                   \
            for (int s = 0; s < ARV/4; s++) {                                   \
                int q = tid + s * 256;                                          \
                int i = q >> 2, kq = (q & 3) * 4;                               \
                As[BUF][kq+0][i] = ra[s*4+0];                                   \
                As[BUF][kq+1][i] = ra[s*4+1];                                   \
                As[BUF][kq+2][i] = ra[s*4+2];                                   \
                As[BUF][kq+3][i] = ra[s*4+3];                                   \
            }                                                                   \
        } else {                                                                \
            _Pragma("unroll")                                                   \
            for (int r = 0; r < ARV; r++) {                                     \
                int e = tid + r * 256;                                          \
                int k = e / BM, i = e % BM;                                     \
                As[BUF][k][i] = ra[r];                                          \
            }                                                                   \
        }
    #define LOAD_B(K0)                                                          \
        if (bCont) {                                                            \
            _Pragma("unroll")                                                   \
            for (int s = 0; s < BRV/4; s++) {                                   \
                int q = tid + s * 256;                                          \
                int j = q >> 2, kq = (q & 3) * 4;                               \
                float4 vv = *reinterpret_cast<const float4*>(                   \
                    Bm + (long)(j0 + j) * sBj + ((K0) + kq));                   \
                rb[s*4+0]=vv.x; rb[s*4+1]=vv.y; rb[s*4+2]=vv.z; rb[s*4+3]=vv.w; \
            }                                                                   \
        } else {                                                                \
            _Pragma("unroll")                                                   \
            for (int r = 0; r < BRV; r++) {                                     \
                int e = tid + r * 256;                                          \
                int k = e / BN, j = e % BN;                                     \
                rb[r] = Bm[(long)(j0 + j) * sBj + (long)((K0) + k) * sBk];      \
            }                                                                   \
        }
    #define STORE_B(BUF)                                                        \
        if (bCont) {                                                            \
            _Pragma("unroll")                                                   \
            for (int s = 0; s < BRV/4; s++) {                                   \
                int q = tid + s * 256;                                          \
                int j = q >> 2, kq = (q & 3) * 4;                               \
                Bs[BUF][kq+0][j] = rb[s*4+0];                                   \
                Bs[BUF][kq+1][j] = rb[s*4+1];                                   \
                Bs[BUF][kq+2][j] = rb[s*4+2];                                   \
                Bs[BUF][kq+3][j] = rb[s*4+3];                                   \
            }                                                                   \
        } else {                                                                \
            _Pragma("unroll")                                                   \
            for (int r = 0; r < BRV; r++) {                                     \
                int e = tid + r * 256;                                          \
                int k = e / BN, j = e % BN;                                     \
                Bs[BUF][k][j] = rb[r];                                          \
            }                                                                   \
        }

    LOAD_A(0) LOAD_B(0) STORE_A(0) STORE_B(0)
    __syncthreads();

    int KB = K / BK;
    for (int kb = 0; kb < KB; kb++) {
        int cur = kb & 1;
        if (kb + 1 < KB) {
            int k0 = (kb + 1) * BK;
            LOAD_A(k0) LOAD_B(k0)
        }
        #pragma unroll
        for (int k = 0; k < BK; k++) {
            float a[TM], b[TN];
            #pragma unroll
            for (int s = 0; s < TM/4; s++) {
                float4 vv = *reinterpret_cast<const float4*>(&As[cur][k][ty*TM + s*4]);
                a[s*4+0]=vv.x; a[s*4+1]=vv.y; a[s*4+2]=vv.z; a[s*4+3]=vv.w;
            }
            #pragma unroll
            for (int s = 0; s < TN/4; s++) {
                float4 vv = *reinterpret_cast<const float4*>(&Bs[cur][k][tx*TN + s*4]);
                b[s*4+0]=vv.x; b[s*4+1]=vv.y; b[s*4+2]=vv.z; b[s*4+3]=vv.w;
            }
            #pragma unroll
            for (int u = 0; u < TM; u++)
                #pragma unroll
                for (int v = 0; v < TN; v++)
                    acc[u][v] += a[u] * b[v];
        }
        if (kb + 1 < KB) {
            int nb = cur ^ 1;
            STORE_A(nb) STORE_B(nb)
        }
        __syncthreads();
    }

    // ---------- epilogue ----------
    #pragma unroll
    for (int u = 0; u < TM; u++) {
        int i = i0 + ty * TM + u;
        float bi = (bias_mode == 1) ? bias[i] : 0.f;
        if (sCj == 1) {
            #pragma unroll
            for (int v0 = 0; v0 < TN; v0 += 4) {
                float4 w;
                float* wp = &w.x;
                #pragma unroll
                for (int v = 0; v < 4; v++) {
                    int j = j0 + tx * TN + v0 + v;
                    float val = alpha * acc[u][v0 + v] + bi;
                    if (bias_mode == 2) val += bias[j];
                    if (Res) val += Res[(long)i * sRi + (long)j * sRj];
                    wp[v] = val;
                }
                *reinterpret_cast<float4*>(&C[(long)i * sCi + (j0 + tx*TN + v0)]) = w;
            }
        } else {
            #pragma unroll
            for (int v = 0; v < TN; v++) {
                int j = j0 + tx * TN + v;
                float val = alpha * acc[u][v] + bi;
                if (bias_mode == 2) val += bias[j];
                if (Res) val += Res[(long)i * sRi + (long)j * sRj];
                C[(long)i * sCi + (long)j * sCj] = val;
            }
        }
    }
    #undef LOAD_A
    #undef STORE_A
    #undef LOAD_B
    #undef STORE_B
}

// ---------------- tiny / elementwise kernels --------------------------------
__global__ void emb_kernel(const float* __restrict__ emb,
                           const float* __restrict__ w,
                           const float* __restrict__ bias)
{
    int b = blockIdx.x;
    __shared__ float e[EMBD];
    if (threadIdx.x < EMBD) {
        float v = emb[b * EMBD + threadIdx.x];
        e[threadIdx.x] = v / (1.f + __expf(-v));
    }
    __syncthreads();
    int o = threadIdx.x;   // blockDim = 1024 = 2*DIM
    float acc = bias[o];
    const float* wr = w + (long)o * EMBD;
    #pragma unroll 8
    for (int kk = 0; kk < EMBD; kk++) acc += e[kk] * wr[kk];
    if (o < DIM) g_scale[b * DIM + o] = 1.f + acc;
    else         g_shift[b * DIM + (o - DIM)] = acc;
}

__global__ void gn_stats_kernel(const float* __restrict__ X)
{
    __shared__ float sh[32];
    int b = blockIdx.x / GROUPS, g = blockIdx.x % GROUPS;
    const int CH = DIM / GROUPS;
    const float* p = X + ((long)b * DIM + (long)g * CH) * NTOK;
    float s = 0.f, ss = 0.f;
    for (int i = threadIdx.x; i < CH * NTOK; i += blockDim.x) {
        float v = p[i]; s += v; ss += v * v;
    }
    s  = block_reduce_sum(s, sh);
    ss = block_reduce_sum(ss, sh);
    if (threadIdx.x == 0) {
        float inv = 1.f / (CH * NTOK);
        float mu = s * inv;
        float var = ss * inv - mu * mu;
        g_gn_mu[blockIdx.x] = mu;
        g_gn_rs[blockIdx.x] = rsqrtf(var + 1e-6f);
    }
}

__global__ void gn_apply_kernel(const float* __restrict__ X,
                                const float* __restrict__ gn_g,
                                const float* __restrict__ gn_b,
                                float* __restrict__ H)
{
    long idx = (long)blockIdx.x * blockDim.x + threadIdx.x;
    long bc = idx >> 10;
    int c = (int)(bc % DIM);
    int b = (int)(bc / DIM);
    int grp = b * GROUPS + (c >> 4);
    float v = (X[idx] - g_gn_mu[grp]) * g_gn_rs[grp] * gn_g[c] + gn_b[c];
    v = v * g_scale[bc] + g_shift[bc];
    H[idx] = v / (1.f + __expf(-v));
}

__global__ void layernorm_kernel(const float* __restrict__ X, float* __restrict__ Y,
                                 const float* __restrict__ g, const float* __restrict__ b)
{
    __shared__ float sh[32];
    long t = blockIdx.x;
    const float* x = X + t * DIM;
    float* y = Y + t * DIM;
    float s = 0.f, ss = 0.f;
    for (int i = threadIdx.x; i < DIM; i += blockDim.x) {
        float v = x[i]; s += v; ss += v * v;
    }
    s  = block_reduce_sum(s, sh);
    ss = block_reduce_sum(ss, sh);
    float mu = s * (1.f / DIM);
    float var = ss * (1.f / DIM) - mu * mu;
    float rs = rsqrtf(var + 1e-5f);
    for (int i = threadIdx.x; i < DIM; i += blockDim.x)
        y[i] = (x[i] - mu) * rs * g[i] + b[i];
}

__global__ void softmax_kernel(float* __restrict__ S, int W)
{
    __shared__ float sh[32];
    float* p = S + (long)blockIdx.x * W;
    float m = -3.4e38f;
    for (int j = threadIdx.x; j < W; j += blockDim.x) m = fmaxf(m, p[j]);
    m = block_reduce_max(m, sh);
    float s = 0.f;
    for (int j = threadIdx.x; j < W; j += blockDim.x) {
        float e = __expf(p[j] - m);
        p[j] = e; s += e;
    }
    s = block_reduce_sum(s, sh);
    float inv = 1.f / s;
    for (int j = threadIdx.x; j < W; j += blockDim.x) p[j] *= inv;
}

__global__ void geglu_kernel(const float* __restrict__ U, float* __restrict__ V)
{
    long idx = (long)blockIdx.x * blockDim.x + threadIdx.x;
    long t = idx / DFF;
    int f = (int)(idx - t * DFF);
    float a = U[t * (2 * DFF) + f];
    float gg = U[t * (2 * DFF) + DFF + f];
    float ge = 0.5f * gg * (1.f + erff(gg * 0.70710678118654752f));
    V[idx] = a * ge;
}

__global__ void out_transpose_kernel(const float* __restrict__ XT, float* __restrict__ OUT)
{
    __shared__ float tile[32][33];
    int b = blockIdx.z;
    int n0 = blockIdx.x * 32, c0 = blockIdx.y * 32;
    for (int r = threadIdx.y; r < 32; r += 8)
        tile[r][threadIdx.x] = XT[((long)b * NTOK + n0 + r) * DIM + c0 + threadIdx.x];
    __syncthreads();
    for (int r = threadIdx.y; r < 32; r += 8)
        OUT[((long)b * DIM + c0 + r) * NTOK + n0 + threadIdx.x] = tile[threadIdx.x][r];
}

// ---------------- host orchestration ----------------------------------------
static void launch_gemm(const float* A, long sAi, long sAk, long sAo, long sAin,
                        const float* Bm, long sBj, long sBk, long sBo, long sBin,
                        float* C, long sCi, long sCj, long sCo, long sCin,
                        const float* bias, int bmode,
                        const float* R, long sRi, long sRj, long sRo, long sRin,
                        int M, int N, int K, int batch, int batchInner, float alpha)
{
    if ((N % 128) == 0) {
        dim3 grid(N / 128, M / 128, batch);
        gemm_tpl<128,128,8,8><<<grid, 256>>>(A, sAi, sAk, sAo, sAin,
            Bm, sBj, sBk, sBo, sBin, C, sCi, sCj, sCo, sCin,
            bias, bmode, R, sRi, sRj, sRo, sRin, K, batchInner, alpha);
    } else {
        dim3 grid(N / 64, M / 128, batch);
        gemm_tpl<128,64,8,4><<<grid, 256>>>(A, sAi, sAk, sAo, sAin,
            Bm, sBj, sBk, sBo, sBin, C, sCi, sCj, sCo, sCin,
            bias, bmode, R, sRi, sRj, sRo, sRin, K, batchInner, alpha);
    }
}

extern "C" void kernel_launch(void* const* d_in, const int* in_sizes, int n_in,
                              void* d_out, int out_size)
{
    const float* x      = (const float*)d_in[0];
    const float* emb    = (const float*)d_in[1];
    const float* ctx    = (const float*)d_in[2];
    const float* w_emb  = (const float*)d_in[3];
    const float* b_emb  = (const float*)d_in[4];
    const float* gn_g   = (const float*)d_in[5];
    const float* gn_b   = (const float*)d_in[6];
    const float* conv_w = (const float*)d_in[7];
    const float* conv_b = (const float*)d_in[8];
    const float* a1_wq  = (const float*)d_in[9];
    const float* a1_wk  = (const float*)d_in[10];
    const float* a1_wv  = (const float*)d_in[11];
    const float* a1_wo  = (const float*)d_in[12];
    const float* a1_bo  = (const float*)d_in[13];
    const float* a2_wq  = (const float*)d_in[14];
    const float* a2_wk  = (const float*)d_in[15];
    const float* a2_wv  = (const float*)d_in[16];
    const float* a2_wo  = (const float*)d_in[17];
    const float* a2_bo  = (const float*)d_in[18];
    const float* ln1_g  = (const float*)d_in[19];
    const float* ln1_b  = (const float*)d_in[20];
    const float* ln2_g  = (const float*)d_in[21];
    const float* ln2_b  = (const float*)d_in[22];
    const float* ln3_g  = (const float*)d_in[23];
    const float* ln3_b  = (const float*)d_in[24];
    const float* ff_w1  = (const float*)d_in[25];
    const float* ff_b1  = (const float*)d_in[26];
    const float* ff_w2  = (const float*)d_in[27];
    const float* ff_b2  = (const float*)d_in[28];
    float* out = (float*)d_out;

    float *xt, *buf, *q, *k, *v, *o, *sc, *u, *vf;
    cudaGetSymbolAddress((void**)&xt,  g_xt);
    cudaGetSymbolAddress((void**)&buf, g_buf);
    cudaGetSymbolAddress((void**)&q,   g_q);
    cudaGetSymbolAddress((void**)&k,   g_k);
    cudaGetSymbolAddress((void**)&v,   g_v);
    cudaGetSymbolAddress((void**)&o,   g_o);
    cudaGetSymbolAddress((void**)&sc,  g_scores);
    cudaGetSymbolAddress((void**)&u,   g_u);
    cudaGetSymbolAddress((void**)&vf,  g_vf);

    const long TD = (long)NTOK * DIM;
    const long XD = (long)DIM * NTOK;
    const float iscale = 0.125f;

    // 1) embedding modulation
    emb_kernel<<<BSZ, 2 * DIM>>>(emb, w_emb, b_emb);
    // 2) GroupNorm stats + apply + silu
    gn_stats_kernel<<<BSZ * GROUPS, 256>>>(x);
    gn_apply_kernel<<<(int)((long)BSZ * DIM * NTOK / 256), 256>>>(x, gn_g, gn_b, buf);
    // 3) 1x1 conv + residual, token-major output:
    //    xt[n,o] = sum_c buf[c,n]*w[o,c] + conv_b[o] + x[c=o,n]
    launch_gemm(buf, 1, NTOK, XD, 0,
                conv_w, DIM, 1, 0, 0,
                xt, DIM, 1, TD, 0,
                conv_b, 2,
                x, 1, NTOK, XD, 0,
                NTOK, DIM, DIM, BSZ, 1, 1.f);

    // ---- self attention ----
    layernorm_kernel<<<BSZ * NTOK, 256>>>(xt, buf, ln1_g, ln1_b);
    launch_gemm(buf, DIM, 1, 0, 0, a1_wq, DIM, 1, 0, 0, q, INNER, 1, 0, 0,
                nullptr, 0, nullptr, 0, 0, 0, 0, BSZ * NTOK, INNER, DIM, 1, 1, 1.f);
    launch_gemm(buf, DIM, 1, 0, 0, a1_wk, DIM, 1, 0, 0, k, INNER, 1, 0, 0,
                nullptr, 0, nullptr, 0, 0, 0, 0, BSZ * NTOK, INNER, DIM, 1, 1, 1.f);
    launch_gemm(buf, DIM, 1, 0, 0, a1_wv, DIM, 1, 0, 0, v, INNER, 1, 0, 0,
                nullptr, 0, nullptr, 0, 0, 0, 0, BSZ * NTOK, INNER, DIM, 1, 1, 1.f);
    launch_gemm(q, INNER, 1, TD, DHEAD,
                k, INNER, 1, TD, DHEAD,
                sc, NTOK, 1, (long)HEADS * NTOK * NTOK, (long)NTOK * NTOK,
                nullptr, 0, nullptr, 0, 0, 0, 0,
                NTOK, NTOK, DHEAD, BSZ * HEADS, HEADS, iscale);
    softmax_kernel<<<BSZ * HEADS * NTOK, 256>>>(sc, NTOK);
    launch_gemm(sc, NTOK, 1, (long)HEADS * NTOK * NTOK, (long)NTOK * NTOK,
                v, 1, INNER, TD, DHEAD,
                o, INNER, 1, TD, DHEAD,
                nullptr, 0, nullptr, 0, 0, 0, 0,
                NTOK, DHEAD, NTOK, BSZ * HEADS, HEADS, 1.f);
    launch_gemm(o, INNER, 1, 0, 0, a1_wo, INNER, 1, 0, 0, xt, DIM, 1, 0, 0,
                a1_bo, 2, xt, DIM, 1, 0, 0,
                BSZ * NTOK, DIM, INNER, 1, 1, 1.f);

    // ---- cross attention ----
    layernorm_kernel<<<BSZ * NTOK, 256>>>(xt, buf, ln2_g, ln2_b);
    launch_gemm(buf, DIM, 1, 0, 0, a2_wq, DIM, 1, 0, 0, q, INNER, 1, 0, 0,
                nullptr, 0, nullptr, 0, 0, 0, 0, BSZ * NTOK, INNER, DIM, 1, 1, 1.f);
    launch_gemm(ctx, 1, MTOK, (long)CDIM * MTOK, 0,
                a2_wk, CDIM, 1, 0, 0,
                k, INNER, 1, (long)MTOK * INNER, 0,
                nullptr, 0, nullptr, 0, 0, 0, 0,
                MTOK, INNER, CDIM, BSZ, 1, 1.f);
    launch_gemm(ctx, 1, MTOK, (long)CDIM * MTOK, 0,
                a2_wv, CDIM, 1, 0, 0,
                v, INNER, 1, (long)MTOK * INNER, 0,
                nullptr, 0, nullptr, 0, 0, 0, 0,
                MTOK, INNER, CDIM, BSZ, 1, 1.f);
    launch_gemm(q, INNER, 1, TD, DHEAD,
                k, INNER, 1, (long)MTOK * INNER, DHEAD,
                sc, MTOK, 1, (long)HEADS * NTOK * MTOK, (long)NTOK * MTOK,
                nullptr, 0, nullptr, 0, 0, 0, 0,
                NTOK, MTOK, DHEAD, BSZ * HEADS, HEADS, iscale);
    softmax_kernel<<<BSZ * HEADS * NTOK, 256>>>(sc, MTOK);
    launch_gemm(sc, MTOK, 1, (long)HEADS * NTOK * MTOK, (long)NTOK * MTOK,
                v, 1, INNER, (long)MTOK * INNER, DHEAD,
                o, INNER, 1, TD, DHEAD,
                nullptr, 0, nullptr, 0, 0, 0, 0,
                NTOK, DHEAD, MTOK, BSZ * HEADS, HEADS, 1.f);
    launch_gemm(o, INNER, 1, 0, 0, a2_wo, INNER, 1, 0, 0, xt, DIM, 1, 0, 0,
                a2_bo, 2, xt, DIM, 1, 0, 0,
                BSZ * NTOK, DIM, INNER, 1, 1, 1.f);

    // ---- GEGLU feed-forward ----
    layernorm_kernel<<<BSZ * NTOK, 256>>>(xt, buf, ln3_g, ln3_b);
    launch_gemm(buf, DIM, 1, 0, 0, ff_w1, DIM, 1, 0, 0, u, 2 * DFF, 1, 0, 0,
                ff_b1, 2, nullptr, 0, 0, 0, 0,
                BSZ * NTOK, 2 * DFF, DIM, 1, 1, 1.f);
    geglu_kernel<<<(int)((long)BSZ * NTOK * DFF / 256), 256>>>(u, vf);
    launch_gemm(vf, DFF, 1, 0, 0, ff_w2, DFF, 1, 0, 0, xt, DIM, 1, 0, 0,
                ff_b2, 2, xt, DIM, 1, 0, 0,
                BSZ * NTOK, DIM, DFF, 1, 1, 1.f);

    // ---- back to [B, DIM, N] ----
    out_transpose_kernel<<<dim3(NTOK / 32, DIM / 32, BSZ), dim3(32, 8)>>>(xt, out);
}

// round 3
// speedup vs baseline: 2.8017x; 2.2183x over previous
#include <cuda_runtime.h>
#include <cuda_bf16.h>
#include <math.h>
#include <stdint.h>

#define BSZ   8
#define DIM   512
#define NTOK  1024
#define EMBD  128
#define CDIM  512
#define MTOK  256
#define HEADS 8
#define DHEAD 64
#define INNER 512
#define DFF   2048
#define GROUPS 32

// ---------------- scratch (device globals; no allocations allowed) ----------
__device__ float g_xt [BSZ*NTOK*DIM];
__device__ float g_buf[BSZ*NTOK*DIM];
__device__ float g_q  [BSZ*NTOK*INNER];
__device__ float g_k  [BSZ*NTOK*INNER];
__device__ float g_v  [BSZ*NTOK*INNER];
__device__ float g_o  [BSZ*NTOK*INNER];
__device__ float g_scores[BSZ*HEADS*NTOK*NTOK];
__device__ float g_u  [BSZ*NTOK*2*DFF];
__device__ float g_vf [BSZ*NTOK*DFF];
__device__ float g_scale[BSZ*DIM];
__device__ float g_shift[BSZ*DIM];
__device__ float g_gn_mu[BSZ*GROUPS];
__device__ float g_gn_rs[BSZ*GROUPS];

// ---------------- small reductions -----------------------------------------
__device__ __forceinline__ float block_reduce_sum(float v, float* sh) {
    __syncthreads();
    #pragma unroll
    for (int o = 16; o > 0; o >>= 1) v += __shfl_xor_sync(0xffffffffu, v, o);
    int warp = threadIdx.x >> 5;
    if ((threadIdx.x & 31) == 0) sh[warp] = v;
    __syncthreads();
    int nw = blockDim.x >> 5;
    v = (threadIdx.x < nw) ? sh[threadIdx.x] : 0.f;
    if (threadIdx.x < 32) {
        #pragma unroll
        for (int o = 16; o > 0; o >>= 1) v += __shfl_xor_sync(0xffffffffu, v, o);
    }
    if (threadIdx.x == 0) sh[0] = v;
    __syncthreads();
    return sh[0];
}

__device__ __forceinline__ float block_reduce_max(float v, float* sh) {
    __syncthreads();
    #pragma unroll
    for (int o = 16; o > 0; o >>= 1) v = fmaxf(v, __shfl_xor_sync(0xffffffffu, v, o));
    int warp = threadIdx.x >> 5;
    if ((threadIdx.x & 31) == 0) sh[warp] = v;
    __syncthreads();
    int nw = blockDim.x >> 5;
    v = (threadIdx.x < nw) ? sh[threadIdx.x] : -3.4e38f;
    if (threadIdx.x < 32) {
        #pragma unroll
        for (int o = 16; o > 0; o >>= 1) v = fmaxf(v, __shfl_xor_sync(0xffffffffu, v, o));
    }
    if (threadIdx.x == 0) sh[0] = v;
    __syncthreads();
    return sh[0];
}

// ---------------- bf16 tensor-core strided batched GEMM ---------------------
__device__ __forceinline__ void mma16816(float* c, const uint32_t* a, const uint32_t* b) {
    asm volatile(
        "mma.sync.aligned.m16n8k16.row.col.f32.bf16.bf16.f32 "
        "{%0,%1,%2,%3}, {%4,%5,%6,%7}, {%8,%9}, {%0,%1,%2,%3};\n"
        : "+f"(c[0]), "+f"(c[1]), "+f"(c[2]), "+f"(c[3])
        : "r"(a[0]), "r"(a[1]), "r"(a[2]), "r"(a[3]), "r"(b[0]), "r"(b[1]));
}

// C[i,j] = alpha * sum_k A[i*sAi+k*sAk] * B[j*sBj+k*sBk] (+bias)(+res)
// BK=32. 256 threads = 8 warps. M%BM==0, N%BN==0, K%32==0.
template<int BM, int BN, int WM, int WN>
__global__ __launch_bounds__(256) void gemm_bf16(
    const float* __restrict__ A, long sAi, long sAk, long sAo, long sAin,
    const float* __restrict__ Bm, long sBj, long sBk, long sBo, long sBin,
    float* __restrict__ C, long sCi, long sCj, long sCo, long sCin,
    const float* __restrict__ bias, int bias_mode,
    const float* __restrict__ Res, long sRi, long sRj, long sRo, long sRin,
    int K, int batchInner, float alpha)
{
    constexpr int BK = 32;
    constexpr int AP = BK + 8;                 // padded smem row (halves)
    constexpr int WARPS_N = BN / WN;
    constexpr int MT = WM / 16;
    constexpr int NT = WN / 8;
    constexpr int ARV = BM * BK / 256;         // fp32 scalars staged per thread
    constexpr int BRV = BN * BK / 256;

    int z = blockIdx.z;
    int zo = z / batchInner, zi = z - zo * batchInner;
    A  += zo * sAo + zi * sAin;
    Bm += zo * sBo + zi * sBin;
    C  += zo * sCo + zi * sCin;
    if (Res) Res += zo * sRo + zi * sRin;

    int i0 = blockIdx.y * BM;
    int j0 = blockIdx.x * BN;

    __shared__ __nv_bfloat16 As[2][BM][AP];
    __shared__ __nv_bfloat16 Bs[2][BN][AP];

    int tid  = threadIdx.x;
    int warp = tid >> 5;
    int lane = tid & 31;
    int g    = lane >> 2;           // group id (0..7)
    int tg   = lane & 3;            // thread in group
    int warp_m = warp / WARPS_N;
    int warp_n = warp % WARPS_N;
    int m_w = warp_m * WM;
    int n_w = warp_n * WN;

    const bool aCont = (sAk == 1);
    const bool bCont = (sBk == 1);

    float ra[ARV], rb[BRV];
    float acc[MT][NT][4] = {};

    #define LOAD_A(K0)                                                          \
        if (aCont) {                                                            \
            _Pragma("unroll")                                                   \
            for (int s = 0; s < ARV/4; s++) {                                   \
                int q = tid + s * 256;                                          \
                int i = q >> 3, kq = (q & 7) * 4;                               \
                float4 vv = *reinterpret_cast<const float4*>(                   \
                    A + (long)(i0 + i) * sAi + ((K0) + kq));                    \
                ra[s*4+0]=vv.x; ra[s*4+1]=vv.y; ra[s*4+2]=vv.z; ra[s*4+3]=vv.w; \
            }                                                                   \
        } else {                                                                \
            _Pragma("unroll")                                                   \
            for (int r = 0; r < ARV; r++) {                                     \
                int e = tid + r * 256;                                          \
                int i = e & (BM - 1), k = e / BM;                               \
                ra[r] = A[(long)(i0 + i) * sAi + (long)((K0) + k) * sAk];       \
            }                                                                   \
        }
    #define STORE_A(BUF)                                                        \
        if (aCont) {                                                            \
            _Pragma("unroll")                                                   \
            for (int s = 0; s < ARV/4; s++) {                                   \
                int q = tid + s * 256;                                          \
                int i = q >> 3, kq = (q & 7) * 4;                               \
                __nv_bfloat162 p0 = __floats2bfloat162_rn(ra[s*4+0], ra[s*4+1]);\
                __nv_bfloat162 p1 = __floats2bfloat162_rn(ra[s*4+2], ra[s*4+3]);\
                *reinterpret_cast<__nv_bfloat162*>(&As[BUF][i][kq])   = p0;     \
                *reinterpret_cast<__nv_bfloat162*>(&As[BUF][i][kq+2]) = p1;     \
            }                                                                   \
        } else {                                                                \
            _Pragma("unroll")                                                   \
            for (int r = 0; r < ARV; r++) {                                     \
                int e = tid + r * 256;                                          \
                int i = e & (BM - 1), k = e / BM;                               \
                As[BUF][i][k] = __float2bfloat16_rn(ra[r]);                     \
            }                                                                   \
        }
    #define LOAD_B(K0)                                                          \
        if (bCont) {                                                            \
            _Pragma("unroll")                                                   \
            for (int s = 0; s < BRV/4; s++) {                                   \
                int q = tid + s * 256;                                          \
                int j = q >> 3, kq = (q & 7) * 4;                               \
                float4 vv = *reinterpret_cast<const float4*>(                   \
                    Bm + (long)(j0 + j) * sBj + ((K0) + kq));                   \
                rb[s*4+0]=vv.x; rb[s*4+1]=vv.y; rb[s*4+2]=vv.z; rb[s*4+3]=vv.w; \
            }                                                                   \
        } else {                                                                \
            _Pragma("unroll")                                                   \
            for (int r = 0; r < BRV; r++) {                                     \
                int e = tid + r * 256;                                          \
                int j = e & (BN - 1), k = e / BN;                               \
                rb[r] = Bm[(long)(j0 + j) * sBj + (long)((K0) + k) * sBk];      \
            }                                                                   \
        }
    #define STORE_B(BUF)                                                        \
        if (bCont) {                                                            \
            _Pragma("unroll")                                                   \
            for (int s = 0; s < BRV/4; s++) {                                   \
                int q = tid + s * 256;                                          \
                int j = q >> 3, kq = (q & 7) * 4;                               \
                __nv_bfloat162 p0 = __floats2bfloat162_rn(rb[s*4+0], rb[s*4+1]);\
                __nv_bfloat162 p1 = __floats2bfloat162_rn(rb[s*4+2], rb[s*4+3]);\
                *reinterpret_cast<__nv_bfloat162*>(&Bs[BUF][j][kq])   = p0;     \
                *reinterpret_cast<__nv_bfloat162*>(&Bs[BUF][j][kq+2]) = p1;     \
            }                                                                   \
        } else {                                                                \
            _Pragma("unroll")                                                   \
            for (int r = 0; r < BRV; r++) {                                     \
                int e = tid + r * 256;                                          \
                int j = e & (BN - 1), k = e / BN;                               \
                Bs[BUF][j][k] = __float2bfloat16_rn(rb[r]);                     \
            }                                                                   \
        }

    LOAD_A(0) LOAD_B(0) STORE_A(0) STORE_B(0)
    __syncthreads();

    int KB = K / BK;
    for (int kb = 0; kb < KB; kb++) {
        int cur = kb & 1;
        if (kb + 1 < KB) {
            int k0 = (kb + 1) * BK;
            LOAD_A(k0) LOAD_B(k0)
        }
        #pragma unroll
        for (int ks = 0; ks < BK; ks += 16) {
            uint32_t af[MT][4];
            uint32_t bf[NT][2];
            #pragma unroll
            for (int mt = 0; mt < MT; mt++) {
                const __nv_bfloat16* pa = &As[cur][m_w + mt*16 + g][ks + tg*2];
                af[mt][0] = *reinterpret_cast<const uint32_t*>(pa);
                af[mt][1] = *reinterpret_cast<const uint32_t*>(pa + 8*AP);
                af[mt][2] = *reinterpret_cast<const uint32_t*>(pa + 8);
                af[mt][3] = *reinterpret_cast<const uint32_t*>(pa + 8*AP + 8);
            }
            #pragma unroll
            for (int nt = 0; nt < NT; nt++) {
                const __nv_bfloat16* pb = &Bs[cur][n_w + nt*8 + g][ks + tg*2];
                bf[nt][0] = *reinterpret_cast<const uint32_t*>(pb);
                bf[nt][1] = *reinterpret_cast<const uint32_t*>(pb + 8);
            }
            #pragma unroll
            for (int mt = 0; mt < MT; mt++)
                #pragma unroll
                for (int nt = 0; nt < NT; nt++)
                    mma16816(acc[mt][nt], af[mt], bf[nt]);
        }
        if (kb + 1 < KB) {
            int nb = cur ^ 1;
            STORE_A(nb) STORE_B(nb)
        }
        __syncthreads();
    }

    // ---------- epilogue ----------
    #pragma unroll
    for (int mt = 0; mt < MT; mt++) {
        #pragma unroll
        for (int h = 0; h < 2; h++) {
            int i = i0 + m_w + mt*16 + g + 8*h;
            float bi = (bias_mode == 1) ? bias[i] : 0.f;
            #pragma unroll
            for (int nt = 0; nt < NT; nt++) {
                int j = j0 + n_w + nt*8 + tg*2;
                float v0 = alpha * acc[mt][nt][2*h+0] + bi;
                float v1 = alpha * acc[mt][nt][2*h+1] + bi;
                if (bias_mode == 2) { v0 += bias[j]; v1 += bias[j+1]; }
                if (Res) {
                    v0 += Res[(long)i * sRi + (long)j * sRj];
                    v1 += Res[(long)i * sRi + (long)(j+1) * sRj];
                }
                if (sCj == 1) {
                    float2 w2 = make_float2(v0, v1);
                    *reinterpret_cast<float2*>(&C[(long)i * sCi + j]) = w2;
                } else {
                    C[(long)i * sCi + (long)j     * sCj] = v0;
                    C[(long)i * sCi + (long)(j+1) * sCj] = v1;
                }
            }
        }
    }
    #undef LOAD_A
    #undef STORE_A
    #undef LOAD_B
    #undef STORE_B
}

// ---------------- tiny / elementwise kernels --------------------------------
__global__ void emb_kernel(const float* __restrict__ emb,
                           const float* __restrict__ w,
                           const float* __restrict__ bias)
{
    int b = blockIdx.x;
    __shared__ float e[EMBD];
    if (threadIdx.x < EMBD) {
        float v = emb[b * EMBD + threadIdx.x];
        e[threadIdx.x] = v / (1.f + __expf(-v));
    }
    __syncthreads();
    int o = threadIdx.x;   // blockDim = 1024 = 2*DIM
    float acc = bias[o];
    const float* wr = w + (long)o * EMBD;
    #pragma unroll 8
    for (int kk = 0; kk < EMBD; kk++) acc += e[kk] * wr[kk];
    if (o < DIM) g_scale[b * DIM + o] = 1.f + acc;
    else         g_shift[b * DIM + (o - DIM)] = acc;
}

__global__ void gn_stats_kernel(const float* __restrict__ X)
{
    __shared__ float sh[32];
    int b = blockIdx.x / GROUPS, g = blockIdx.x % GROUPS;
    const int CH = DIM / GROUPS;
    const float* p = X + ((long)b * DIM + (long)g * CH) * NTOK;
    float s = 0.f, ss = 0.f;
    for (int i = threadIdx.x; i < CH * NTOK; i += blockDim.x) {
        float v = p[i]; s += v; ss += v * v;
    }
    s  = block_reduce_sum(s, sh);
    ss = block_reduce_sum(ss, sh);
    if (threadIdx.x == 0) {
        float inv = 1.f / (CH * NTOK);
        float mu = s * inv;
        float var = ss * inv - mu * mu;
        g_gn_mu[blockIdx.x] = mu;
        g_gn_rs[blockIdx.x] = rsqrtf(var + 1e-6f);
    }
}

__global__ void gn_apply_kernel(const float* __restrict__ X,
                                const float* __restrict__ gn_g,
                                const float* __restrict__ gn_b,
                                float* __restrict__ H)
{
    long idx = (long)blockIdx.x * blockDim.x + threadIdx.x;
    long bc = idx >> 10;
    int c = (int)(bc % DIM);
    int b = (int)(bc / DIM);
    int grp = b * GROUPS + (c >> 4);
    float v = (X[idx] - g_gn_mu[grp]) * g_gn_rs[grp] * gn_g[c] + gn_b[c];
    v = v * g_scale[bc] + g_shift[bc];
    H[idx] = v / (1.f + __expf(-v));
}

__global__ void layernorm_kernel(const float* __restrict__ X, float* __restrict__ Y,
                                 const float* __restrict__ g, const float* __restrict__ b)
{
    __shared__ float sh[32];
    long t = blockIdx.x;
    const float* x = X + t * DIM;
    float* y = Y + t * DIM;
    float s = 0.f, ss = 0.f;
    for (int i = threadIdx.x; i < DIM; i += blockDim.x) {
        float v = x[i]; s += v; ss += v * v;
    }
    s  = block_reduce_sum(s, sh);
    ss = block_reduce_sum(ss, sh);
    float mu = s * (1.f / DIM);
    float var = ss * (1.f / DIM) - mu * mu;
    float rs = rsqrtf(var + 1e-5f);
    for (int i = threadIdx.x; i < DIM; i += blockDim.x)
        y[i] = (x[i] - mu) * rs * g[i] + b[i];
}

__global__ void softmax_kernel(float* __restrict__ S, int W)
{
    __shared__ float sh[32];
    float* p = S + (long)blockIdx.x * W;
    float m = -3.4e38f;
    for (int j = threadIdx.x; j < W; j += blockDim.x) m = fmaxf(m, p[j]);
    m = block_reduce_max(m, sh);
    float s = 0.f;
    for (int j = threadIdx.x; j < W; j += blockDim.x) {
        float e = __expf(p[j] - m);
        p[j] = e; s += e;
    }
    s = block_reduce_sum(s, sh);
    float inv = 1.f / s;
    for (int j = threadIdx.x; j < W; j += blockDim.x) p[j] *= inv;
}

__global__ void geglu_kernel(const float* __restrict__ U, float* __restrict__ V)
{
    long idx = (long)blockIdx.x * blockDim.x + threadIdx.x;
    long t = idx / DFF;
    int f = (int)(idx - t * DFF);
    float a = U[t * (2 * DFF) + f];
    float gg = U[t * (2 * DFF) + DFF + f];
    float ge = 0.5f * gg * (1.f + erff(gg * 0.70710678118654752f));
    V[idx] = a * ge;
}

__global__ void out_transpose_kernel(const float* __restrict__ XT, float* __restrict__ OUT)
{
    __shared__ float tile[32][33];
    int b = blockIdx.z;
    int n0 = blockIdx.x * 32, c0 = blockIdx.y * 32;
    for (int r = threadIdx.y; r < 32; r += 8)
        tile[r][threadIdx.x] = XT[((long)b * NTOK + n0 + r) * DIM + c0 + threadIdx.x];
    __syncthreads();
    for (int r = threadIdx.y; r < 32; r += 8)
        OUT[((long)b * DIM + c0 + r) * NTOK + n0 + threadIdx.x] = tile[threadIdx.x][r];
}

// ---------------- host orchestration ----------------------------------------
static void launch_gemm(const float* A, long sAi, long sAk, long sAo, long sAin,
                        const float* Bm, long sBj, long sBk, long sBo, long sBin,
                        float* C, long sCi, long sCj, long sCo, long sCin,
                        const float* bias, int bmode,
                        const float* R, long sRi, long sRj, long sRo, long sRin,
                        int M, int N, int K, int batch, int batchInner, float alpha)
{
    if ((N % 128) == 0) {
        dim3 grid(N / 128, M / 128, batch);
        gemm_bf16<128,128,64,32><<<grid, 256>>>(A, sAi, sAk, sAo, sAin,
            Bm, sBj, sBk, sBo, sBin, C, sCi, sCj, sCo, sCin,
            bias, bmode, R, sRi, sRj, sRo, sRin, K, batchInner, alpha);
    } else {
        dim3 grid(N / 64, M / 128, batch);
        gemm_bf16<128,64,32,32><<<grid, 256>>>(A, sAi, sAk, sAo, sAin,
            Bm, sBj, sBk, sBo, sBin, C, sCi, sCj, sCo, sCin,
            bias, bmode, R, sRi, sRj, sRo, sRin, K, batchInner, alpha);
    }
}

extern "C" void kernel_launch(void* const* d_in, const int* in_sizes, int n_in,
                              void* d_out, int out_size)
{
    const float* x      = (const float*)d_in[0];
    const float* emb    = (const float*)d_in[1];
    const float* ctx    = (const float*)d_in[2];
    const float* w_emb  = (const float*)d_in[3];
    const float* b_emb  = (const float*)d_in[4];
    const float* gn_g   = (const float*)d_in[5];
    const float* gn_b   = (const float*)d_in[6];
    const float* conv_w = (const float*)d_in[7];
    const float* conv_b = (const float*)d_in[8];
    const float* a1_wq  = (const float*)d_in[9];
    const float* a1_wk  = (const float*)d_in[10];
    const float* a1_wv  = (const float*)d_in[11];
    const float* a1_wo  = (const float*)d_in[12];
    const float* a1_bo  = (const float*)d_in[13];
    const float* a2_wq  = (const float*)d_in[14];
    const float* a2_wk  = (const float*)d_in[15];
    const float* a2_wv  = (const float*)d_in[16];
    const float* a2_wo  = (const float*)d_in[17];
    const float* a2_bo  = (const float*)d_in[18];
    const float* ln1_g  = (const float*)d_in[19];
    const float* ln1_b  = (const float*)d_in[20];
    const float* ln2_g  = (const float*)d_in[21];
    const float* ln2_b  = (const float*)d_in[22];
    const float* ln3_g  = (const float*)d_in[23];
    const float* ln3_b  = (const float*)d_in[24];
    const float* ff_w1  = (const float*)d_in[25];
    const float* ff_b1  = (const float*)d_in[26];
    const float* ff_w2  = (const float*)d_in[27];
    const float* ff_b2  = (const float*)d_in[28];
    float* out = (float*)d_out;

    float *xt, *buf, *q, *k, *v, *o, *sc, *u, *vf;
    cudaGetSymbolAddress((void**)&xt,  g_xt);
    cudaGetSymbolAddress((void**)&buf, g_buf);
    cudaGetSymbolAddress((void**)&q,   g_q);
    cudaGetSymbolAddress((void**)&k,   g_k);
    cudaGetSymbolAddress((void**)&v,   g_v);
    cudaGetSymbolAddress((void**)&o,   g_o);
    cudaGetSymbolAddress((void**)&sc,  g_scores);
    cudaGetSymbolAddress((void**)&u,   g_u);
    cudaGetSymbolAddress((void**)&vf,  g_vf);

    const long TD = (long)NTOK * DIM;
    const long XD = (long)DIM * NTOK;
    const float iscale = 0.125f;

    // 1) embedding modulation
    emb_kernel<<<BSZ, 2 * DIM>>>(emb, w_emb, b_emb);
    // 2) GroupNorm stats + apply + silu
    gn_stats_kernel<<<BSZ * GROUPS, 256>>>(x);
    gn_apply_kernel<<<(int)((long)BSZ * DIM * NTOK / 256), 256>>>(x, gn_g, gn_b, buf);
    // 3) 1x1 conv + residual, token-major output
    launch_gemm(buf, 1, NTOK, XD, 0,
                conv_w, DIM, 1, 0, 0,
                xt, DIM, 1, TD, 0,
                conv_b, 2,
                x, 1, NTOK, XD, 0,
                NTOK, DIM, DIM, BSZ, 1, 1.f);

    // ---- self attention ----
    layernorm_kernel<<<BSZ * NTOK, 256>>>(xt, buf, ln1_g, ln1_b);
    launch_gemm(buf, DIM, 1, 0, 0, a1_wq, DIM, 1, 0, 0, q, INNER, 1, 0, 0,
                nullptr, 0, nullptr, 0, 0, 0, 0, BSZ * NTOK, INNER, DIM, 1, 1, 1.f);
    launch_gemm(buf, DIM, 1, 0, 0, a1_wk, DIM, 1, 0, 0, k, INNER, 1, 0, 0,
                nullptr, 0, nullptr, 0, 0, 0, 0, BSZ * NTOK, INNER, DIM, 1, 1, 1.f);
    launch_gemm(buf, DIM, 1, 0, 0, a1_wv, DIM, 1, 0, 0, v, INNER, 1, 0, 0,
                nullptr, 0, nullptr, 0, 0, 0, 0, BSZ * NTOK, INNER, DIM, 1, 1, 1.f);
    launch_gemm(q, INNER, 1, TD, DHEAD,
                k, INNER, 1, TD, DHEAD,
                sc, NTOK, 1, (long)HEADS * NTOK * NTOK, (long)NTOK * NTOK,
                nullptr, 0, nullptr, 0, 0, 0, 0,
                NTOK, NTOK, DHEAD, BSZ * HEADS, HEADS, iscale);
    softmax_kernel<<<BSZ * HEADS * NTOK, 256>>>(sc, NTOK);
    launch_gemm(sc, NTOK, 1, (long)HEADS * NTOK * NTOK, (long)NTOK * NTOK,
                v, 1, INNER, TD, DHEAD,
                o, INNER, 1, TD, DHEAD,
                nullptr, 0, nullptr, 0, 0, 0, 0,
                NTOK, DHEAD, NTOK, BSZ * HEADS, HEADS, 1.f);
    launch_gemm(o, INNER, 1, 0, 0, a1_wo, INNER, 1, 0, 0, xt, DIM, 1, 0, 0,
                a1_bo, 2, xt, DIM, 1, 0, 0,
                BSZ * NTOK, DIM, INNER, 1, 1, 1.f);

    // ---- cross attention ----
    layernorm_kernel<<<BSZ * NTOK, 256>>>(xt, buf, ln2_g, ln2_b);
    launch_gemm(buf, DIM, 1, 0, 0, a2_wq, DIM, 1, 0, 0, q, INNER, 1, 0, 0,
                nullptr, 0, nullptr, 0, 0, 0, 0, BSZ * NTOK, INNER, DIM, 1, 1, 1.f);
    launch_gemm(ctx, 1, MTOK, (long)CDIM * MTOK, 0,
                a2_wk, CDIM, 1, 0, 0,
                k, INNER, 1, (long)MTOK * INNER, 0,
                nullptr, 0, nullptr, 0, 0, 0, 0,
                MTOK, INNER, CDIM, BSZ, 1, 1.f);
    launch_gemm(ctx, 1, MTOK, (long)CDIM * MTOK, 0,
                a2_wv, CDIM, 1, 0, 0,
                v, INNER, 1, (long)MTOK * INNER, 0,
                nullptr, 0, nullptr, 0, 0, 0, 0,
                MTOK, INNER, CDIM, BSZ, 1, 1.f);
    launch_gemm(q, INNER, 1, TD, DHEAD,
                k, INNER, 1, (long)MTOK * INNER, DHEAD,
                sc, MTOK, 1, (long)HEADS * NTOK * MTOK, (long)NTOK * MTOK,
                nullptr, 0, nullptr, 0, 0, 0, 0,
                NTOK, MTOK, DHEAD, BSZ * HEADS, HEADS, iscale);
    softmax_kernel<<<BSZ * HEADS * NTOK, 256>>>(sc, MTOK);
    launch_gemm(sc, MTOK, 1, (long)HEADS * NTOK * MTOK, (long)NTOK * MTOK,
                v, 1, INNER, (long)MTOK * INNER, DHEAD,
                o, INNER, 1, TD, DHEAD,
                nullptr, 0, nullptr, 0, 0, 0, 0,
                NTOK, DHEAD, MTOK, BSZ * HEADS, HEADS, 1.f);
    launch_gemm(o, INNER, 1, 0, 0, a2_wo, INNER, 1, 0, 0, xt, DIM, 1, 0, 0,
                a2_bo, 2, xt, DIM, 1, 0, 0,
                BSZ * NTOK, DIM, INNER, 1, 1, 1.f);

    // ---- GEGLU feed-forward ----
    layernorm_kernel<<<BSZ * NTOK, 256>>>(xt, buf, ln3_g, ln3_b);
    launch_gemm(buf, DIM, 1, 0, 0, ff_w1, DIM, 1, 0, 0, u, 2 * DFF, 1, 0, 0,
                ff_b1, 2, nullptr, 0, 0, 0, 0,
                BSZ * NTOK, 2 * DFF, DIM, 1, 1, 1.f);
    geglu_kernel<<<(int)((long)BSZ * NTOK * DFF / 256), 256>>>(u, vf);
    launch_gemm(vf, DFF, 1, 0, 0, ff_w2, DFF, 1, 0, 0, xt, DIM, 1, 0, 0,
                ff_b2, 2, xt, DIM, 1, 0, 0,
                BSZ * NTOK, DIM, DFF, 1, 1, 1.f);

    // ---- back to [B, DIM, N] ----
    out_transpose_kernel<<<dim3(NTOK / 32, DIM / 32, BSZ), dim3(32, 8)>>>(xt, out);
}

// round 4
// speedup vs baseline: 4.1461x; 1.4798x over previous
#include <cuda_runtime.h>
#include <cuda_bf16.h>
#include <math.h>
#include <stdint.h>

#define BSZ   8
#define DIM   512
#define NTOK  1024
#define EMBD  128
#define CDIM  512
#define MTOK  256
#define HEADS 8
#define DHEAD 64
#define INNER 512
#define DFF   2048
#define GROUPS 32

// ---------------- scratch (device globals; no allocations allowed) ----------
__device__ float g_xt [BSZ*NTOK*DIM];
__device__ float g_buf[BSZ*NTOK*DIM];
__device__ float g_q  [BSZ*NTOK*INNER];   // holds bf16 (reinterpreted)
__device__ float g_k  [BSZ*NTOK*INNER];   // holds bf16
__device__ float g_v  [BSZ*NTOK*INNER];   // holds bf16
__device__ float g_o  [BSZ*NTOK*INNER];   // fp32 attention output
__device__ float g_u  [BSZ*NTOK*2*DFF];
__device__ float g_vf [BSZ*NTOK*DFF];
__device__ float g_scale[BSZ*DIM];
__device__ float g_shift[BSZ*DIM];
__device__ float g_gn_mu[BSZ*GROUPS];
__device__ float g_gn_rs[BSZ*GROUPS];

// ---------------- small reductions -----------------------------------------
__device__ __forceinline__ float block_reduce_sum(float v, float* sh) {
    __syncthreads();
    #pragma unroll
    for (int o = 16; o > 0; o >>= 1) v += __shfl_xor_sync(0xffffffffu, v, o);
    int warp = threadIdx.x >> 5;
    if ((threadIdx.x & 31) == 0) sh[warp] = v;
    __syncthreads();
    int nw = blockDim.x >> 5;
    v = (threadIdx.x < nw) ? sh[threadIdx.x] : 0.f;
    if (threadIdx.x < 32) {
        #pragma unroll
        for (int o = 16; o > 0; o >>= 1) v += __shfl_xor_sync(0xffffffffu, v, o);
    }
    if (threadIdx.x == 0) sh[0] = v;
    __syncthreads();
    return sh[0];
}

// ---------------- bf16 tensor-core mma --------------------------------------
__device__ __forceinline__ void mma16816(float* c, const uint32_t* a, const uint32_t* b) {
    asm volatile(
        "mma.sync.aligned.m16n8k16.row.col.f32.bf16.bf16.f32 "
        "{%0,%1,%2,%3}, {%4,%5,%6,%7}, {%8,%9}, {%0,%1,%2,%3};\n"
        : "+f"(c[0]), "+f"(c[1]), "+f"(c[2]), "+f"(c[3])
        : "r"(a[0]), "r"(a[1]), "r"(a[2]), "r"(a[3]), "r"(b[0]), "r"(b[1]));
}

// ---------------- generic strided batched GEMM (bf16 MMA, fp32 in) ----------
// C[i,j] = alpha * sum_k A[i*sAi+k*sAk] * B[j*sBj+k*sBk] (+bias)(+res)
// out_bf16: C is __nv_bfloat16* (strides in elements), else float*.
template<int BM, int BN, int WM, int WN>
__global__ __launch_bounds__(256) void gemm_bf16(
    const float* __restrict__ A, long sAi, long sAk, long sAo, long sAin,
    const float* __restrict__ Bm, long sBj, long sBk, long sBo, long sBin,
    void* __restrict__ Cv, long sCi, long sCj, long sCo, long sCin,
    const float* __restrict__ bias, int bias_mode,
    const float* __restrict__ Res, long sRi, long sRj, long sRo, long sRin,
    int K, int batchInner, float alpha, int out_bf16)
{
    constexpr int BK = 32;
    constexpr int AP = BK + 8;
    constexpr int WARPS_N = BN / WN;
    constexpr int MT = WM / 16;
    constexpr int NT = WN / 8;
    constexpr int ARV = BM * BK / 256;
    constexpr int BRV = BN * BK / 256;

    int z = blockIdx.z;
    int zo = z / batchInner, zi = z - zo * batchInner;
    A  += zo * sAo + zi * sAin;
    Bm += zo * sBo + zi * sBin;
    long cOff = zo * sCo + zi * sCin;
    if (Res) Res += zo * sRo + zi * sRin;

    int i0 = blockIdx.y * BM;
    int j0 = blockIdx.x * BN;

    __shared__ __nv_bfloat16 As[2][BM][AP];
    __shared__ __nv_bfloat16 Bs[2][BN][AP];

    int tid  = threadIdx.x;
    int warp = tid >> 5;
    int lane = tid & 31;
    int g    = lane >> 2;
    int tg   = lane & 3;
    int warp_m = warp / WARPS_N;
    int warp_n = warp % WARPS_N;
    int m_w = warp_m * WM;
    int n_w = warp_n * WN;

    const bool aCont = (sAk == 1);
    const bool bCont = (sBk == 1);

    float ra[ARV], rb[BRV];
    float acc[MT][NT][4] = {};

    #define LOAD_A(K0)                                                          \
        if (aCont) {                                                            \
            _Pragma("unroll")                                                   \
            for (int s = 0; s < ARV/4; s++) {                                   \
                int q = tid + s * 256;                                          \
                int i = q >> 3, kq = (q & 7) * 4;                               \
                float4 vv = *reinterpret_cast<const float4*>(                   \
                    A + (long)(i0 + i) * sAi + ((K0) + kq));                    \
                ra[s*4+0]=vv.x; ra[s*4+1]=vv.y; ra[s*4+2]=vv.z; ra[s*4+3]=vv.w; \
            }                                                                   \
        } else {                                                                \
            _Pragma("unroll")                                                   \
            for (int r = 0; r < ARV; r++) {                                     \
                int e = tid + r * 256;                                          \
                int i = e & (BM - 1), k = e / BM;                               \
                ra[r] = A[(long)(i0 + i) * sAi + (long)((K0) + k) * sAk];       \
            }                                                                   \
        }
    #define STORE_A(BUF)                                                        \
        if (aCont) {                                                            \
            _Pragma("unroll")                                                   \
            for (int s = 0; s < ARV/4; s++) {                                   \
                int q = tid + s * 256;                                          \
                int i = q >> 3, kq = (q & 7) * 4;                               \
                __nv_bfloat162 p0 = __floats2bfloat162_rn(ra[s*4+0], ra[s*4+1]);\
                __nv_bfloat162 p1 = __floats2bfloat162_rn(ra[s*4+2], ra[s*4+3]);\
                *reinterpret_cast<__nv_bfloat162*>(&As[BUF][i][kq])   = p0;     \
                *reinterpret_cast<__nv_bfloat162*>(&As[BUF][i][kq+2]) = p1;     \
            }                                                                   \
        } else {                                                                \
            _Pragma("unroll")                                                   \
            for (int r = 0; r < ARV; r++) {                                     \
                int e = tid + r * 256;                                          \
                int i = e & (BM - 1), k = e / BM;                               \
                As[BUF][i][k] = __float2bfloat16_rn(ra[r]);                     \
            }                                                                   \
        }
    #define LOAD_B(K0)                                                          \
        if (bCont) {                                                            \
            _Pragma("unroll")                                                   \
            for (int s = 0; s < BRV/4; s++) {                                   \
                int q = tid + s * 256;                                          \
                int j = q >> 3, kq = (q & 7) * 4;                               \
                float4 vv = *reinterpret_cast<const float4*>(                   \
                    Bm + (long)(j0 + j) * sBj + ((K0) + kq));                   \
                rb[s*4+0]=vv.x; rb[s*4+1]=vv.y; rb[s*4+2]=vv.z; rb[s*4+3]=vv.w; \
            }                                                                   \
        } else {                                                                \
            _Pragma("unroll")                                                   \
            for (int r = 0; r < BRV; r++) {                                     \
                int e = tid + r * 256;                                          \
                int j = e & (BN - 1), k = e / BN;                               \
                rb[r] = Bm[(long)(j0 + j) * sBj + (long)((K0) + k) * sBk];      \
            }                                                                   \
        }
    #define STORE_B(BUF)                                                        \
        if (bCont) {                                                            \
            _Pragma("unroll")                                                   \
            for (int s = 0; s < BRV/4; s++) {                                   \
                int q = tid + s * 256;                                          \
                int j = q >> 3, kq = (q & 7) * 4;                               \
                __nv_bfloat162 p0 = __floats2bfloat162_rn(rb[s*4+0], rb[s*4+1]);\
                __nv_bfloat162 p1 = __floats2bfloat162_rn(rb[s*4+2], rb[s*4+3]);\
                *reinterpret_cast<__nv_bfloat162*>(&Bs[BUF][j][kq])   = p0;     \
                *reinterpret_cast<__nv_bfloat162*>(&Bs[BUF][j][kq+2]) = p1;     \
            }                                                                   \
        } else {                                                                \
            _Pragma("unroll")                                                   \
            for (int r = 0; r < BRV; r++) {                                     \
                int e = tid + r * 256;                                          \
                int j = e & (BN - 1), k = e / BN;                               \
                Bs[BUF][j][k] = __float2bfloat16_rn(rb[r]);                     \
            }                                                                   \
        }

    LOAD_A(0) LOAD_B(0) STORE_A(0) STORE_B(0)
    __syncthreads();

    int KB = K / BK;
    for (int kb = 0; kb < KB; kb++) {
        int cur = kb & 1;
        if (kb + 1 < KB) {
            int k0 = (kb + 1) * BK;
            LOAD_A(k0) LOAD_B(k0)
        }
        #pragma unroll
        for (int ks = 0; ks < BK; ks += 16) {
            uint32_t af[MT][4];
            uint32_t bf[NT][2];
            #pragma unroll
            for (int mt = 0; mt < MT; mt++) {
                const __nv_bfloat16* pa = &As[cur][m_w + mt*16 + g][ks + tg*2];
                af[mt][0] = *reinterpret_cast<const uint32_t*>(pa);
                af[mt][1] = *reinterpret_cast<const uint32_t*>(pa + 8*AP);
                af[mt][2] = *reinterpret_cast<const uint32_t*>(pa + 8);
                af[mt][3] = *reinterpret_cast<const uint32_t*>(pa + 8*AP + 8);
            }
            #pragma unroll
            for (int nt = 0; nt < NT; nt++) {
                const __nv_bfloat16* pb = &Bs[cur][n_w + nt*8 + g][ks + tg*2];
                bf[nt][0] = *reinterpret_cast<const uint32_t*>(pb);
                bf[nt][1] = *reinterpret_cast<const uint32_t*>(pb + 8);
            }
            #pragma unroll
            for (int mt = 0; mt < MT; mt++)
                #pragma unroll
                for (int nt = 0; nt < NT; nt++)
                    mma16816(acc[mt][nt], af[mt], bf[nt]);
        }
        if (kb + 1 < KB) {
            int nb = cur ^ 1;
            STORE_A(nb) STORE_B(nb)
        }
        __syncthreads();
    }

    // ---------- epilogue ----------
    float* Cf = reinterpret_cast<float*>(Cv) + cOff;
    __nv_bfloat16* Ch = reinterpret_cast<__nv_bfloat16*>(Cv) + cOff;
    #pragma unroll
    for (int mt = 0; mt < MT; mt++) {
        #pragma unroll
        for (int h = 0; h < 2; h++) {
            int i = i0 + m_w + mt*16 + g + 8*h;
            float bi = (bias_mode == 1) ? bias[i] : 0.f;
            #pragma unroll
            for (int nt = 0; nt < NT; nt++) {
                int j = j0 + n_w + nt*8 + tg*2;
                float v0 = alpha * acc[mt][nt][2*h+0] + bi;
                float v1 = alpha * acc[mt][nt][2*h+1] + bi;
                if (bias_mode == 2) { v0 += bias[j]; v1 += bias[j+1]; }
                if (Res) {
                    v0 += Res[(long)i * sRi + (long)j * sRj];
                    v1 += Res[(long)i * sRi + (long)(j+1) * sRj];
                }
                if (out_bf16) {
                    __nv_bfloat162 p = __floats2bfloat162_rn(v0, v1);
                    *reinterpret_cast<__nv_bfloat162*>(&Ch[(long)i * sCi + j]) = p;
                } else if (sCj == 1) {
                    *reinterpret_cast<float2*>(&Cf[(long)i * sCi + j]) = make_float2(v0, v1);
                } else {
                    Cf[(long)i * sCi + (long)j     * sCj] = v0;
                    Cf[(long)i * sCi + (long)(j+1) * sCj] = v1;
                }
            }
        }
    }
    #undef LOAD_A
    #undef STORE_A
    #undef LOAD_B
    #undef STORE_B
}

// ---------------- fused flash attention -------------------------------------
// Q/K/V bf16 [B][Ntok][INNER] (head-offset view), O fp32 same layout.
// Block: 128 threads (4 warps), 64 q rows; key tiles of 64.
#define FPITCH 72
__global__ __launch_bounds__(128) void flash_kernel(
    const __nv_bfloat16* __restrict__ Q,
    const __nv_bfloat16* __restrict__ K,
    const __nv_bfloat16* __restrict__ V,
    float* __restrict__ O,
    int nk, long kv_bstride)
{
    __shared__ __nv_bfloat16 Qs[64][FPITCH];
    __shared__ __nv_bfloat16 Ks[64][FPITCH];
    __shared__ __nv_bfloat16 Vs[64][FPITCH];

    int tid = threadIdx.x, warp = tid >> 5, lane = tid & 31;
    int g = lane >> 2, tg = lane & 3;
    int b = blockIdx.y / HEADS, h = blockIdx.y % HEADS;
    const __nv_bfloat16* qb = Q + ((long)b*NTOK + blockIdx.x*64)*INNER + h*DHEAD;
    const __nv_bfloat16* kb = K + (long)b*kv_bstride + h*DHEAD;
    const __nv_bfloat16* vb = V + (long)b*kv_bstride + h*DHEAD;
    float* ob = O + ((long)b*NTOK + blockIdx.x*64)*INNER + h*DHEAD;

    #pragma unroll
    for (int t = 0; t < 4; t++) {
        int c = tid + t*128;
        int r = c >> 3, c8 = (c & 7) * 8;
        *reinterpret_cast<uint4*>(&Qs[r][c8]) =
            *reinterpret_cast<const uint4*>(&qb[(long)r*INNER + c8]);
    }

    int mrow = warp * 16;
    float m_i[2] = {-1e30f, -1e30f}, l_i[2] = {0.f, 0.f};
    float oa[8][4];
    #pragma unroll
    for (int nt = 0; nt < 8; nt++) { oa[nt][0]=0.f; oa[nt][1]=0.f; oa[nt][2]=0.f; oa[nt][3]=0.f; }

    __syncthreads();

    for (int kt = 0; kt < nk; kt += 64) {
        #pragma unroll
        for (int t = 0; t < 4; t++) {
            int c = tid + t*128;
            int r = c >> 3, c8 = (c & 7) * 8;
            *reinterpret_cast<uint4*>(&Ks[r][c8]) =
                *reinterpret_cast<const uint4*>(&kb[(long)(kt + r)*INNER + c8]);
            *reinterpret_cast<uint4*>(&Vs[r][c8]) =
                *reinterpret_cast<const uint4*>(&vb[(long)(kt + r)*INNER + c8]);
        }
        __syncthreads();

        // ---- scores: S = Q @ K^T (scale pre-folded into Q) ----
        float s[8][4] = {};
        #pragma unroll
        for (int kc = 0; kc < 64; kc += 16) {
            uint32_t aq[4];
            const __nv_bfloat16* pa = &Qs[mrow + g][kc + tg*2];
            aq[0] = *reinterpret_cast<const uint32_t*>(pa);
            aq[1] = *reinterpret_cast<const uint32_t*>(pa + 8*FPITCH);
            aq[2] = *reinterpret_cast<const uint32_t*>(pa + 8);
            aq[3] = *reinterpret_cast<const uint32_t*>(pa + 8*FPITCH + 8);
            #pragma unroll
            for (int nt = 0; nt < 8; nt++) {
                uint32_t bk[2];
                const __nv_bfloat16* pb = &Ks[nt*8 + g][kc + tg*2];
                bk[0] = *reinterpret_cast<const uint32_t*>(pb);
                bk[1] = *reinterpret_cast<const uint32_t*>(pb + 8);
                mma16816(s[nt], aq, bk);
            }
        }

        // ---- online softmax ----
        #pragma unroll
        for (int h2 = 0; h2 < 2; h2++) {
            float mt = -1e30f;
            #pragma unroll
            for (int nt = 0; nt < 8; nt++)
                mt = fmaxf(mt, fmaxf(s[nt][2*h2], s[nt][2*h2+1]));
            mt = fmaxf(mt, __shfl_xor_sync(0xffffffffu, mt, 1));
            mt = fmaxf(mt, __shfl_xor_sync(0xffffffffu, mt, 2));
            float mnew = fmaxf(m_i[h2], mt);
            float corr = __expf(m_i[h2] - mnew);
            m_i[h2] = mnew;
            float lsum = 0.f;
            #pragma unroll
            for (int nt = 0; nt < 8; nt++) {
                float e0 = __expf(s[nt][2*h2]   - mnew);
                float e1 = __expf(s[nt][2*h2+1] - mnew);
                s[nt][2*h2] = e0; s[nt][2*h2+1] = e1;
                lsum += e0 + e1;
            }
            lsum += __shfl_xor_sync(0xffffffffu, lsum, 1);
            lsum += __shfl_xor_sync(0xffffffffu, lsum, 2);
            l_i[h2] = l_i[h2] * corr + lsum;
            #pragma unroll
            for (int nt = 0; nt < 8; nt++) { oa[nt][2*h2] *= corr; oa[nt][2*h2+1] *= corr; }
        }

        // ---- O += P @ V ----
        #pragma unroll
        for (int kc = 0; kc < 4; kc++) {
            uint32_t ap[4];
            __nv_bfloat162 t0 = __floats2bfloat162_rn(s[2*kc][0],   s[2*kc][1]);
            __nv_bfloat162 t1 = __floats2bfloat162_rn(s[2*kc][2],   s[2*kc][3]);
            __nv_bfloat162 t2 = __floats2bfloat162_rn(s[2*kc+1][0], s[2*kc+1][1]);
            __nv_bfloat162 t3 = __floats2bfloat162_rn(s[2*kc+1][2], s[2*kc+1][3]);
            ap[0] = *reinterpret_cast<uint32_t*>(&t0);
            ap[1] = *reinterpret_cast<uint32_t*>(&t1);
            ap[2] = *reinterpret_cast<uint32_t*>(&t2);
            ap[3] = *reinterpret_cast<uint32_t*>(&t3);
            #pragma unroll
            for (int nt = 0; nt < 8; nt++) {
                uint32_t bv[2];
                uint16_t x0 = *reinterpret_cast<const uint16_t*>(&Vs[kc*16 + 2*tg    ][nt*8 + g]);
                uint16_t x1 = *reinterpret_cast<const uint16_t*>(&Vs[kc*16 + 2*tg + 1][nt*8 + g]);
                uint16_t x2 = *reinterpret_cast<const uint16_t*>(&Vs[kc*16 + 2*tg + 8][nt*8 + g]);
                uint16_t x3 = *reinterpret_cast<const uint16_t*>(&Vs[kc*16 + 2*tg + 9][nt*8 + g]);
                bv[0] = (uint32_t)x0 | ((uint32_t)x1 << 16);
                bv[1] = (uint32_t)x2 | ((uint32_t)x3 << 16);
                mma16816(oa[nt], ap, bv);
            }
        }
        __syncthreads();
    }

    #pragma unroll
    for (int h2 = 0; h2 < 2; h2++) {
        float inv = 1.f / l_i[h2];
        int r = mrow + g + 8*h2;
        #pragma unroll
        for (int nt = 0; nt < 8; nt++) {
            float2 w = make_float2(oa[nt][2*h2] * inv, oa[nt][2*h2+1] * inv);
            *reinterpret_cast<float2*>(&ob[(long)r*INNER + nt*8 + tg*2]) = w;
        }
    }
}

// ---------------- tiny / elementwise kernels --------------------------------
__global__ void emb_kernel(const float* __restrict__ emb,
                           const float* __restrict__ w,
                           const float* __restrict__ bias)
{
    int b = blockIdx.x;
    __shared__ float e[EMBD];
    if (threadIdx.x < EMBD) {
        float v = emb[b * EMBD + threadIdx.x];
        e[threadIdx.x] = v / (1.f + __expf(-v));
    }
    __syncthreads();
    int o = threadIdx.x;
    float acc = bias[o];
    const float* wr = w + (long)o * EMBD;
    #pragma unroll 8
    for (int kk = 0; kk < EMBD; kk++) acc += e[kk] * wr[kk];
    if (o < DIM) g_scale[b * DIM + o] = 1.f + acc;
    else         g_shift[b * DIM + (o - DIM)] = acc;
}

__global__ void gn_stats_kernel(const float* __restrict__ X)
{
    __shared__ float sh[32];
    int b = blockIdx.x / GROUPS, g = blockIdx.x % GROUPS;
    const int CH = DIM / GROUPS;
    const float* p = X + ((long)b * DIM + (long)g * CH) * NTOK;
    float s = 0.f, ss = 0.f;
    for (int i = threadIdx.x; i < CH * NTOK; i += blockDim.x) {
        float v = p[i]; s += v; ss += v * v;
    }
    s  = block_reduce_sum(s, sh);
    ss = block_reduce_sum(ss, sh);
    if (threadIdx.x == 0) {
        float inv = 1.f / (CH * NTOK);
        float mu = s * inv;
        float var = ss * inv - mu * mu;
        g_gn_mu[blockIdx.x] = mu;
        g_gn_rs[blockIdx.x] = rsqrtf(var + 1e-6f);
    }
}

__global__ void gn_apply_kernel(const float* __restrict__ X,
                                const float* __restrict__ gn_g,
                                const float* __restrict__ gn_b,
                                float* __restrict__ H)
{
    long idx = (long)blockIdx.x * blockDim.x + threadIdx.x;
    long bc = idx >> 10;
    int c = (int)(bc % DIM);
    int b = (int)(bc / DIM);
    int grp = b * GROUPS + (c >> 4);
    float v = (X[idx] - g_gn_mu[grp]) * g_gn_rs[grp] * gn_g[c] + gn_b[c];
    v = v * g_scale[bc] + g_shift[bc];
    H[idx] = v / (1.f + __expf(-v));
}

__global__ void layernorm_kernel(const float* __restrict__ X, float* __restrict__ Y,
                                 const float* __restrict__ g, const float* __restrict__ b)
{
    __shared__ float sh[32];
    long t = blockIdx.x;
    const float* x = X + t * DIM;
    float* y = Y + t * DIM;
    float s = 0.f, ss = 0.f;
    for (int i = threadIdx.x; i < DIM; i += blockDim.x) {
        float v = x[i]; s += v; ss += v * v;
    }
    s  = block_reduce_sum(s, sh);
    ss = block_reduce_sum(ss, sh);
    float mu = s * (1.f / DIM);
    float var = ss * (1.f / DIM) - mu * mu;
    float rs = rsqrtf(var + 1e-5f);
    for (int i = threadIdx.x; i < DIM; i += blockDim.x)
        y[i] = (x[i] - mu) * rs * g[i] + b[i];
}

__global__ void geglu_kernel(const float* __restrict__ U, float* __restrict__ V)
{
    long idx = (long)blockIdx.x * blockDim.x + threadIdx.x;
    long t = idx / DFF;
    int f = (int)(idx - t * DFF);
    float a = U[t * (2 * DFF) + f];
    float gg = U[t * (2 * DFF) + DFF + f];
    float ge = 0.5f * gg * (1.f + erff(gg * 0.70710678118654752f));
    V[idx] = a * ge;
}

__global__ void out_transpose_kernel(const float* __restrict__ XT, float* __restrict__ OUT)
{
    __shared__ float tile[32][33];
    int b = blockIdx.z;
    int n0 = blockIdx.x * 32, c0 = blockIdx.y * 32;
    for (int r = threadIdx.y; r < 32; r += 8)
        tile[r][threadIdx.x] = XT[((long)b * NTOK + n0 + r) * DIM + c0 + threadIdx.x];
    __syncthreads();
    for (int r = threadIdx.y; r < 32; r += 8)
        OUT[((long)b * DIM + c0 + r) * NTOK + n0 + threadIdx.x] = tile[threadIdx.x][r];
}

// ---------------- host orchestration ----------------------------------------
static void launch_gemm(const float* A, long sAi, long sAk, long sAo, long sAin,
                        const float* Bm, long sBj, long sBk, long sBo, long sBin,
                        void* C, long sCi, long sCj, long sCo, long sCin,
                        const float* bias, int bmode,
                        const float* R, long sRi, long sRj, long sRo, long sRin,
                        int M, int N, int K, int batch, int batchInner, float alpha,
                        int out_bf16)
{
    dim3 grid(N / 128, M / 128, batch);
    gemm_bf16<128,128,64,32><<<grid, 256>>>(A, sAi, sAk, sAo, sAin,
        Bm, sBj, sBk, sBo, sBin, C, sCi, sCj, sCo, sCin,
        bias, bmode, R, sRi, sRj, sRo, sRin, K, batchInner, alpha, out_bf16);
}

extern "C" void kernel_launch(void* const* d_in, const int* in_sizes, int n_in,
                              void* d_out, int out_size)
{
    const float* x      = (const float*)d_in[0];
    const float* emb    = (const float*)d_in[1];
    const float* ctx    = (const float*)d_in[2];
    const float* w_emb  = (const float*)d_in[3];
    const float* b_emb  = (const float*)d_in[4];
    const float* gn_g   = (const float*)d_in[5];
    const float* gn_b   = (const float*)d_in[6];
    const float* conv_w = (const float*)d_in[7];
    const float* conv_b = (const float*)d_in[8];
    const float* a1_wq  = (const float*)d_in[9];
    const float* a1_wk  = (const float*)d_in[10];
    const float* a1_wv  = (const float*)d_in[11];
    const float* a1_wo  = (const float*)d_in[12];
    const float* a1_bo  = (const float*)d_in[13];
    const float* a2_wq  = (const float*)d_in[14];
    const float* a2_wk  = (const float*)d_in[15];
    const float* a2_wv  = (const float*)d_in[16];
    const float* a2_wo  = (const float*)d_in[17];
    const float* a2_bo  = (const float*)d_in[18];
    const float* ln1_g  = (const float*)d_in[19];
    const float* ln1_b  = (const float*)d_in[20];
    const float* ln2_g  = (const float*)d_in[21];
    const float* ln2_b  = (const float*)d_in[22];
    const float* ln3_g  = (const float*)d_in[23];
    const float* ln3_b  = (const float*)d_in[24];
    const float* ff_w1  = (const float*)d_in[25];
    const float* ff_b1  = (const float*)d_in[26];
    const float* ff_w2  = (const float*)d_in[27];
    const float* ff_b2  = (const float*)d_in[28];
    float* out = (float*)d_out;

    float *xt, *buf, *q, *k, *v, *o, *u, *vf;
    cudaGetSymbolAddress((void**)&xt,  g_xt);
    cudaGetSymbolAddress((void**)&buf, g_buf);
    cudaGetSymbolAddress((void**)&q,   g_q);
    cudaGetSymbolAddress((void**)&k,   g_k);
    cudaGetSymbolAddress((void**)&v,   g_v);
    cudaGetSymbolAddress((void**)&o,   g_o);
    cudaGetSymbolAddress((void**)&u,   g_u);
    cudaGetSymbolAddress((void**)&vf,  g_vf);
    __nv_bfloat16* qh = (__nv_bfloat16*)q;
    __nv_bfloat16* kh = (__nv_bfloat16*)k;
    __nv_bfloat16* vh = (__nv_bfloat16*)v;

    const long TD = (long)NTOK * DIM;
    const long XD = (long)DIM * NTOK;
    const float iscale = 0.125f;   // 1/sqrt(DHEAD), folded into Q projection

    emb_kernel<<<BSZ, 2 * DIM>>>(emb, w_emb, b_emb);
    gn_stats_kernel<<<BSZ * GROUPS, 256>>>(x);
    gn_apply_kernel<<<(int)((long)BSZ * DIM * NTOK / 256), 256>>>(x, gn_g, gn_b, buf);
    // 1x1 conv + residual -> token-major xt (fp32)
    launch_gemm(buf, 1, NTOK, XD, 0,
                conv_w, DIM, 1, 0, 0,
                xt, DIM, 1, TD, 0,
                conv_b, 2,
                x, 1, NTOK, XD, 0,
                NTOK, DIM, DIM, BSZ, 1, 1.f, 0);

    // ---- self attention (fused flash) ----
    layernorm_kernel<<<BSZ * NTOK, 256>>>(xt, buf, ln1_g, ln1_b);
    launch_gemm(buf, DIM, 1, 0, 0, a1_wq, DIM, 1, 0, 0, qh, INNER, 1, 0, 0,
                nullptr, 0, nullptr, 0, 0, 0, 0, BSZ * NTOK, INNER, DIM, 1, 1, iscale, 1);
    launch_gemm(buf, DIM, 1, 0, 0, a1_wk, DIM, 1, 0, 0, kh, INNER, 1, 0, 0,
                nullptr, 0, nullptr, 0, 0, 0, 0, BSZ * NTOK, INNER, DIM, 1, 1, 1.f, 1);
    launch_gemm(buf, DIM, 1, 0, 0, a1_wv, DIM, 1, 0, 0, vh, INNER, 1, 0, 0,
                nullptr, 0, nullptr, 0, 0, 0, 0, BSZ * NTOK, INNER, DIM, 1, 1, 1.f, 1);
    flash_kernel<<<dim3(NTOK/64, BSZ*HEADS), 128>>>(qh, kh, vh, o, NTOK, (long)NTOK*INNER);
    launch_gemm(o, INNER, 1, 0, 0, a1_wo, INNER, 1, 0, 0, xt, DIM, 1, 0, 0,
                a1_bo, 2, xt, DIM, 1, 0, 0,
                BSZ * NTOK, DIM, INNER, 1, 1, 1.f, 0);

    // ---- cross attention (fused flash) ----
    layernorm_kernel<<<BSZ * NTOK, 256>>>(xt, buf, ln2_g, ln2_b);
    launch_gemm(buf, DIM, 1, 0, 0, a2_wq, DIM, 1, 0, 0, qh, INNER, 1, 0, 0,
                nullptr, 0, nullptr, 0, 0, 0, 0, BSZ * NTOK, INNER, DIM, 1, 1, iscale, 1);
    launch_gemm(ctx, 1, MTOK, (long)CDIM * MTOK, 0,
                a2_wk, CDIM, 1, 0, 0,
                kh, INNER, 1, (long)MTOK * INNER, 0,
                nullptr, 0, nullptr, 0, 0, 0, 0,
                MTOK, INNER, CDIM, BSZ, 1, 1.f, 1);
    launch_gemm(ctx, 1, MTOK, (long)CDIM * MTOK, 0,
                a2_wv, CDIM, 1, 0, 0,
                vh, INNER, 1, (long)MTOK * INNER, 0,
                nullptr, 0, nullptr, 0, 0, 0, 0,
                MTOK, INNER, CDIM, BSZ, 1, 1.f, 1);
    flash_kernel<<<dim3(NTOK/64, BSZ*HEADS), 128>>>(qh, kh, vh, o, MTOK, (long)MTOK*INNER);
    launch_gemm(o, INNER, 1, 0, 0, a2_wo, INNER, 1, 0, 0, xt, DIM, 1, 0, 0,
                a2_bo, 2, xt, DIM, 1, 0, 0,
                BSZ * NTOK, DIM, INNER, 1, 1, 1.f, 0);

    // ---- GEGLU feed-forward ----
    layernorm_kernel<<<BSZ * NTOK, 256>>>(xt, buf, ln3_g, ln3_b);
    launch_gemm(buf, DIM, 1, 0, 0, ff_w1, DIM, 1, 0, 0, u, 2 * DFF, 1, 0, 0,
                ff_b1, 2, nullptr, 0, 0, 0, 0,
                BSZ * NTOK, 2 * DFF, DIM, 1, 1, 1.f, 0);
    geglu_kernel<<<(int)((long)BSZ * NTOK * DFF / 256), 256>>>(u, vf);
    launch_gemm(vf, DFF, 1, 0, 0, ff_w2, DFF, 1, 0, 0, xt, DIM, 1, 0, 0,
                ff_b2, 2, xt, DIM, 1, 0, 0,
                BSZ * NTOK, DIM, DFF, 1, 1, 1.f, 0);

    // ---- back to [B, DIM, N] ----
    out_transpose_kernel<<<dim3(NTOK / 32, DIM / 32, BSZ), dim3(32, 8)>>>(xt, out);
}

// round 6
// speedup vs baseline: 5.2574x; 1.2680x over previous
#include <cuda_runtime.h>
#include <cuda_bf16.h>
#include <math.h>
#include <stdint.h>

#define BSZ   8
#define DIM   512
#define NTOK  1024
#define EMBD  128
#define CDIM  512
#define MTOK  256
#define HEADS 8
#define DHEAD 64
#define INNER 512
#define DFF   2048
#define GROUPS 32

// ---------------- scratch (device globals; no allocations allowed) ----------
__device__ float g_xt [BSZ*NTOK*DIM];            // fp32 residual stream (token-major)
__device__ float g_buf[BSZ*NTOK*DIM];            // fp32 xT residual for conv
__device__ float g_u  [BSZ*NTOK*2*DFF];          // GEGLU pre-activation fp32
__device__ __nv_bfloat16 g_bbuf[BSZ*NTOK*DIM];   // bf16 activations (LN out / silu-h)
__device__ __nv_bfloat16 g_qh [BSZ*NTOK*INNER];
__device__ __nv_bfloat16 g_kh [BSZ*NTOK*INNER];
__device__ __nv_bfloat16 g_vh [BSZ*NTOK*INNER];
__device__ __nv_bfloat16 g_oh [BSZ*NTOK*INNER];
__device__ __nv_bfloat16 g_vfh[BSZ*NTOK*DFF];
__device__ __nv_bfloat16 g_ctxT[BSZ*MTOK*CDIM];
// bf16 weights (converted once per launch)
__device__ __nv_bfloat16 g_wconv[DIM*DIM];
__device__ __nv_bfloat16 g_w1q[INNER*DIM], g_w1k[INNER*DIM], g_w1v[INNER*DIM], g_w1o[DIM*INNER];
__device__ __nv_bfloat16 g_w2q[INNER*DIM], g_w2k[INNER*CDIM], g_w2v[INNER*CDIM], g_w2o[DIM*INNER];
__device__ __nv_bfloat16 g_wf1[2*DFF*DIM], g_wf2[DIM*DFF];
__device__ float g_scale[BSZ*DIM];
__device__ float g_shift[BSZ*DIM];
__device__ float g_gn_mu[BSZ*GROUPS];
__device__ float g_gn_rs[BSZ*GROUPS];

// ---------------- helpers ----------------------------------------------------
__device__ __forceinline__ float block_reduce_sum(float v, float* sh) {
    __syncthreads();
    #pragma unroll
    for (int o = 16; o > 0; o >>= 1) v += __shfl_xor_sync(0xffffffffu, v, o);
    int warp = threadIdx.x >> 5;
    if ((threadIdx.x & 31) == 0) sh[warp] = v;
    __syncthreads();
    int nw = blockDim.x >> 5;
    v = (threadIdx.x < nw) ? sh[threadIdx.x] : 0.f;
    if (threadIdx.x < 32) {
        #pragma unroll
        for (int o = 16; o > 0; o >>= 1) v += __shfl_xor_sync(0xffffffffu, v, o);
    }
    if (threadIdx.x == 0) sh[0] = v;
    __syncthreads();
    return sh[0];
}

__device__ __forceinline__ void mma16816(float* c, const uint32_t* a, const uint32_t* b) {
    asm volatile(
        "mma.sync.aligned.m16n8k16.row.col.f32.bf16.bf16.f32 "
        "{%0,%1,%2,%3}, {%4,%5,%6,%7}, {%8,%9}, {%0,%1,%2,%3};\n"
        : "+f"(c[0]), "+f"(c[1]), "+f"(c[2]), "+f"(c[3])
        : "r"(a[0]), "r"(a[1]), "r"(a[2]), "r"(a[3]), "r"(b[0]), "r"(b[1]));
}

__device__ __forceinline__ void cpa16(uint32_t s, const void* g) {
    asm volatile("cp.async.ca.shared.global [%0], [%1], 16;\n" :: "r"(s), "l"(g));
}
__device__ __forceinline__ void cpa_commit() { asm volatile("cp.async.commit_group;\n"); }
__device__ __forceinline__ void cpa_wait0()  { asm volatile("cp.async.wait_group 0;\n" ::: "memory"); }

// ---------------- bf16 GEMM: C[i,j] = alpha*sum_k A[i,k]*B[j,k] (+bias_j)(+Res)
template<int BM, int BN, int WM, int WN>
__global__ __launch_bounds__(256) void gemm_bb(
    const __nv_bfloat16* __restrict__ A, int lda,
    const __nv_bfloat16* __restrict__ Bm, int ldb,
    void* __restrict__ Cv, int ldc,
    const float* __restrict__ bias,
    const float* __restrict__ Res, int ldr,
    int K, float alpha, int out_bf16)
{
    constexpr int BK = 32, AP = 40;
    constexpr int WARPS_N = BN / WN;
    constexpr int MT = WM / 16, NT = WN / 8;
    constexpr int ACH = BM * 4 / 256;     // 16B chunks per thread for A tile
    constexpr int BCH = BN * 4 / 256;

    int i0 = blockIdx.y * BM, j0 = blockIdx.x * BN;
    __shared__ __align__(16) __nv_bfloat16 As[2][BM][AP];
    __shared__ __align__(16) __nv_bfloat16 Bs[2][BN][AP];
    uint32_t sA0 = (uint32_t)__cvta_generic_to_shared(&As[0][0][0]);
    uint32_t sB0 = (uint32_t)__cvta_generic_to_shared(&Bs[0][0][0]);

    int tid = threadIdx.x, warp = tid >> 5, lane = tid & 31;
    int g = lane >> 2, tg = lane & 3;
    int m_w = (warp / WARPS_N) * WM, n_w = (warp % WARPS_N) * WN;

    float acc[MT][NT][4] = {};

    auto load_tiles = [&](int k0, int buf) {
        #pragma unroll
        for (int t = 0; t < ACH; t++) {
            int c = tid + t * 256;
            int row = c >> 2, off = (c & 3) * 8;
            cpa16(sA0 + buf * (BM * AP * 2) + (row * AP + off) * 2,
                  A + (long)(i0 + row) * lda + k0 + off);
        }
        #pragma unroll
        for (int t = 0; t < BCH; t++) {
            int c = tid + t * 256;
            int row = c >> 2, off = (c & 3) * 8;
            cpa16(sB0 + buf * (BN * AP * 2) + (row * AP + off) * 2,
                  Bm + (long)(j0 + row) * ldb + k0 + off);
        }
        cpa_commit();
    };

    load_tiles(0, 0);
    cpa_wait0();
    __syncthreads();

    int KB = K / BK;
    for (int kb = 0; kb < KB; kb++) {
        int cur = kb & 1;
        if (kb + 1 < KB) load_tiles((kb + 1) * BK, cur ^ 1);
        #pragma unroll
        for (int ks = 0; ks < BK; ks += 16) {
            uint32_t af[MT][4];
            uint32_t bf[NT][2];
            #pragma unroll
            for (int mt = 0; mt < MT; mt++) {
                const __nv_bfloat16* pa = &As[cur][m_w + mt*16 + g][ks + tg*2];
                af[mt][0] = *reinterpret_cast<const uint32_t*>(pa);
                af[mt][1] = *reinterpret_cast<const uint32_t*>(pa + 8*AP);
                af[mt][2] = *reinterpret_cast<const uint32_t*>(pa + 8);
                af[mt][3] = *reinterpret_cast<const uint32_t*>(pa + 8*AP + 8);
            }
            #pragma unroll
            for (int nt = 0; nt < NT; nt++) {
                const __nv_bfloat16* pb = &Bs[cur][n_w + nt*8 + g][ks + tg*2];
                bf[nt][0] = *reinterpret_cast<const uint32_t*>(pb);
                bf[nt][1] = *reinterpret_cast<const uint32_t*>(pb + 8);
            }
            #pragma unroll
            for (int mt = 0; mt < MT; mt++)
                #pragma unroll
                for (int nt = 0; nt < NT; nt++)
                    mma16816(acc[mt][nt], af[mt], bf[nt]);
        }
        if (kb + 1 < KB) cpa_wait0();
        __syncthreads();
    }

    // ---------- epilogue ----------
    float* Cf = reinterpret_cast<float*>(Cv);
    __nv_bfloat16* Ch = reinterpret_cast<__nv_bfloat16*>(Cv);
    #pragma unroll
    for (int mt = 0; mt < MT; mt++) {
        #pragma unroll
        for (int h = 0; h < 2; h++) {
            int i = i0 + m_w + mt*16 + g + 8*h;
            #pragma unroll
            for (int nt = 0; nt < NT; nt++) {
                int j = j0 + n_w + nt*8 + tg*2;
                float v0 = alpha * acc[mt][nt][2*h+0];
                float v1 = alpha * acc[mt][nt][2*h+1];
                if (bias) { v0 += bias[j]; v1 += bias[j+1]; }
                if (Res) {
                    const float* rp = &Res[(long)i * ldr + j];
                    v0 += rp[0]; v1 += rp[1];
                }
                if (out_bf16) {
                    *reinterpret_cast<__nv_bfloat162*>(&Ch[(long)i * ldc + j]) =
                        __floats2bfloat162_rn(v0, v1);
                } else {
                    *reinterpret_cast<float2*>(&Cf[(long)i * ldc + j]) = make_float2(v0, v1);
                }
            }
        }
    }
}

// ---------------- fused flash attention (bf16 in, bf16 out) ------------------
#define FPITCH 72
__global__ __launch_bounds__(128) void flash_kernel(
    const __nv_bfloat16* __restrict__ Q,
    const __nv_bfloat16* __restrict__ K,
    const __nv_bfloat16* __restrict__ V,
    __nv_bfloat16* __restrict__ O,
    int nk, long kv_bstride)
{
    __shared__ __align__(16) __nv_bfloat16 Qs[64][FPITCH];
    __shared__ __align__(16) __nv_bfloat16 Ks[64][FPITCH];
    __shared__ __align__(16) __nv_bfloat16 Vs[64][FPITCH];

    int tid = threadIdx.x, warp = tid >> 5, lane = tid & 31;
    int g = lane >> 2, tg = lane & 3;
    int b = blockIdx.y / HEADS, h = blockIdx.y % HEADS;
    const __nv_bfloat16* qb = Q + ((long)b*NTOK + blockIdx.x*64)*INNER + h*DHEAD;
    const __nv_bfloat16* kb = K + (long)b*kv_bstride + h*DHEAD;
    const __nv_bfloat16* vb = V + (long)b*kv_bstride + h*DHEAD;
    __nv_bfloat16* ob = O + ((long)b*NTOK + blockIdx.x*64)*INNER + h*DHEAD;

    #pragma unroll
    for (int t = 0; t < 4; t++) {
        int c = tid + t*128;
        int r = c >> 3, c8 = (c & 7) * 8;
        *reinterpret_cast<uint4*>(&Qs[r][c8]) =
            *reinterpret_cast<const uint4*>(&qb[(long)r*INNER + c8]);
    }

    int mrow = warp * 16;
    float m_i[2] = {-1e30f, -1e30f}, l_i[2] = {0.f, 0.f};
    float oa[8][4];
    #pragma unroll
    for (int nt = 0; nt < 8; nt++) { oa[nt][0]=0.f; oa[nt][1]=0.f; oa[nt][2]=0.f; oa[nt][3]=0.f; }

    __syncthreads();

    for (int kt = 0; kt < nk; kt += 64) {
        #pragma unroll
        for (int t = 0; t < 4; t++) {
            int c = tid + t*128;
            int r = c >> 3, c8 = (c & 7) * 8;
            *reinterpret_cast<uint4*>(&Ks[r][c8]) =
                *reinterpret_cast<const uint4*>(&kb[(long)(kt + r)*INNER + c8]);
            *reinterpret_cast<uint4*>(&Vs[r][c8]) =
                *reinterpret_cast<const uint4*>(&vb[(long)(kt + r)*INNER + c8]);
        }
        __syncthreads();

        float s[8][4] = {};
        #pragma unroll
        for (int kc = 0; kc < 64; kc += 16) {
            uint32_t aq[4];
            const __nv_bfloat16* pa = &Qs[mrow + g][kc + tg*2];
            aq[0] = *reinterpret_cast<const uint32_t*>(pa);
            aq[1] = *reinterpret_cast<const uint32_t*>(pa + 8*FPITCH);
            aq[2] = *reinterpret_cast<const uint32_t*>(pa + 8);
            aq[3] = *reinterpret_cast<const uint32_t*>(pa + 8*FPITCH + 8);
            #pragma unroll
            for (int nt = 0; nt < 8; nt++) {
                uint32_t bk[2];
                const __nv_bfloat16* pb = &Ks[nt*8 + g][kc + tg*2];
                bk[0] = *reinterpret_cast<const uint32_t*>(pb);
                bk[1] = *reinterpret_cast<const uint32_t*>(pb + 8);
                mma16816(s[nt], aq, bk);
            }
        }

        #pragma unroll
        for (int h2 = 0; h2 < 2; h2++) {
            float mt = -1e30f;
            #pragma unroll
            for (int nt = 0; nt < 8; nt++)
                mt = fmaxf(mt, fmaxf(s[nt][2*h2], s[nt][2*h2+1]));
            mt = fmaxf(mt, __shfl_xor_sync(0xffffffffu, mt, 1));
            mt = fmaxf(mt, __shfl_xor_sync(0xffffffffu, mt, 2));
            float mnew = fmaxf(m_i[h2], mt);
            float corr = __expf(m_i[h2] - mnew);
            m_i[h2] = mnew;
            float lsum = 0.f;
            #pragma unroll
            for (int nt = 0; nt < 8; nt++) {
                float e0 = __expf(s[nt][2*h2]   - mnew);
                float e1 = __expf(s[nt][2*h2+1] - mnew);
                s[nt][2*h2] = e0; s[nt][2*h2+1] = e1;
                lsum += e0 + e1;
            }
            lsum += __shfl_xor_sync(0xffffffffu, lsum, 1);
            lsum += __shfl_xor_sync(0xffffffffu, lsum, 2);
            l_i[h2] = l_i[h2] * corr + lsum;
            #pragma unroll
            for (int nt = 0; nt < 8; nt++) { oa[nt][2*h2] *= corr; oa[nt][2*h2+1] *= corr; }
        }

        #pragma unroll
        for (int kc = 0; kc < 4; kc++) {
            uint32_t ap[4];
            __nv_bfloat162 t0 = __floats2bfloat162_rn(s[2*kc][0],   s[2*kc][1]);
            __nv_bfloat162 t1 = __floats2bfloat162_rn(s[2*kc][2],   s[2*kc][3]);
            __nv_bfloat162 t2 = __floats2bfloat162_rn(s[2*kc+1][0], s[2*kc+1][1]);
            __nv_bfloat162 t3 = __floats2bfloat162_rn(s[2*kc+1][2], s[2*kc+1][3]);
            ap[0] = *reinterpret_cast<uint32_t*>(&t0);
            ap[1] = *reinterpret_cast<uint32_t*>(&t1);
            ap[2] = *reinterpret_cast<uint32_t*>(&t2);
            ap[3] = *reinterpret_cast<uint32_t*>(&t3);
            #pragma unroll
            for (int nt = 0; nt < 8; nt++) {
                uint32_t bv[2];
                uint16_t x0 = *reinterpret_cast<const uint16_t*>(&Vs[kc*16 + 2*tg    ][nt*8 + g]);
                uint16_t x1 = *reinterpret_cast<const uint16_t*>(&Vs[kc*16 + 2*tg + 1][nt*8 + g]);
                uint16_t x2 = *reinterpret_cast<const uint16_t*>(&Vs[kc*16 + 2*tg + 8][nt*8 + g]);
                uint16_t x3 = *reinterpret_cast<const uint16_t*>(&Vs[kc*16 + 2*tg + 9][nt*8 + g]);
                bv[0] = (uint32_t)x0 | ((uint32_t)x1 << 16);
                bv[1] = (uint32_t)x2 | ((uint32_t)x3 << 16);
                mma16816(oa[nt], ap, bv);
            }
        }
        __syncthreads();
    }

    #pragma unroll
    for (int h2 = 0; h2 < 2; h2++) {
        float inv = 1.f / l_i[h2];
        int r = mrow + g + 8*h2;
        #pragma unroll
        for (int nt = 0; nt < 8; nt++) {
            *reinterpret_cast<__nv_bfloat162*>(&ob[(long)r*INNER + nt*8 + tg*2]) =
                __floats2bfloat162_rn(oa[nt][2*h2] * inv, oa[nt][2*h2+1] * inv);
        }
    }
}

// ---------------- small kernels ----------------------------------------------
__global__ void f2bf_kernel(const float* __restrict__ s, __nv_bfloat16* __restrict__ d, int n)
{
    int i = (blockIdx.x * blockDim.x + threadIdx.x) * 4;
    if (i < n) {
        float4 v = *reinterpret_cast<const float4*>(s + i);
        *reinterpret_cast<__nv_bfloat162*>(d + i)     = __floats2bfloat162_rn(v.x, v.y);
        *reinterpret_cast<__nv_bfloat162*>(d + i + 2) = __floats2bfloat162_rn(v.z, v.w);
    }
}

__global__ void emb_kernel(const float* __restrict__ emb,
                           const float* __restrict__ w,
                           const float* __restrict__ bias)
{
    int b = blockIdx.x;
    __shared__ float e[EMBD];
    if (threadIdx.x < EMBD) {
        float v = emb[b * EMBD + threadIdx.x];
        e[threadIdx.x] = v / (1.f + __expf(-v));
    }
    __syncthreads();
    int o = threadIdx.x;
    float acc = bias[o];
    const float* wr = w + (long)o * EMBD;
    #pragma unroll 8
    for (int kk = 0; kk < EMBD; kk++) acc += e[kk] * wr[kk];
    if (o < DIM) g_scale[b * DIM + o] = 1.f + acc;
    else         g_shift[b * DIM + (o - DIM)] = acc;
}

__global__ void gn_stats_kernel(const float* __restrict__ X)
{
    __shared__ float sh[32];
    int b = blockIdx.x / GROUPS, g = blockIdx.x % GROUPS;
    const int CH = DIM / GROUPS;
    const float* p = X + ((long)b * DIM + (long)g * CH) * NTOK;
    float s = 0.f, ss = 0.f;
    for (int i = threadIdx.x; i < CH * NTOK; i += blockDim.x) {
        float v = p[i]; s += v; ss += v * v;
    }
    s  = block_reduce_sum(s, sh);
    ss = block_reduce_sum(ss, sh);
    if (threadIdx.x == 0) {
        float inv = 1.f / (CH * NTOK);
        float mu = s * inv;
        float var = ss * inv - mu * mu;
        g_gn_mu[blockIdx.x] = mu;
        g_gn_rs[blockIdx.x] = rsqrtf(var + 1e-6f);
    }
}

// GroupNorm-modulate-SiLU + transpose: writes hT (bf16 token-major) and xT (fp32)
__global__ void gn_apply_t_kernel(const float* __restrict__ X,
                                  const float* __restrict__ gn_g,
                                  const float* __restrict__ gn_b,
                                  __nv_bfloat16* __restrict__ HT,
                                  float* __restrict__ XT)
{
    __shared__ float tile[32][33];
    int b = blockIdx.z;
    int n0 = blockIdx.x * 32, c0 = blockIdx.y * 32;
    for (int r = threadIdx.y; r < 32; r += 8)
        tile[r][threadIdx.x] = X[((long)b * DIM + c0 + r) * NTOK + n0 + threadIdx.x];
    __syncthreads();
    int c = c0 + threadIdx.x;
    int grp = b * GROUPS + (c >> 4);
    float mu = g_gn_mu[grp], rs = g_gn_rs[grp];
    float gg = gn_g[c], bb = gn_b[c];
    float sc = g_scale[b * DIM + c], sf = g_shift[b * DIM + c];
    for (int r = threadIdx.y; r < 32; r += 8) {
        int n = n0 + r;
        float raw = tile[threadIdx.x][r];
        float v = (raw - mu) * rs * gg + bb;
        v = v * sc + sf;
        float s = v / (1.f + __expf(-v));
        HT[((long)b * NTOK + n) * DIM + c] = __float2bfloat16_rn(s);
        XT[((long)b * NTOK + n) * DIM + c] = raw;
    }
}

__global__ void ctx_transpose_kernel(const float* __restrict__ CTX,
                                     __nv_bfloat16* __restrict__ CT)
{
    __shared__ float tile[32][33];
    int b = blockIdx.z;
    int m0 = blockIdx.x * 32, c0 = blockIdx.y * 32;
    for (int r = threadIdx.y; r < 32; r += 8)
        tile[r][threadIdx.x] = CTX[((long)b * CDIM + c0 + r) * MTOK + m0 + threadIdx.x];
    __syncthreads();
    for (int r = threadIdx.y; r < 32; r += 8)
        CT[((long)b * MTOK + m0 + r) * CDIM + c0 + threadIdx.x] =
            __float2bfloat16_rn(tile[threadIdx.x][r]);
}

__global__ void layernorm_kernel(const float* __restrict__ X, __nv_bfloat16* __restrict__ Y,
                                 const float* __restrict__ g, const float* __restrict__ b)
{
    __shared__ float sh[32];
    long t = blockIdx.x;
    const float* x = X + t * DIM;
    __nv_bfloat16* y = Y + t * DIM;
    float s = 0.f, ss = 0.f;
    for (int i = threadIdx.x; i < DIM; i += blockDim.x) {
        float v = x[i]; s += v; ss += v * v;
    }
    s  = block_reduce_sum(s, sh);
    ss = block_reduce_sum(ss, sh);
    float mu = s * (1.f / DIM);
    float var = ss * (1.f / DIM) - mu * mu;
    float rs = rsqrtf(var + 1e-5f);
    for (int i = threadIdx.x; i < DIM; i += blockDim.x)
        y[i] = __float2bfloat16_rn((x[i] - mu) * rs * g[i] + b[i]);
}

__global__ void geglu_kernel(const float* __restrict__ U, __nv_bfloat16* __restrict__ V)
{
    long idx = (long)blockIdx.x * blockDim.x + threadIdx.x;
    long t = idx / DFF;
    int f = (int)(idx - t * DFF);
    float a = U[t * (2 * DFF) + f];
    float gg = U[t * (2 * DFF) + DFF + f];
    float ge = 0.5f * gg * (1.f + erff(gg * 0.70710678118654752f));
    V[idx] = __float2bfloat16_rn(a * ge);
}

__global__ void out_transpose_kernel(const float* __restrict__ XT, float* __restrict__ OUT)
{
    __shared__ float tile[32][33];
    int b = blockIdx.z;
    int n0 = blockIdx.x * 32, c0 = blockIdx.y * 32;
    for (int r = threadIdx.y; r < 32; r += 8)
        tile[r][threadIdx.x] = XT[((long)b * NTOK + n0 + r) * DIM + c0 + threadIdx.x];
    __syncthreads();
    for (int r = threadIdx.y; r < 32; r += 8)
        OUT[((long)b * DIM + c0 + r) * NTOK + n0 + threadIdx.x] = tile[threadIdx.x][r];
}

// ---------------- host orchestration ----------------------------------------
static void launch_bb(const __nv_bfloat16* A, int lda, const __nv_bfloat16* B, int ldb,
                      void* C, int ldc, const float* bias, const float* R, int ldr,
                      int M, int N, int K, float alpha, int out_bf16)
{
    dim3 grid(N / 128, M / 128);
    gemm_bb<128,128,64,32><<<grid, 256>>>(A, lda, B, ldb, C, ldc, bias, R, ldr,
                                          K, alpha, out_bf16);
}

static void conv_w_bf(const float* src, __nv_bfloat16* dst, int n)
{
    f2bf_kernel<<<(n / 4 + 255) / 256, 256>>>(src, dst, n);
}

extern "C" void kernel_launch(void* const* d_in, const int* in_sizes, int n_in,
                              void* d_out, int out_size)
{
    const float* x      = (const float*)d_in[0];
    const float* emb    = (const float*)d_in[1];
    const float* ctx    = (const float*)d_in[2];
    const float* w_emb  = (const float*)d_in[3];
    const float* b_emb  = (const float*)d_in[4];
    const float* gn_g   = (const float*)d_in[5];
    const float* gn_b   = (const float*)d_in[6];
    const float* conv_w = (const float*)d_in[7];
    const float* conv_b = (const float*)d_in[8];
    const float* a1_wq  = (const float*)d_in[9];
    const float* a1_wk  = (const float*)d_in[10];
    const float* a1_wv  = (const float*)d_in[11];
    const float* a1_wo  = (const float*)d_in[12];
    const float* a1_bo  = (const float*)d_in[13];
    const float* a2_wq  = (const float*)d_in[14];
    const float* a2_wk  = (const float*)d_in[15];
    const float* a2_wv  = (const float*)d_in[16];
    const float* a2_wo  = (const float*)d_in[17];
    const float* a2_bo  = (const float*)d_in[18];
    const float* ln1_g  = (const float*)d_in[19];
    const float* ln1_b  = (const float*)d_in[20];
    const float* ln2_g  = (const float*)d_in[21];
    const float* ln2_b  = (const float*)d_in[22];
    const float* ln3_g  = (const float*)d_in[23];
    const float* ln3_b  = (const float*)d_in[24];
    const float* ff_w1  = (const float*)d_in[25];
    const float* ff_b1  = (const float*)d_in[26];
    const float* ff_w2  = (const float*)d_in[27];
    const float* ff_b2  = (const float*)d_in[28];
    float* out = (float*)d_out;

    float *xt, *xT, *u;
    __nv_bfloat16 *bbuf, *qh, *kh, *vh, *oh, *vfh, *ctxT;
    __nv_bfloat16 *wconv, *w1q, *w1k, *w1v, *w1o, *w2q, *w2k, *w2v, *w2o, *wf1, *wf2;
    cudaGetSymbolAddress((void**)&xt,   g_xt);
    cudaGetSymbolAddress((void**)&xT,   g_buf);
    cudaGetSymbolAddress((void**)&u,    g_u);
    cudaGetSymbolAddress((void**)&bbuf, g_bbuf);
    cudaGetSymbolAddress((void**)&qh,   g_qh);
    cudaGetSymbolAddress((void**)&kh,   g_kh);
    cudaGetSymbolAddress((void**)&vh,   g_vh);
    cudaGetSymbolAddress((void**)&oh,   g_oh);
    cudaGetSymbolAddress((void**)&vfh,  g_vfh);
    cudaGetSymbolAddress((void**)&ctxT, g_ctxT);
    cudaGetSymbolAddress((void**)&wconv, g_wconv);
    cudaGetSymbolAddress((void**)&w1q,  g_w1q);
    cudaGetSymbolAddress((void**)&w1k,  g_w1k);
    cudaGetSymbolAddress((void**)&w1v,  g_w1v);
    cudaGetSymbolAddress((void**)&w1o,  g_w1o);
    cudaGetSymbolAddress((void**)&w2q,  g_w2q);
    cudaGetSymbolAddress((void**)&w2k,  g_w2k);
    cudaGetSymbolAddress((void**)&w2v,  g_w2v);
    cudaGetSymbolAddress((void**)&w2o,  g_w2o);
    cudaGetSymbolAddress((void**)&wf1,  g_wf1);
    cudaGetSymbolAddress((void**)&wf2,  g_wf2);

    const int MTOT = BSZ * NTOK;          // 8192
    const float iscale = 0.125f;          // 1/sqrt(DHEAD) folded into Q proj

    // weight conversions (independent of activations; issue first)
    conv_w_bf(conv_w, wconv, DIM*DIM);
    conv_w_bf(a1_wq, w1q, INNER*DIM);
    conv_w_bf(a1_wk, w1k, INNER*DIM);
    conv_w_bf(a1_wv, w1v, INNER*DIM);
    conv_w_bf(a1_wo, w1o, DIM*INNER);
    conv_w_bf(a2_wq, w2q, INNER*DIM);
    conv_w_bf(a2_wk, w2k, INNER*CDIM);
    conv_w_bf(a2_wv, w2v, INNER*CDIM);
    conv_w_bf(a2_wo, w2o, DIM*INNER);
    conv_w_bf(ff_w1, wf1, 2*DFF*DIM);
    conv_w_bf(ff_w2, wf2, DIM*DFF);
    ctx_transpose_kernel<<<dim3(MTOK/32, CDIM/32, BSZ), dim3(32, 8)>>>(ctx, ctxT);

    // residual branch
    emb_kernel<<<BSZ, 2 * DIM>>>(emb, w_emb, b_emb);
    gn_stats_kernel<<<BSZ * GROUPS, 256>>>(x);
    gn_apply_t_kernel<<<dim3(NTOK/32, DIM/32, BSZ), dim3(32, 8)>>>(x, gn_g, gn_b, bbuf, xT);
    // conv 1x1 + residual -> xt fp32 token-major
    launch_bb(bbuf, DIM, wconv, DIM, xt, DIM, conv_b, xT, DIM,
              MTOT, DIM, DIM, 1.f, 0);

    // ---- self attention ----
    layernorm_kernel<<<MTOT, 256>>>(xt, bbuf, ln1_g, ln1_b);
    launch_bb(bbuf, DIM, w1q, DIM, qh, INNER, nullptr, nullptr, 0, MTOT, INNER, DIM, iscale, 1);
    launch_bb(bbuf, DIM, w1k, DIM, kh, INNER, nullptr, nullptr, 0, MTOT, INNER, DIM, 1.f, 1);
    launch_bb(bbuf, DIM, w1v, DIM, vh, INNER, nullptr, nullptr, 0, MTOT, INNER, DIM, 1.f, 1);
    flash_kernel<<<dim3(NTOK/64, BSZ*HEADS), 128>>>(qh, kh, vh, oh, NTOK, (long)NTOK*INNER);
    launch_bb(oh, INNER, w1o, INNER, xt, DIM, a1_bo, xt, DIM, MTOT, DIM, INNER, 1.f, 0);

    // ---- cross attention ----
    layernorm_kernel<<<MTOT, 256>>>(xt, bbuf, ln2_g, ln2_b);
    launch_bb(bbuf, DIM, w2q, DIM, qh, INNER, nullptr, nullptr, 0, MTOT, INNER, DIM, iscale, 1);
    launch_bb(ctxT, CDIM, w2k, CDIM, kh, INNER, nullptr, nullptr, 0, BSZ*MTOK, INNER, CDIM, 1.f, 1);
    launch_bb(ctxT, CDIM, w2v, CDIM, vh, INNER, nullptr, nullptr, 0, BSZ*MTOK, INNER, CDIM, 1.f, 1);
    flash_kernel<<<dim3(NTOK/64, BSZ*HEADS), 128>>>(qh, kh, vh, oh, MTOK, (long)MTOK*INNER);
    launch_bb(oh, INNER, w2o, INNER, xt, DIM, a2_bo, xt, DIM, MTOT, DIM, INNER, 1.f, 0);

    // ---- GEGLU feed-forward ----
    layernorm_kernel<<<MTOT, 256>>>(xt, bbuf, ln3_g, ln3_b);
    launch_bb(bbuf, DIM, wf1, DIM, u, 2*DFF, ff_b1, nullptr, 0, MTOT, 2*DFF, DIM, 1.f, 0);
    geglu_kernel<<<(int)((long)MTOT * DFF / 256), 256>>>(u, vfh);
    launch_bb(vfh, DFF, wf2, DFF, xt, DIM, ff_b2, xt, DIM, MTOT, DIM, DFF, 1.f, 0);

    // ---- back to [B, DIM, N] ----
    out_transpose_kernel<<<dim3(NTOK / 32, DIM / 32, BSZ), dim3(32, 8)>>>(xt, out);
}

// round 7
// speedup vs baseline: 6.2725x; 1.1931x over previous
#include <cuda_runtime.h>
#include <cuda_bf16.h>
#include <math.h>
#include <stdint.h>

#define BSZ   8
#define DIM   512
#define NTOK  1024
#define EMBD  128
#define CDIM  512
#define MTOK  256
#define HEADS 8
#define DHEAD 64
#define INNER 512
#define DFF   2048
#define GROUPS 32

// ---------------- scratch (device globals; no allocations allowed) ----------
__device__ float g_xt [BSZ*NTOK*DIM];            // fp32 residual stream (token-major)
__device__ float g_buf[BSZ*NTOK*DIM];            // fp32 xT residual for conv
__device__ __nv_bfloat16 g_bbuf[BSZ*NTOK*DIM];   // bf16 activations (LN out / silu-h)
__device__ __nv_bfloat16 g_qkvh[BSZ*NTOK*3*INNER];
__device__ __nv_bfloat16 g_qh [BSZ*NTOK*INNER];
__device__ __nv_bfloat16 g_kvh2[BSZ*MTOK*2*INNER];
__device__ __nv_bfloat16 g_oh [BSZ*NTOK*INNER];
__device__ __nv_bfloat16 g_vfh[BSZ*NTOK*DFF];
__device__ __nv_bfloat16 g_ctxT[BSZ*MTOK*CDIM];
// bf16 weights (converted once per launch)
__device__ __nv_bfloat16 g_wconv[DIM*DIM];
__device__ __nv_bfloat16 g_wqkv[3*INNER*DIM];    // [q(scaled);k;v]
__device__ __nv_bfloat16 g_w1o[DIM*INNER];
__device__ __nv_bfloat16 g_w2q[INNER*DIM];       // scaled
__device__ __nv_bfloat16 g_wkv2[2*INNER*CDIM];   // [k;v]
__device__ __nv_bfloat16 g_w2o[DIM*INNER];
__device__ __nv_bfloat16 g_wf1p[2*DFF*DIM];      // geglu-permuted
__device__ __nv_bfloat16 g_wf2[DIM*DFF];
__device__ float g_pb1[2*DFF];                   // permuted ff bias1
__device__ float g_scale[BSZ*DIM];
__device__ float g_shift[BSZ*DIM];
__device__ float g_gn_mu[BSZ*GROUPS];
__device__ float g_gn_rs[BSZ*GROUPS];

// ---------------- helpers ----------------------------------------------------
__device__ __forceinline__ float block_reduce_sum(float v, float* sh) {
    __syncthreads();
    #pragma unroll
    for (int o = 16; o > 0; o >>= 1) v += __shfl_xor_sync(0xffffffffu, v, o);
    int warp = threadIdx.x >> 5;
    if ((threadIdx.x & 31) == 0) sh[warp] = v;
    __syncthreads();
    int nw = blockDim.x >> 5;
    v = (threadIdx.x < nw) ? sh[threadIdx.x] : 0.f;
    if (threadIdx.x < 32) {
        #pragma unroll
        for (int o = 16; o > 0; o >>= 1) v += __shfl_xor_sync(0xffffffffu, v, o);
    }
    if (threadIdx.x == 0) sh[0] = v;
    __syncthreads();
    return sh[0];
}

__device__ __forceinline__ void mma16816(float* c, const uint32_t* a, const uint32_t* b) {
    asm volatile(
        "mma.sync.aligned.m16n8k16.row.col.f32.bf16.bf16.f32 "
        "{%0,%1,%2,%3}, {%4,%5,%6,%7}, {%8,%9}, {%0,%1,%2,%3};\n"
        : "+f"(c[0]), "+f"(c[1]), "+f"(c[2]), "+f"(c[3])
        : "r"(a[0]), "r"(a[1]), "r"(a[2]), "r"(a[3]), "r"(b[0]), "r"(b[1]));
}

__device__ __forceinline__ void ldsm4(uint32_t* r, uint32_t a) {
    asm volatile("ldmatrix.sync.aligned.m8n8.x4.shared.b16 {%0,%1,%2,%3}, [%4];\n"
        : "=r"(r[0]), "=r"(r[1]), "=r"(r[2]), "=r"(r[3]) : "r"(a));
}
__device__ __forceinline__ void ldsm4t(uint32_t* r, uint32_t a) {
    asm volatile("ldmatrix.sync.aligned.m8n8.x4.trans.shared.b16 {%0,%1,%2,%3}, [%4];\n"
        : "=r"(r[0]), "=r"(r[1]), "=r"(r[2]), "=r"(r[3]) : "r"(a));
}

__device__ __forceinline__ void cpa16(uint32_t s, const void* g) {
    asm volatile("cp.async.ca.shared.global [%0], [%1], 16;\n" :: "r"(s), "l"(g));
}
__device__ __forceinline__ void cpa_commit() { asm volatile("cp.async.commit_group;\n"); }
__device__ __forceinline__ void cpa_wait0()  { asm volatile("cp.async.wait_group 0;\n" ::: "memory"); }

__device__ __forceinline__ float gelu_exact(float g) {
    return 0.5f * g * (1.f + erff(g * 0.70710678118654752f));
}

// ---------------- bf16 GEMM: C[i,j] = alpha*sum_k A[i,k]*B[j,k] --------------
// out_mode: 0 fp32 (+bias +Res), 1 bf16 (+bias), 2 geglu-bf16 (pairs -> a*gelu(g))
template<int BM, int BN, int WM, int WN>
__global__ __launch_bounds__(256) void gemm_bb(
    const __nv_bfloat16* __restrict__ A, int lda,
    const __nv_bfloat16* __restrict__ Bm, int ldb,
    void* __restrict__ Cv, int ldc,
    const float* __restrict__ bias,
    const float* __restrict__ Res, int ldr,
    int K, float alpha, int out_mode)
{
    constexpr int BK = 32, AP = 40;
    constexpr int WARPS_N = BN / WN;
    constexpr int MT = WM / 16, NT = WN / 8;
    constexpr int ACH = BM * 4 / 256;
    constexpr int BCH = BN * 4 / 256;

    int i0 = blockIdx.y * BM, j0 = blockIdx.x * BN;
    __shared__ __align__(16) __nv_bfloat16 As[2][BM][AP];
    __shared__ __align__(16) __nv_bfloat16 Bs[2][BN][AP];
    uint32_t sA0 = (uint32_t)__cvta_generic_to_shared(&As[0][0][0]);
    uint32_t sB0 = (uint32_t)__cvta_generic_to_shared(&Bs[0][0][0]);

    int tid = threadIdx.x, warp = tid >> 5, lane = tid & 31;
    int g = lane >> 2, tg = lane & 3;
    int m_w = (warp / WARPS_N) * WM, n_w = (warp % WARPS_N) * WN;

    // ldmatrix lane bases
    uint32_t aBase = sA0 + (uint32_t)(((m_w + (lane & 15)) * AP + ((lane >> 4) * 8)) * 2);
    uint32_t bBase = sB0 + (uint32_t)(((n_w + ((lane & 7) | ((lane & 16) >> 1))) * AP + (lane & 8)) * 2);

    float acc[MT][NT][4] = {};

    auto load_tiles = [&](int k0, int buf) {
        #pragma unroll
        for (int t = 0; t < ACH; t++) {
            int c = tid + t * 256;
            int row = c >> 2, off = (c & 3) * 8;
            cpa16(sA0 + buf * (BM * AP * 2) + (row * AP + off) * 2,
                  A + (long)(i0 + row) * lda + k0 + off);
        }
        #pragma unroll
        for (int t = 0; t < BCH; t++) {
            int c = tid + t * 256;
            int row = c >> 2, off = (c & 3) * 8;
            cpa16(sB0 + buf * (BN * AP * 2) + (row * AP + off) * 2,
                  Bm + (long)(j0 + row) * ldb + k0 + off);
        }
        cpa_commit();
    };

    load_tiles(0, 0);
    cpa_wait0();
    __syncthreads();

    int KB = K / BK;
    for (int kb = 0; kb < KB; kb++) {
        int cur = kb & 1;
        if (kb + 1 < KB) load_tiles((kb + 1) * BK, cur ^ 1);
        uint32_t aB = aBase + cur * (BM * AP * 2);
        uint32_t bB = bBase + cur * (BN * AP * 2);
        #pragma unroll
        for (int ks = 0; ks < BK; ks += 16) {
            uint32_t af[MT][4];
            uint32_t bf[NT][2];
            #pragma unroll
            for (int mt = 0; mt < MT; mt++)
                ldsm4(af[mt], aB + (mt * 16 * AP + ks) * 2);
            #pragma unroll
            for (int p = 0; p < NT / 2; p++) {
                uint32_t r[4];
                ldsm4(r, bB + (p * 16 * AP + ks) * 2);
                bf[2*p][0] = r[0]; bf[2*p][1] = r[1];
                bf[2*p+1][0] = r[2]; bf[2*p+1][1] = r[3];
            }
            #pragma unroll
            for (int mt = 0; mt < MT; mt++)
                #pragma unroll
                for (int nt = 0; nt < NT; nt++)
                    mma16816(acc[mt][nt], af[mt], bf[nt]);
        }
        if (kb + 1 < KB) cpa_wait0();
        __syncthreads();
    }

    // ---------- epilogue ----------
    float* Cf = reinterpret_cast<float*>(Cv);
    __nv_bfloat16* Ch = reinterpret_cast<__nv_bfloat16*>(Cv);
    #pragma unroll
    for (int mt = 0; mt < MT; mt++) {
        #pragma unroll
        for (int h = 0; h < 2; h++) {
            int i = i0 + m_w + mt*16 + g + 8*h;
            #pragma unroll
            for (int nt = 0; nt < NT; nt++) {
                int j = j0 + n_w + nt*8 + tg*2;
                float v0 = alpha * acc[mt][nt][2*h+0];
                float v1 = alpha * acc[mt][nt][2*h+1];
                if (bias) { v0 += bias[j]; v1 += bias[j+1]; }
                if (out_mode == 2) {
                    Ch[(long)i * ldc + (j >> 1)] = __float2bfloat16_rn(v0 * gelu_exact(v1));
                } else if (out_mode == 1) {
                    *reinterpret_cast<__nv_bfloat162*>(&Ch[(long)i * ldc + j]) =
                        __floats2bfloat162_rn(v0, v1);
                } else {
                    if (Res) {
                        const float* rp = &Res[(long)i * ldr + j];
                        v0 += rp[0]; v1 += rp[1];
                    }
                    *reinterpret_cast<float2*>(&Cf[(long)i * ldc + j]) = make_float2(v0, v1);
                }
            }
        }
    }
}

// ---------------- fused flash attention (bf16 in, bf16 out) ------------------
#define FPITCH 72
__global__ __launch_bounds__(128) void flash_kernel(
    const __nv_bfloat16* __restrict__ Q, int q_ld,
    const __nv_bfloat16* __restrict__ K,
    const __nv_bfloat16* __restrict__ V, int kv_ld,
    __nv_bfloat16* __restrict__ O,
    int nk, long kv_bstride)
{
    __shared__ __align__(16) __nv_bfloat16 Qs[64][FPITCH];
    __shared__ __align__(16) __nv_bfloat16 Ks[64][FPITCH];
    __shared__ __align__(16) __nv_bfloat16 Vs[64][FPITCH];
    uint32_t sQ = (uint32_t)__cvta_generic_to_shared(&Qs[0][0]);
    uint32_t sK = (uint32_t)__cvta_generic_to_shared(&Ks[0][0]);
    uint32_t sV = (uint32_t)__cvta_generic_to_shared(&Vs[0][0]);

    int tid = threadIdx.x, warp = tid >> 5, lane = tid & 31;
    int g = lane >> 2, tg = lane & 3;
    int b = blockIdx.y / HEADS, h = blockIdx.y % HEADS;
    const __nv_bfloat16* qb = Q + ((long)b*NTOK + blockIdx.x*64)*q_ld + h*DHEAD;
    const __nv_bfloat16* kb = K + (long)b*kv_bstride + h*DHEAD;
    const __nv_bfloat16* vb = V + (long)b*kv_bstride + h*DHEAD;
    __nv_bfloat16* ob = O + ((long)b*NTOK + blockIdx.x*64)*INNER + h*DHEAD;

    int mrow = warp * 16;
    // ldmatrix lane bases
    uint32_t qBase = sQ + (uint32_t)(((mrow + (lane & 15)) * FPITCH + (lane >> 4) * 8) * 2);
    uint32_t kBase = sK + (uint32_t)((((lane & 7) | ((lane & 16) >> 1)) * FPITCH + (lane & 8)) * 2);
    uint32_t vBase = sV + (uint32_t)(((((lane >> 3) & 1) * 8 + (lane & 7)) * FPITCH + (lane >> 4) * 8) * 2);

    #pragma unroll
    for (int t = 0; t < 4; t++) {
        int c = tid + t*128;
        int r = c >> 3, c8 = (c & 7) * 8;
        *reinterpret_cast<uint4*>(&Qs[r][c8]) =
            *reinterpret_cast<const uint4*>(&qb[(long)r*q_ld + c8]);
    }

    float m_i[2] = {-1e30f, -1e30f}, l_i[2] = {0.f, 0.f};
    float oa[8][4];
    #pragma unroll
    for (int nt = 0; nt < 8; nt++) { oa[nt][0]=0.f; oa[nt][1]=0.f; oa[nt][2]=0.f; oa[nt][3]=0.f; }

    __syncthreads();

    for (int kt = 0; kt < nk; kt += 64) {
        #pragma unroll
        for (int t = 0; t < 4; t++) {
            int c = tid + t*128;
            int r = c >> 3, c8 = (c & 7) * 8;
            *reinterpret_cast<uint4*>(&Ks[r][c8]) =
                *reinterpret_cast<const uint4*>(&kb[(long)(kt + r)*kv_ld + c8]);
            *reinterpret_cast<uint4*>(&Vs[r][c8]) =
                *reinterpret_cast<const uint4*>(&vb[(long)(kt + r)*kv_ld + c8]);
        }
        __syncthreads();

        // ---- S = Q @ K^T ----
        float s[8][4] = {};
        #pragma unroll
        for (int kc = 0; kc < 64; kc += 16) {
            uint32_t aq[4];
            ldsm4(aq, qBase + kc * 2);
            uint32_t bk[8][2];
            #pragma unroll
            for (int p = 0; p < 4; p++) {
                uint32_t r[4];
                ldsm4(r, kBase + (p * 16 * FPITCH + kc) * 2);
                bk[2*p][0] = r[0]; bk[2*p][1] = r[1];
                bk[2*p+1][0] = r[2]; bk[2*p+1][1] = r[3];
            }
            #pragma unroll
            for (int nt = 0; nt < 8; nt++)
                mma16816(s[nt], aq, bk[nt]);
        }

        // ---- online softmax ----
        #pragma unroll
        for (int h2 = 0; h2 < 2; h2++) {
            float mt = -1e30f;
            #pragma unroll
            for (int nt = 0; nt < 8; nt++)
                mt = fmaxf(mt, fmaxf(s[nt][2*h2], s[nt][2*h2+1]));
            mt = fmaxf(mt, __shfl_xor_sync(0xffffffffu, mt, 1));
            mt = fmaxf(mt, __shfl_xor_sync(0xffffffffu, mt, 2));
            float mnew = fmaxf(m_i[h2], mt);
            float corr = __expf(m_i[h2] - mnew);
            m_i[h2] = mnew;
            float lsum = 0.f;
            #pragma unroll
            for (int nt = 0; nt < 8; nt++) {
                float e0 = __expf(s[nt][2*h2]   - mnew);
                float e1 = __expf(s[nt][2*h2+1] - mnew);
                s[nt][2*h2] = e0; s[nt][2*h2+1] = e1;
                lsum += e0 + e1;
            }
            lsum += __shfl_xor_sync(0xffffffffu, lsum, 1);
            lsum += __shfl_xor_sync(0xffffffffu, lsum, 2);
            l_i[h2] = l_i[h2] * corr + lsum;
            #pragma unroll
            for (int nt = 0; nt < 8; nt++) { oa[nt][2*h2] *= corr; oa[nt][2*h2+1] *= corr; }
        }

        // ---- O += P @ V ----
        #pragma unroll
        for (int kc = 0; kc < 4; kc++) {
            uint32_t ap[4];
            __nv_bfloat162 t0 = __floats2bfloat162_rn(s[2*kc][0],   s[2*kc][1]);
            __nv_bfloat162 t1 = __floats2bfloat162_rn(s[2*kc][2],   s[2*kc][3]);
            __nv_bfloat162 t2 = __floats2bfloat162_rn(s[2*kc+1][0], s[2*kc+1][1]);
            __nv_bfloat162 t3 = __floats2bfloat162_rn(s[2*kc+1][2], s[2*kc+1][3]);
            ap[0] = *reinterpret_cast<uint32_t*>(&t0);
            ap[1] = *reinterpret_cast<uint32_t*>(&t1);
            ap[2] = *reinterpret_cast<uint32_t*>(&t2);
            ap[3] = *reinterpret_cast<uint32_t*>(&t3);
            uint32_t bv[8][2];
            #pragma unroll
            for (int p = 0; p < 4; p++) {
                uint32_t r[4];
                ldsm4t(r, vBase + (kc * 16 * FPITCH + p * 16) * 2);
                bv[2*p][0] = r[0]; bv[2*p][1] = r[1];
                bv[2*p+1][0] = r[2]; bv[2*p+1][1] = r[3];
            }
            #pragma unroll
            for (int nt = 0; nt < 8; nt++)
                mma16816(oa[nt], ap, bv[nt]);
        }
        __syncthreads();
    }

    #pragma unroll
    for (int h2 = 0; h2 < 2; h2++) {
        float inv = 1.f / l_i[h2];
        int r = mrow + g + 8*h2;
        #pragma unroll
        for (int nt = 0; nt < 8; nt++) {
            *reinterpret_cast<__nv_bfloat162*>(&ob[(long)r*INNER + nt*8 + tg*2]) =
                __floats2bfloat162_rn(oa[nt][2*h2] * inv, oa[nt][2*h2+1] * inv);
        }
    }
}

// ---------------- small kernels ----------------------------------------------
__global__ void f2bf_kernel(const float* __restrict__ s, __nv_bfloat16* __restrict__ d,
                            int n, float scale)
{
    int i = (blockIdx.x * blockDim.x + threadIdx.x) * 4;
    if (i < n) {
        float4 v = *reinterpret_cast<const float4*>(s + i);
        *reinterpret_cast<__nv_bfloat162*>(d + i)     = __floats2bfloat162_rn(v.x*scale, v.y*scale);
        *reinterpret_cast<__nv_bfloat162*>(d + i + 2) = __floats2bfloat162_rn(v.z*scale, v.w*scale);
    }
}

// geglu weight permute+convert: out row 2f = src row f; out row 2f+1 = src row DFF+f
__global__ void wf1_perm_kernel(const float* __restrict__ src, __nv_bfloat16* __restrict__ dst)
{
    int i = (blockIdx.x * blockDim.x + threadIdx.x) * 4;   // n = 2*DFF*DIM
    int row = i / DIM, col = i % DIM;
    int srow = (row >> 1) + (row & 1) * DFF;
    float4 v = *reinterpret_cast<const float4*>(src + (long)srow * DIM + col);
    *reinterpret_cast<__nv_bfloat162*>(dst + i)     = __floats2bfloat162_rn(v.x, v.y);
    *reinterpret_cast<__nv_bfloat162*>(dst + i + 2) = __floats2bfloat162_rn(v.z, v.w);
}

__global__ void pb1_perm_kernel(const float* __restrict__ src, float* __restrict__ dst)
{
    int f = blockIdx.x * blockDim.x + threadIdx.x;
    if (f < DFF) { dst[2*f] = src[f]; dst[2*f+1] = src[DFF + f]; }
}

__global__ void emb_kernel(const float* __restrict__ emb,
                           const float* __restrict__ w,
                           const float* __restrict__ bias)
{
    int b = blockIdx.x;
    __shared__ float e[EMBD];
    if (threadIdx.x < EMBD) {
        float v = emb[b * EMBD + threadIdx.x];
        e[threadIdx.x] = v / (1.f + __expf(-v));
    }
    __syncthreads();
    int o = threadIdx.x;
    float acc = bias[o];
    const float* wr = w + (long)o * EMBD;
    #pragma unroll 8
    for (int kk = 0; kk < EMBD; kk++) acc += e[kk] * wr[kk];
    if (o < DIM) g_scale[b * DIM + o] = 1.f + acc;
    else         g_shift[b * DIM + (o - DIM)] = acc;
}

__global__ void gn_stats_kernel(const float* __restrict__ X)
{
    __shared__ float sh[32];
    int b = blockIdx.x / GROUPS, g = blockIdx.x % GROUPS;
    const int CH = DIM / GROUPS;
    const float* p = X + ((long)b * DIM + (long)g * CH) * NTOK;
    float s = 0.f, ss = 0.f;
    for (int i = threadIdx.x; i < CH * NTOK; i += blockDim.x) {
        float v = p[i]; s += v; ss += v * v;
    }
    s  = block_reduce_sum(s, sh);
    ss = block_reduce_sum(ss, sh);
    if (threadIdx.x == 0) {
        float inv = 1.f / (CH * NTOK);
        float mu = s * inv;
        float var = ss * inv - mu * mu;
        g_gn_mu[blockIdx.x] = mu;
        g_gn_rs[blockIdx.x] = rsqrtf(var + 1e-6f);
    }
}

__global__ void gn_apply_t_kernel(const float* __restrict__ X,
                                  const float* __restrict__ gn_g,
                                  const float* __restrict__ gn_b,
                                  __nv_bfloat16* __restrict__ HT,
                                  float* __restrict__ XT)
{
    __shared__ float tile[32][33];
    int b = blockIdx.z;
    int n0 = blockIdx.x * 32, c0 = blockIdx.y * 32;
    for (int r = threadIdx.y; r < 32; r += 8)
        tile[r][threadIdx.x] = X[((long)b * DIM + c0 + r) * NTOK + n0 + threadIdx.x];
    __syncthreads();
    int c = c0 + threadIdx.x;
    int grp = b * GROUPS + (c >> 4);
    float mu = g_gn_mu[grp], rs = g_gn_rs[grp];
    float gg = gn_g[c], bb = gn_b[c];
    float sc = g_scale[b * DIM + c], sf = g_shift[b * DIM + c];
    for (int r = threadIdx.y; r < 32; r += 8) {
        int n = n0 + r;
        float raw = tile[threadIdx.x][r];
        float v = (raw - mu) * rs * gg + bb;
        v = v * sc + sf;
        float s = v / (1.f + __expf(-v));
        HT[((long)b * NTOK + n) * DIM + c] = __float2bfloat16_rn(s);
        XT[((long)b * NTOK + n) * DIM + c] = raw;
    }
}

__global__ void ctx_transpose_kernel(const float* __restrict__ CTX,
                                     __nv_bfloat16* __restrict__ CT)
{
    __shared__ float tile[32][33];
    int b = blockIdx.z;
    int m0 = blockIdx.x * 32, c0 = blockIdx.y * 32;
    for (int r = threadIdx.y; r < 32; r += 8)
        tile[r][threadIdx.x] = CTX[((long)b * CDIM + c0 + r) * MTOK + m0 + threadIdx.x];
    __syncthreads();
    for (int r = threadIdx.y; r < 32; r += 8)
        CT[((long)b * MTOK + m0 + r) * CDIM + c0 + threadIdx.x] =
            __float2bfloat16_rn(tile[threadIdx.x][r]);
}

__global__ void layernorm_kernel(const float* __restrict__ X, __nv_bfloat16* __restrict__ Y,
                                 const float* __restrict__ g, const float* __restrict__ b)
{
    __shared__ float sh[32];
    long t = blockIdx.x;
    const float* x = X + t * DIM;
    __nv_bfloat16* y = Y + t * DIM;
    float s = 0.f, ss = 0.f;
    for (int i = threadIdx.x; i < DIM; i += blockDim.x) {
        float v = x[i]; s += v; ss += v * v;
    }
    s  = block_reduce_sum(s, sh);
    ss = block_reduce_sum(ss, sh);
    float mu = s * (1.f / DIM);
    float var = ss * (1.f / DIM) - mu * mu;
    float rs = rsqrtf(var + 1e-5f);
    for (int i = threadIdx.x; i < DIM; i += blockDim.x)
        y[i] = __float2bfloat16_rn((x[i] - mu) * rs * g[i] + b[i]);
}

__global__ void out_transpose_kernel(const float* __restrict__ XT, float* __restrict__ OUT)
{
    __shared__ float tile[32][33];
    int b = blockIdx.z;
    int n0 = blockIdx.x * 32, c0 = blockIdx.y * 32;
    for (int r = threadIdx.y; r < 32; r += 8)
        tile[r][threadIdx.x] = XT[((long)b * NTOK + n0 + r) * DIM + c0 + threadIdx.x];
    __syncthreads();
    for (int r = threadIdx.y; r < 32; r += 8)
        OUT[((long)b * DIM + c0 + r) * NTOK + n0 + threadIdx.x] = tile[threadIdx.x][r];
}

// ---------------- host orchestration ----------------------------------------
static void launch_bb(const __nv_bfloat16* A, int lda, const __nv_bfloat16* B, int ldb,
                      void* C, int ldc, const float* bias, const float* R, int ldr,
                      int M, int N, int K, float alpha, int out_mode)
{
    dim3 grid(N / 128, M / 128);
    gemm_bb<128,128,64,32><<<grid, 256>>>(A, lda, B, ldb, C, ldc, bias, R, ldr,
                                          K, alpha, out_mode);
}

static void conv_w_bf(const float* src, __nv_bfloat16* dst, int n, float scale = 1.f)
{
    f2bf_kernel<<<(n / 4 + 255) / 256, 256>>>(src, dst, n, scale);
}

extern "C" void kernel_launch(void* const* d_in, const int* in_sizes, int n_in,
                              void* d_out, int out_size)
{
    const float* x      = (const float*)d_in[0];
    const float* emb    = (const float*)d_in[1];
    const float* ctx    = (const float*)d_in[2];
    const float* w_emb  = (const float*)d_in[3];
    const float* b_emb  = (const float*)d_in[4];
    const float* gn_g   = (const float*)d_in[5];
    const float* gn_b   = (const float*)d_in[6];
    const float* conv_w = (const float*)d_in[7];
    const float* conv_b = (const float*)d_in[8];
    const float* a1_wq  = (const float*)d_in[9];
    const float* a1_wk  = (const float*)d_in[10];
    const float* a1_wv  = (const float*)d_in[11];
    const float* a1_wo  = (const float*)d_in[12];
    const float* a1_bo  = (const float*)d_in[13];
    const float* a2_wq  = (const float*)d_in[14];
    const float* a2_wk  = (const float*)d_in[15];
    const float* a2_wv  = (const float*)d_in[16];
    const float* a2_wo  = (const float*)d_in[17];
    const float* a2_bo  = (const float*)d_in[18];
    const float* ln1_g  = (const float*)d_in[19];
    const float* ln1_b  = (const float*)d_in[20];
    const float* ln2_g  = (const float*)d_in[21];
    const float* ln2_b  = (const float*)d_in[22];
    const float* ln3_g  = (const float*)d_in[23];
    const float* ln3_b  = (const float*)d_in[24];
    const float* ff_w1  = (const float*)d_in[25];
    const float* ff_b1  = (const float*)d_in[26];
    const float* ff_w2  = (const float*)d_in[27];
    const float* ff_b2  = (const float*)d_in[28];
    float* out = (float*)d_out;

    float *xt, *xT, *pb1;
    __nv_bfloat16 *bbuf, *qkvh, *qh, *kvh2, *oh, *vfh, *ctxT;
    __nv_bfloat16 *wconv, *wqkv, *w1o, *w2q, *wkv2, *w2o, *wf1p, *wf2;
    cudaGetSymbolAddress((void**)&xt,   g_xt);
    cudaGetSymbolAddress((void**)&xT,   g_buf);
    cudaGetSymbolAddress((void**)&pb1,  g_pb1);
    cudaGetSymbolAddress((void**)&bbuf, g_bbuf);
    cudaGetSymbolAddress((void**)&qkvh, g_qkvh);
    cudaGetSymbolAddress((void**)&qh,   g_qh);
    cudaGetSymbolAddress((void**)&kvh2, g_kvh2);
    cudaGetSymbolAddress((void**)&oh,   g_oh);
    cudaGetSymbolAddress((void**)&vfh,  g_vfh);
    cudaGetSymbolAddress((void**)&ctxT, g_ctxT);
    cudaGetSymbolAddress((void**)&wconv, g_wconv);
    cudaGetSymbolAddress((void**)&wqkv, g_wqkv);
    cudaGetSymbolAddress((void**)&w1o,  g_w1o);
    cudaGetSymbolAddress((void**)&w2q,  g_w2q);
    cudaGetSymbolAddress((void**)&wkv2, g_wkv2);
    cudaGetSymbolAddress((void**)&w2o,  g_w2o);
    cudaGetSymbolAddress((void**)&wf1p, g_wf1p);
    cudaGetSymbolAddress((void**)&wf2,  g_wf2);

    const int MTOT = BSZ * NTOK;          // 8192
    const float iscale = 0.125f;          // folded into Wq conversions

    // weight conversions (once per launch)
    conv_w_bf(conv_w, wconv, DIM*DIM);
    conv_w_bf(a1_wq, wqkv,               INNER*DIM, iscale);
    conv_w_bf(a1_wk, wqkv +   INNER*DIM, INNER*DIM);
    conv_w_bf(a1_wv, wqkv + 2*INNER*DIM, INNER*DIM);
    conv_w_bf(a1_wo, w1o, DIM*INNER);
    conv_w_bf(a2_wq, w2q, INNER*DIM, iscale);
    conv_w_bf(a2_wk, wkv2,              INNER*CDIM);
    conv_w_bf(a2_wv, wkv2 + INNER*CDIM, INNER*CDIM);
    conv_w_bf(a2_wo, w2o, DIM*INNER);
    wf1_perm_kernel<<<(2*DFF*DIM/4 + 255)/256, 256>>>(ff_w1, wf1p);
    pb1_perm_kernel<<<(DFF + 255)/256, 256>>>(ff_b1, pb1);
    conv_w_bf(ff_w2, wf2, DIM*DFF);
    ctx_transpose_kernel<<<dim3(MTOK/32, CDIM/32, BSZ), dim3(32, 8)>>>(ctx, ctxT);

    // residual branch
    emb_kernel<<<BSZ, 2 * DIM>>>(emb, w_emb, b_emb);
    gn_stats_kernel<<<BSZ * GROUPS, 256>>>(x);
    gn_apply_t_kernel<<<dim3(NTOK/32, DIM/32, BSZ), dim3(32, 8)>>>(x, gn_g, gn_b, bbuf, xT);
    launch_bb(bbuf, DIM, wconv, DIM, xt, DIM, conv_b, xT, DIM,
              MTOT, DIM, DIM, 1.f, 0);

    // ---- self attention ----
    layernorm_kernel<<<MTOT, 256>>>(xt, bbuf, ln1_g, ln1_b);
    launch_bb(bbuf, DIM, wqkv, DIM, qkvh, 3*INNER, nullptr, nullptr, 0,
              MTOT, 3*INNER, DIM, 1.f, 1);
    flash_kernel<<<dim3(NTOK/64, BSZ*HEADS), 128>>>(
        qkvh, 3*INNER, qkvh + INNER, qkvh + 2*INNER, 3*INNER, oh,
        NTOK, (long)NTOK*3*INNER);
    launch_bb(oh, INNER, w1o, INNER, xt, DIM, a1_bo, xt, DIM, MTOT, DIM, INNER, 1.f, 0);

    // ---- cross attention ----
    layernorm_kernel<<<MTOT, 256>>>(xt, bbuf, ln2_g, ln2_b);
    launch_bb(bbuf, DIM, w2q, DIM, qh, INNER, nullptr, nullptr, 0,
              MTOT, INNER, DIM, 1.f, 1);
    launch_bb(ctxT, CDIM, wkv2, CDIM, kvh2, 2*INNER, nullptr, nullptr, 0,
              BSZ*MTOK, 2*INNER, CDIM, 1.f, 1);
    flash_kernel<<<dim3(NTOK/64, BSZ*HEADS), 128>>>(
        qh, INNER, kvh2, kvh2 + INNER, 2*INNER, oh,
        MTOK, (long)MTOK*2*INNER);
    launch_bb(oh, INNER, w2o, INNER, xt, DIM, a2_bo, xt, DIM, MTOT, DIM, INNER, 1.f, 0);

    // ---- GEGLU feed-forward (fused into FF1 epilogue) ----
    layernorm_kernel<<<MTOT, 256>>>(xt, bbuf, ln3_g, ln3_b);
    launch_bb(bbuf, DIM, wf1p, DIM, vfh, DFF, pb1, nullptr, 0,
              MTOT, 2*DFF, DIM, 1.f, 2);
    launch_bb(vfh, DFF, wf2, DFF, xt, DIM, ff_b2, xt, DIM, MTOT, DIM, DFF, 1.f, 0);

    // ---- back to [B, DIM, N] ----
    out_transpose_kernel<<<dim3(NTOK / 32, DIM / 32, BSZ), dim3(32, 8)>>>(xt, out);
}

// round 8
// speedup vs baseline: 6.5605x; 1.0459x over previous
#include <cuda_runtime.h>
#include <cuda_bf16.h>
#include <math.h>
#include <stdint.h>

#define BSZ   8
#define DIM   512
#define NTOK  1024
#define EMBD  128
#define CDIM  512
#define MTOK  256
#define HEADS 8
#define DHEAD 64
#define INNER 512
#define DFF   2048
#define GROUPS 32

// ---------------- scratch (device globals; no allocations allowed) ----------
__device__ float g_xt [BSZ*NTOK*DIM];
__device__ float g_buf[BSZ*NTOK*DIM];
__device__ __nv_bfloat16 g_bbuf[BSZ*NTOK*DIM];
__device__ __nv_bfloat16 g_qkvh[BSZ*NTOK*3*INNER];
__device__ __nv_bfloat16 g_qh [BSZ*NTOK*INNER];
__device__ __nv_bfloat16 g_kvh2[BSZ*MTOK*2*INNER];
__device__ __nv_bfloat16 g_oh [BSZ*NTOK*INNER];
__device__ __nv_bfloat16 g_vfh[BSZ*NTOK*DFF];
__device__ __nv_bfloat16 g_ctxT[BSZ*MTOK*CDIM];
__device__ __nv_bfloat16 g_wconv[DIM*DIM];
__device__ __nv_bfloat16 g_wqkv[3*INNER*DIM];
__device__ __nv_bfloat16 g_w1o[DIM*INNER];
__device__ __nv_bfloat16 g_w2q[INNER*DIM];
__device__ __nv_bfloat16 g_wkv2[2*INNER*CDIM];
__device__ __nv_bfloat16 g_w2o[DIM*INNER];
__device__ __nv_bfloat16 g_wf1p[2*DFF*DIM];
__device__ __nv_bfloat16 g_wf2[DIM*DFF];
__device__ float g_pb1[2*DFF];
__device__ float g_scale[BSZ*DIM];
__device__ float g_shift[BSZ*DIM];
__device__ float g_gn_mu[BSZ*GROUPS];
__device__ float g_gn_rs[BSZ*GROUPS];

// ---------------- helpers ----------------------------------------------------
__device__ __forceinline__ float block_reduce_sum(float v, float* sh) {
    __syncthreads();
    #pragma unroll
    for (int o = 16; o > 0; o >>= 1) v += __shfl_xor_sync(0xffffffffu, v, o);
    int warp = threadIdx.x >> 5;
    if ((threadIdx.x & 31) == 0) sh[warp] = v;
    __syncthreads();
    int nw = blockDim.x >> 5;
    v = (threadIdx.x < nw) ? sh[threadIdx.x] : 0.f;
    if (threadIdx.x < 32) {
        #pragma unroll
        for (int o = 16; o > 0; o >>= 1) v += __shfl_xor_sync(0xffffffffu, v, o);
    }
    if (threadIdx.x == 0) sh[0] = v;
    __syncthreads();
    return sh[0];
}

__device__ __forceinline__ void mma16816(float* c, const uint32_t* a, const uint32_t* b) {
    asm volatile(
        "mma.sync.aligned.m16n8k16.row.col.f32.bf16.bf16.f32 "
        "{%0,%1,%2,%3}, {%4,%5,%6,%7}, {%8,%9}, {%0,%1,%2,%3};\n"
        : "+f"(c[0]), "+f"(c[1]), "+f"(c[2]), "+f"(c[3])
        : "r"(a[0]), "r"(a[1]), "r"(a[2]), "r"(a[3]), "r"(b[0]), "r"(b[1]));
}

__device__ __forceinline__ void ldsm4(uint32_t* r, uint32_t a) {
    asm volatile("ldmatrix.sync.aligned.m8n8.x4.shared.b16 {%0,%1,%2,%3}, [%4];\n"
        : "=r"(r[0]), "=r"(r[1]), "=r"(r[2]), "=r"(r[3]) : "r"(a));
}
__device__ __forceinline__ void ldsm4t(uint32_t* r, uint32_t a) {
    asm volatile("ldmatrix.sync.aligned.m8n8.x4.trans.shared.b16 {%0,%1,%2,%3}, [%4];\n"
        : "=r"(r[0]), "=r"(r[1]), "=r"(r[2]), "=r"(r[3]) : "r"(a));
}

__device__ __forceinline__ void cpa16(uint32_t s, const void* g) {
    asm volatile("cp.async.ca.shared.global [%0], [%1], 16;\n" :: "r"(s), "l"(g));
}
__device__ __forceinline__ void cpa_commit() { asm volatile("cp.async.commit_group;\n"); }
__device__ __forceinline__ void cpa_wait0()  { asm volatile("cp.async.wait_group 0;\n" ::: "memory"); }
__device__ __forceinline__ void cpa_wait1()  { asm volatile("cp.async.wait_group 1;\n" ::: "memory"); }

__device__ __forceinline__ float gelu_exact(float g) {
    return 0.5f * g * (1.f + erff(g * 0.70710678118654752f));
}

// ---------------- bf16 GEMM ---------------------------------------------------
// out_mode: 0 fp32 (+bias +Res), 1 bf16 (+bias), 2 geglu-bf16, 3 fp32-transposed out
template<int BM, int BN, int WM, int WN>
__global__ __launch_bounds__(256) void gemm_bb(
    const __nv_bfloat16* __restrict__ A, int lda,
    const __nv_bfloat16* __restrict__ Bm, int ldb,
    void* __restrict__ Cv, int ldc,
    const float* __restrict__ bias,
    const float* __restrict__ Res, int ldr,
    int K, float alpha, int out_mode)
{
    constexpr int BK = 32, AP = 40;
    constexpr int WARPS_N = BN / WN;
    constexpr int MT = WM / 16, NT = WN / 8;
    constexpr int ACH = BM * 4 / 256;
    constexpr int BCH = BN * 4 / 256;

    int i0 = blockIdx.y * BM, j0 = blockIdx.x * BN;
    __shared__ __align__(16) __nv_bfloat16 As[2][BM][AP];
    __shared__ __align__(16) __nv_bfloat16 Bs[2][BN][AP];
    uint32_t sA0 = (uint32_t)__cvta_generic_to_shared(&As[0][0][0]);
    uint32_t sB0 = (uint32_t)__cvta_generic_to_shared(&Bs[0][0][0]);

    int tid = threadIdx.x, warp = tid >> 5, lane = tid & 31;
    int g = lane >> 2, tg = lane & 3;
    int m_w = (warp / WARPS_N) * WM, n_w = (warp % WARPS_N) * WN;

    uint32_t aBase = sA0 + (uint32_t)(((m_w + (lane & 15)) * AP + ((lane >> 4) * 8)) * 2);
    uint32_t bBase = sB0 + (uint32_t)(((n_w + ((lane & 7) | ((lane & 16) >> 1))) * AP + (lane & 8)) * 2);

    float acc[MT][NT][4] = {};

    auto load_tiles = [&](int k0, int buf) {
        #pragma unroll
        for (int t = 0; t < ACH; t++) {
            int c = tid + t * 256;
            int row = c >> 2, off = (c & 3) * 8;
            cpa16(sA0 + buf * (BM * AP * 2) + (row * AP + off) * 2,
                  A + (long)(i0 + row) * lda + k0 + off);
        }
        #pragma unroll
        for (int t = 0; t < BCH; t++) {
            int c = tid + t * 256;
            int row = c >> 2, off = (c & 3) * 8;
            cpa16(sB0 + buf * (BN * AP * 2) + (row * AP + off) * 2,
                  Bm + (long)(j0 + row) * ldb + k0 + off);
        }
        cpa_commit();
    };

    load_tiles(0, 0);
    cpa_wait0();
    __syncthreads();

    int KB = K / BK;
    for (int kb = 0; kb < KB; kb++) {
        int cur = kb & 1;
        if (kb + 1 < KB) load_tiles((kb + 1) * BK, cur ^ 1);
        uint32_t aB = aBase + cur * (BM * AP * 2);
        uint32_t bB = bBase + cur * (BN * AP * 2);
        #pragma unroll
        for (int ks = 0; ks < BK; ks += 16) {
            uint32_t af[MT][4];
            uint32_t bf[NT][2];
            #pragma unroll
            for (int mt = 0; mt < MT; mt++)
                ldsm4(af[mt], aB + (mt * 16 * AP + ks) * 2);
            #pragma unroll
            for (int p = 0; p < NT / 2; p++) {
                uint32_t r[4];
                ldsm4(r, bB + (p * 16 * AP + ks) * 2);
                bf[2*p][0] = r[0]; bf[2*p][1] = r[1];
                bf[2*p+1][0] = r[2]; bf[2*p+1][1] = r[3];
            }
            #pragma unroll
            for (int mt = 0; mt < MT; mt++)
                #pragma unroll
                for (int nt = 0; nt < NT; nt++)
                    mma16816(acc[mt][nt], af[mt], bf[nt]);
        }
        if (kb + 1 < KB) cpa_wait0();
        __syncthreads();
    }

    float* Cf = reinterpret_cast<float*>(Cv);
    __nv_bfloat16* Ch = reinterpret_cast<__nv_bfloat16*>(Cv);

    if (out_mode == 3) {
        // transposed fp32 output: out[(b*DIM + jglob)*NTOK + iglob], staged via smem
        constexpr int SP = 33;
        float* stage = reinterpret_cast<float*>(&As[0][0][0]);  // 128*33*4 = 16.9KB <= 20.5KB
        int bb = i0 >> 10;            // BM=128, NTOK=1024
        int nbase = i0 & (NTOK - 1);
        #pragma unroll
        for (int pass = 0; pass < 4; pass++) {
            __syncthreads();
            int rlo = pass * 32;
            #pragma unroll
            for (int mt = 0; mt < MT; mt++) {
                #pragma unroll
                for (int h = 0; h < 2; h++) {
                    int il = m_w + mt*16 + g + 8*h;
                    if (il >= rlo && il < rlo + 32) {
                        #pragma unroll
                        for (int nt = 0; nt < NT; nt++) {
                            int j = n_w + nt*8 + tg*2;
                            float v0 = alpha * acc[mt][nt][2*h]   + bias[j0 + j];
                            float v1 = alpha * acc[mt][nt][2*h+1] + bias[j0 + j + 1];
                            const float* rp = &Res[(long)(i0 + il) * ldr + j0 + j];
                            v0 += rp[0]; v1 += rp[1];
                            stage[j * SP + (il & 31)]       = v0;
                            stage[(j + 1) * SP + (il & 31)] = v1;
                        }
                    }
                }
            }
            __syncthreads();
            for (int q = tid; q < BN * 2; q += 256) {
                int c = q >> 1, half = q & 1;
                float* op = &Cf[((long)bb * DIM + j0 + c) * NTOK + nbase + rlo + half*16];
                float* sp = &stage[c * SP + half * 16];
                #pragma unroll
                for (int s = 0; s < 4; s++) {
                    ((float4*)op)[s] = make_float4(sp[s*4], sp[s*4+1], sp[s*4+2], sp[s*4+3]);
                }
            }
        }
        return;
    }

    #pragma unroll
    for (int mt = 0; mt < MT; mt++) {
        #pragma unroll
        for (int h = 0; h < 2; h++) {
            int i = i0 + m_w + mt*16 + g + 8*h;
            #pragma unroll
            for (int nt = 0; nt < NT; nt++) {
                int j = j0 + n_w + nt*8 + tg*2;
                float v0 = alpha * acc[mt][nt][2*h+0];
                float v1 = alpha * acc[mt][nt][2*h+1];
                if (bias) { v0 += bias[j]; v1 += bias[j+1]; }
                if (out_mode == 2) {
                    Ch[(long)i * ldc + (j >> 1)] = __float2bfloat16_rn(v0 * gelu_exact(v1));
                } else if (out_mode == 1) {
                    *reinterpret_cast<__nv_bfloat162*>(&Ch[(long)i * ldc + j]) =
                        __floats2bfloat162_rn(v0, v1);
                } else {
                    if (Res) {
                        const float* rp = &Res[(long)i * ldr + j];
                        v0 += rp[0]; v1 += rp[1];
                    }
                    *reinterpret_cast<float2*>(&Cf[(long)i * ldc + j]) = make_float2(v0, v1);
                }
            }
        }
    }
}

// ---------------- fused flash attention (cp.async K/V pipeline) ---------------
#define FPITCH 72
#define FTILEB (64 * FPITCH * 2)
__global__ __launch_bounds__(128) void flash_kernel(
    const __nv_bfloat16* __restrict__ Q, int q_ld,
    const __nv_bfloat16* __restrict__ K,
    const __nv_bfloat16* __restrict__ V, int kv_ld,
    __nv_bfloat16* __restrict__ O,
    int nk, long kv_bstride)
{
    __shared__ __align__(16) __nv_bfloat16 Qs[64][FPITCH];
    __shared__ __align__(16) __nv_bfloat16 Ks[2][64][FPITCH];
    __shared__ __align__(16) __nv_bfloat16 Vs[2][64][FPITCH];
    uint32_t sQ = (uint32_t)__cvta_generic_to_shared(&Qs[0][0]);
    uint32_t sK = (uint32_t)__cvta_generic_to_shared(&Ks[0][0][0]);
    uint32_t sV = (uint32_t)__cvta_generic_to_shared(&Vs[0][0][0]);

    int tid = threadIdx.x, warp = tid >> 5, lane = tid & 31;
    int g = lane >> 2, tg = lane & 3;
    int b = blockIdx.y / HEADS, h = blockIdx.y % HEADS;
    const __nv_bfloat16* qb = Q + ((long)b*NTOK + blockIdx.x*64)*q_ld + h*DHEAD;
    const __nv_bfloat16* kb = K + (long)b*kv_bstride + h*DHEAD;
    const __nv_bfloat16* vb = V + (long)b*kv_bstride + h*DHEAD;
    __nv_bfloat16* ob = O + ((long)b*NTOK + blockIdx.x*64)*INNER + h*DHEAD;

    int mrow = warp * 16;
    uint32_t qBase = sQ + (uint32_t)(((mrow + (lane & 15)) * FPITCH + (lane >> 4) * 8) * 2);
    uint32_t kBase = sK + (uint32_t)((((lane & 7) | ((lane & 16) >> 1)) * FPITCH + (lane & 8)) * 2);
    uint32_t vBase = sV + (uint32_t)(((((lane >> 3) & 1) * 8 + (lane & 7)) * FPITCH + (lane >> 4) * 8) * 2);

    auto pf = [&](int kt, int buf) {
        #pragma unroll
        for (int t = 0; t < 4; t++) {
            int c = tid + t*128;
            int r = c >> 3, c8 = (c & 7) * 8;
            cpa16(sK + buf*FTILEB + (r*FPITCH + c8)*2, kb + (long)(kt + r)*kv_ld + c8);
            cpa16(sV + buf*FTILEB + (r*FPITCH + c8)*2, vb + (long)(kt + r)*kv_ld + c8);
        }
        cpa_commit();
    };

    #pragma unroll
    for (int t = 0; t < 4; t++) {
        int c = tid + t*128;
        int r = c >> 3, c8 = (c & 7) * 8;
        *reinterpret_cast<uint4*>(&Qs[r][c8]) =
            *reinterpret_cast<const uint4*>(&qb[(long)r*q_ld + c8]);
    }
    pf(0, 0);
    if (nk > 64) pf(64, 1);

    float m_i[2] = {-1e30f, -1e30f}, l_i[2] = {0.f, 0.f};
    float oa[8][4];
    #pragma unroll
    for (int nt = 0; nt < 8; nt++) { oa[nt][0]=0.f; oa[nt][1]=0.f; oa[nt][2]=0.f; oa[nt][3]=0.f; }

    __syncthreads();   // Q visibility

    int T = nk >> 6;
    for (int t = 0; t < T; t++) {
        int buf = t & 1;
        if (t + 1 < T) cpa_wait1(); else cpa_wait0();
        __syncthreads();
        uint32_t kB = kBase + buf*FTILEB;
        uint32_t vB = vBase + buf*FTILEB;

        // ---- S = Q @ K^T ----
        float s[8][4] = {};
        #pragma unroll
        for (int kc = 0; kc < 64; kc += 16) {
            uint32_t aq[4];
            ldsm4(aq, qBase + kc * 2);
            uint32_t bk[8][2];
            #pragma unroll
            for (int p = 0; p < 4; p++) {
                uint32_t r[4];
                ldsm4(r, kB + (p * 16 * FPITCH + kc) * 2);
                bk[2*p][0] = r[0]; bk[2*p][1] = r[1];
                bk[2*p+1][0] = r[2]; bk[2*p+1][1] = r[3];
            }
            #pragma unroll
            for (int nt = 0; nt < 8; nt++)
                mma16816(s[nt], aq, bk[nt]);
        }

        // ---- online softmax ----
        #pragma unroll
        for (int h2 = 0; h2 < 2; h2++) {
            float mt = -1e30f;
            #pragma unroll
            for (int nt = 0; nt < 8; nt++)
                mt = fmaxf(mt, fmaxf(s[nt][2*h2], s[nt][2*h2+1]));
            mt = fmaxf(mt, __shfl_xor_sync(0xffffffffu, mt, 1));
            mt = fmaxf(mt, __shfl_xor_sync(0xffffffffu, mt, 2));
            float mnew = fmaxf(m_i[h2], mt);
            float corr = __expf(m_i[h2] - mnew);
            m_i[h2] = mnew;
            float lsum = 0.f;
            #pragma unroll
            for (int nt = 0; nt < 8; nt++) {
                float e0 = __expf(s[nt][2*h2]   - mnew);
                float e1 = __expf(s[nt][2*h2+1] - mnew);
                s[nt][2*h2] = e0; s[nt][2*h2+1] = e1;
                lsum += e0 + e1;
            }
            lsum += __shfl_xor_sync(0xffffffffu, lsum, 1);
            lsum += __shfl_xor_sync(0xffffffffu, lsum, 2);
            l_i[h2] = l_i[h2] * corr + lsum;
            #pragma unroll
            for (int nt = 0; nt < 8; nt++) { oa[nt][2*h2] *= corr; oa[nt][2*h2+1] *= corr; }
        }

        // ---- O += P @ V ----
        #pragma unroll
        for (int kc = 0; kc < 4; kc++) {
            uint32_t ap[4];
            __nv_bfloat162 t0 = __floats2bfloat162_rn(s[2*kc][0],   s[2*kc][1]);
            __nv_bfloat162 t1 = __floats2bfloat162_rn(s[2*kc][2],   s[2*kc][3]);
            __nv_bfloat162 t2 = __floats2bfloat162_rn(s[2*kc+1][0], s[2*kc+1][1]);
            __nv_bfloat162 t3 = __floats2bfloat162_rn(s[2*kc+1][2], s[2*kc+1][3]);
            ap[0] = *reinterpret_cast<uint32_t*>(&t0);
            ap[1] = *reinterpret_cast<uint32_t*>(&t1);
            ap[2] = *reinterpret_cast<uint32_t*>(&t2);
            ap[3] = *reinterpret_cast<uint32_t*>(&t3);
            uint32_t bv[8][2];
            #pragma unroll
            for (int p = 0; p < 4; p++) {
                uint32_t r[4];
                ldsm4t(r, vB + (kc * 16 * FPITCH + p * 16) * 2);
                bv[2*p][0] = r[0]; bv[2*p][1] = r[1];
                bv[2*p+1][0] = r[2]; bv[2*p+1][1] = r[3];
            }
            #pragma unroll
            for (int nt = 0; nt < 8; nt++)
                mma16816(oa[nt], ap, bv[nt]);
        }
        __syncthreads();   // done reading buf
        if (t + 2 < T) pf((t + 2) * 64, buf);
    }

    #pragma unroll
    for (int h2 = 0; h2 < 2; h2++) {
        float inv = 1.f / l_i[h2];
        int r = mrow + g + 8*h2;
        #pragma unroll
        for (int nt = 0; nt < 8; nt++) {
            *reinterpret_cast<__nv_bfloat162*>(&ob[(long)r*INNER + nt*8 + tg*2]) =
                __floats2bfloat162_rn(oa[nt][2*h2] * inv, oa[nt][2*h2+1] * inv);
        }
    }
}

// ---------------- fused weight conversion -------------------------------------
#define SQW (INNER*DIM)
#define N_CONV  (DIM*DIM)
#define N_WF1   (2*DFF*DIM)
#define N_WF2   (DIM*DFF)
#define TOT_W   (N_CONV + 3*SQW + SQW + SQW + 2*SQW + SQW + N_WF1 + N_WF2)
__global__ void convert_all_kernel(
    const float* __restrict__ conv_w,
    const float* __restrict__ a1q, const float* __restrict__ a1k,
    const float* __restrict__ a1v, const float* __restrict__ a1o,
    const float* __restrict__ a2q, const float* __restrict__ a2k,
    const float* __restrict__ a2v, const float* __restrict__ a2o,
    const float* __restrict__ f1,  const float* __restrict__ f2,
    const float* __restrict__ b1)
{
    long i = (long)(blockIdx.x * 256 + threadIdx.x) * 4;
    auto cvt = [](const float* s, __nv_bfloat16* d, long si, long di, float sc) {
        float4 v = *reinterpret_cast<const float4*>(s + si);
        *reinterpret_cast<__nv_bfloat162*>(d + di)     = __floats2bfloat162_rn(v.x*sc, v.y*sc);
        *reinterpret_cast<__nv_bfloat162*>(d + di + 2) = __floats2bfloat162_rn(v.z*sc, v.w*sc);
    };
    if (i < N_CONV) { cvt(conv_w, g_wconv, i, i, 1.f); return; }
    i -= N_CONV;
    if (i < SQW)    { cvt(a1q, g_wqkv, i, i, 0.125f); return; }
    i -= SQW;
    if (i < SQW)    { cvt(a1k, g_wqkv, i, i + SQW, 1.f); return; }
    i -= SQW;
    if (i < SQW)    { cvt(a1v, g_wqkv, i, i + 2*SQW, 1.f); return; }
    i -= SQW;
    if (i < SQW)    { cvt(a1o, g_w1o, i, i, 1.f); return; }
    i -= SQW;
    if (i < SQW)    { cvt(a2q, g_w2q, i, i, 0.125f); return; }
    i -= SQW;
    if (i < SQW)    { cvt(a2k, g_wkv2, i, i, 1.f); return; }
    i -= SQW;
    if (i < SQW)    { cvt(a2v, g_wkv2, i, i + SQW, 1.f); return; }
    i -= SQW;
    if (i < SQW)    { cvt(a2o, g_w2o, i, i, 1.f); return; }
    i -= SQW;
    if (i < N_WF1) {
        int row = (int)(i / DIM), col = (int)(i % DIM);
        int srow = (row >> 1) + (row & 1) * DFF;
        cvt(f1, g_wf1p, (long)srow * DIM + col, i, 1.f);
        return;
    }
    i -= N_WF1;
    if (i < N_WF2)  { cvt(f2, g_wf2, i, i, 1.f); return; }
    i -= N_WF2;
    if (i < 2*DFF) {
        #pragma unroll
        for (int s = 0; s < 4; s++) {
            long o = i + s;
            g_pb1[o] = b1[(o >> 1) + (o & 1) * DFF];
        }
    }
}

// ---------------- small kernels ----------------------------------------------
__global__ void emb_kernel(const float* __restrict__ emb,
                           const float* __restrict__ w,
                           const float* __restrict__ bias)
{
    int b = blockIdx.x;
    __shared__ float e[EMBD];
    if (threadIdx.x < EMBD) {
        float v = emb[b * EMBD + threadIdx.x];
        e[threadIdx.x] = v / (1.f + __expf(-v));
    }
    __syncthreads();
    int o = threadIdx.x;
    float acc = bias[o];
    const float* wr = w + (long)o * EMBD;
    #pragma unroll 8
    for (int kk = 0; kk < EMBD; kk++) acc += e[kk] * wr[kk];
    if (o < DIM) g_scale[b * DIM + o] = 1.f + acc;
    else         g_shift[b * DIM + (o - DIM)] = acc;
}

__global__ void gn_stats_kernel(const float* __restrict__ X)
{
    __shared__ float sh[32];
    int b = blockIdx.x / GROUPS, g = blockIdx.x % GROUPS;
    const int CH = DIM / GROUPS;
    const float* p = X + ((long)b * DIM + (long)g * CH) * NTOK;
    float s = 0.f, ss = 0.f;
    for (int i = threadIdx.x; i < CH * NTOK; i += blockDim.x) {
        float v = p[i]; s += v; ss += v * v;
    }
    s  = block_reduce_sum(s, sh);
    ss = block_reduce_sum(ss, sh);
    if (threadIdx.x == 0) {
        float inv = 1.f / (CH * NTOK);
        float mu = s * inv;
        float var = ss * inv - mu * mu;
        g_gn_mu[blockIdx.x] = mu;
        g_gn_rs[blockIdx.x] = rsqrtf(var + 1e-6f);
    }
}

__global__ void gn_apply_t_kernel(const float* __restrict__ X,
                                  const float* __restrict__ gn_g,
                                  const float* __restrict__ gn_b,
                                  __nv_bfloat16* __restrict__ HT,
                                  float* __restrict__ XT)
{
    __shared__ float tile[32][33];
    int b = blockIdx.z;
    int n0 = blockIdx.x * 32, c0 = blockIdx.y * 32;
    for (int r = threadIdx.y; r < 32; r += 8)
        tile[r][threadIdx.x] = X[((long)b * DIM + c0 + r) * NTOK + n0 + threadIdx.x];
    __syncthreads();
    int c = c0 + threadIdx.x;
    int grp = b * GROUPS + (c >> 4);
    float mu = g_gn_mu[grp], rs = g_gn_rs[grp];
    float gg = gn_g[c], bb = gn_b[c];
    float sc = g_scale[b * DIM + c], sf = g_shift[b * DIM + c];
    for (int r = threadIdx.y; r < 32; r += 8) {
        int n = n0 + r;
        float raw = tile[threadIdx.x][r];
        float v = (raw - mu) * rs * gg + bb;
        v = v * sc + sf;
        float s = v / (1.f + __expf(-v));
        HT[((long)b * NTOK + n) * DIM + c] = __float2bfloat16_rn(s);
        XT[((long)b * NTOK + n) * DIM + c] = raw;
    }
}

__global__ void ctx_transpose_kernel(const float* __restrict__ CTX,
                                     __nv_bfloat16* __restrict__ CT)
{
    __shared__ float tile[32][33];
    int b = blockIdx.z;
    int m0 = blockIdx.x * 32, c0 = blockIdx.y * 32;
    for (int r = threadIdx.y; r < 32; r += 8)
        tile[r][threadIdx.x] = CTX[((long)b * CDIM + c0 + r) * MTOK + m0 + threadIdx.x];
    __syncthreads();
    for (int r = threadIdx.y; r < 32; r += 8)
        CT[((long)b * MTOK + m0 + r) * CDIM + c0 + threadIdx.x] =
            __float2bfloat16_rn(tile[threadIdx.x][r]);
}

__global__ void layernorm_kernel(const float* __restrict__ X, __nv_bfloat16* __restrict__ Y,
                                 const float* __restrict__ g, const float* __restrict__ b)
{
    __shared__ float sh[32];
    long t = blockIdx.x;
    const float* x = X + t * DIM;
    __nv_bfloat16* y = Y + t * DIM;
    float s = 0.f, ss = 0.f;
    for (int i = threadIdx.x; i < DIM; i += blockDim.x) {
        float v = x[i]; s += v; ss += v * v;
    }
    s  = block_reduce_sum(s, sh);
    ss = block_reduce_sum(ss, sh);
    float mu = s * (1.f / DIM);
    float var = ss * (1.f / DIM) - mu * mu;
    float rs = rsqrtf(var + 1e-5f);
    for (int i = threadIdx.x; i < DIM; i += blockDim.x)
        y[i] = __float2bfloat16_rn((x[i] - mu) * rs * g[i] + b[i]);
}

// ---------------- host orchestration ----------------------------------------
static void launch_bb(const __nv_bfloat16* A, int lda, const __nv_bfloat16* B, int ldb,
                      void* C, int ldc, const float* bias, const float* R, int ldr,
                      int M, int N, int K, float alpha, int out_mode)
{
    dim3 grid(N / 128, M / 128);
    gemm_bb<128,128,64,32><<<grid, 256>>>(A, lda, B, ldb, C, ldc, bias, R, ldr,
                                          K, alpha, out_mode);
}

extern "C" void kernel_launch(void* const* d_in, const int* in_sizes, int n_in,
                              void* d_out, int out_size)
{
    const float* x      = (const float*)d_in[0];
    const float* emb    = (const float*)d_in[1];
    const float* ctx    = (const float*)d_in[2];
    const float* w_emb  = (const float*)d_in[3];
    const float* b_emb  = (const float*)d_in[4];
    const float* gn_g   = (const float*)d_in[5];
    const float* gn_b   = (const float*)d_in[6];
    const float* conv_w = (const float*)d_in[7];
    const float* conv_b = (const float*)d_in[8];
    const float* a1_wq  = (const float*)d_in[9];
    const float* a1_wk  = (const float*)d_in[10];
    const float* a1_wv  = (const float*)d_in[11];
    const float* a1_wo  = (const float*)d_in[12];
    const float* a1_bo  = (const float*)d_in[13];
    const float* a2_wq  = (const float*)d_in[14];
    const float* a2_wk  = (const float*)d_in[15];
    const float* a2_wv  = (const float*)d_in[16];
    const float* a2_wo  = (const float*)d_in[17];
    const float* a2_bo  = (const float*)d_in[18];
    const float* ln1_g  = (const float*)d_in[19];
    const float* ln1_b  = (const float*)d_in[20];
    const float* ln2_g  = (const float*)d_in[21];
    const float* ln2_b  = (const float*)d_in[22];
    const float* ln3_g  = (const float*)d_in[23];
    const float* ln3_b  = (const float*)d_in[24];
    const float* ff_w1  = (const float*)d_in[25];
    const float* ff_b1  = (const float*)d_in[26];
    const float* ff_w2  = (const float*)d_in[27];
    const float* ff_b2  = (const float*)d_in[28];
    float* out = (float*)d_out;

    float *xt, *xT, *pb1;
    __nv_bfloat16 *bbuf, *qkvh, *qh, *kvh2, *oh, *vfh, *ctxT;
    __nv_bfloat16 *wconv, *wqkv, *w1o, *w2q, *wkv2, *w2o, *wf1p, *wf2;
    cudaGetSymbolAddress((void**)&xt,   g_xt);
    cudaGetSymbolAddress((void**)&xT,   g_buf);
    cudaGetSymbolAddress((void**)&pb1,  g_pb1);
    cudaGetSymbolAddress((void**)&bbuf, g_bbuf);
    cudaGetSymbolAddress((void**)&qkvh, g_qkvh);
    cudaGetSymbolAddress((void**)&qh,   g_qh);
    cudaGetSymbolAddress((void**)&kvh2, g_kvh2);
    cudaGetSymbolAddress((void**)&oh,   g_oh);
    cudaGetSymbolAddress((void**)&vfh,  g_vfh);
    cudaGetSymbolAddress((void**)&ctxT, g_ctxT);
    cudaGetSymbolAddress((void**)&wconv, g_wconv);
    cudaGetSymbolAddress((void**)&wqkv, g_wqkv);
    cudaGetSymbolAddress((void**)&w1o,  g_w1o);
    cudaGetSymbolAddress((void**)&w2q,  g_w2q);
    cudaGetSymbolAddress((void**)&wkv2, g_wkv2);
    cudaGetSymbolAddress((void**)&w2o,  g_w2o);
    cudaGetSymbolAddress((void**)&wf1p, g_wf1p);
    cudaGetSymbolAddress((void**)&wf2,  g_wf2);

    const int MTOT = BSZ * NTOK;

    // one fused weight conversion launch
    {
        long tot4 = TOT_W / 4 + (2*DFF) / 4;
        int blocks = (int)((tot4 + 255) / 256);
        convert_all_kernel<<<blocks, 256>>>(conv_w, a1_wq, a1_wk, a1_wv, a1_wo,
                                            a2_wq, a2_wk, a2_wv, a2_wo,
                                            ff_w1, ff_w2, ff_b1);
    }
    ctx_transpose_kernel<<<dim3(MTOK/32, CDIM/32, BSZ), dim3(32, 8)>>>(ctx, ctxT);

    emb_kernel<<<BSZ, 2 * DIM>>>(emb, w_emb, b_emb);
    gn_stats_kernel<<<BSZ * GROUPS, 256>>>(x);
    gn_apply_t_kernel<<<dim3(NTOK/32, DIM/32, BSZ), dim3(32, 8)>>>(x, gn_g, gn_b, bbuf, xT);
    launch_bb(bbuf, DIM, wconv, DIM, xt, DIM, conv_b, xT, DIM,
              MTOT, DIM, DIM, 1.f, 0);

    // ---- self attention ----
    layernorm_kernel<<<MTOT, 256>>>(xt, bbuf, ln1_g, ln1_b);
    launch_bb(bbuf, DIM, wqkv, DIM, qkvh, 3*INNER, nullptr, nullptr, 0,
              MTOT, 3*INNER, DIM, 1.f, 1);
    flash_kernel<<<dim3(NTOK/64, BSZ*HEADS), 128>>>(
        qkvh, 3*INNER, qkvh + INNER, qkvh + 2*INNER, 3*INNER, oh,
        NTOK, (long)NTOK*3*INNER);
    launch_bb(oh, INNER, w1o, INNER, xt, DIM, a1_bo, xt, DIM, MTOT, DIM, INNER, 1.f, 0);

    // ---- cross attention ----
    layernorm_kernel<<<MTOT, 256>>>(xt, bbuf, ln2_g, ln2_b);
    launch_bb(bbuf, DIM, w2q, DIM, qh, INNER, nullptr, nullptr, 0,
              MTOT, INNER, DIM, 1.f, 1);
    launch_bb(ctxT, CDIM, wkv2, CDIM, kvh2, 2*INNER, nullptr, nullptr, 0,
              BSZ*MTOK, 2*INNER, CDIM, 1.f, 1);
    flash_kernel<<<dim3(NTOK/64, BSZ*HEADS), 128>>>(
        qh, INNER, kvh2, kvh2 + INNER, 2*INNER, oh,
        MTOK, (long)MTOK*2*INNER);
    launch_bb(oh, INNER, w2o, INNER, xt, DIM, a2_bo, xt, DIM, MTOT, DIM, INNER, 1.f, 0);

    // ---- GEGLU feed-forward ----
    layernorm_kernel<<<MTOT, 256>>>(xt, bbuf, ln3_g, ln3_b);
    launch_bb(bbuf, DIM, wf1p, DIM, vfh, DFF, pb1, nullptr, 0,
              MTOT, 2*DFF, DIM, 1.f, 2);
    // FF2 with fused transposed output -> out[B, DIM, N]
    launch_bb(vfh, DFF, wf2, DFF, out, 0, ff_b2, xt, DIM, MTOT, DIM, DFF, 1.f, 3);
}